// round 1
// baseline (speedup 1.0000x reference)
#include <cuda_runtime.h>

#define E_DIM 1024
#define HEADS 16
#define HD 64
#define BATCH 4
#define SEQ 2048
#define BS (BATCH*SEQ)   // 8192

// Scratch (device globals: allocation-guard safe)
__device__ float g_q[BATCH*HEADS*SEQ*HD];
__device__ float g_k[BATCH*HEADS*SEQ*HD];
__device__ float g_v[BATCH*HEADS*SEQ*HD];
__device__ float g_y[BS*E_DIM];

// ---------------------------------------------------------------------------
// Tiled SGEMM: C[M,N] = A[M,1024] @ W[1024,N] + bias
// MODE 0: epilogue scatters into g_q/g_k/g_v in [B,H,S,D] layout (N=3072)
// MODE 1: epilogue writes out[M,N] directly; A ignored, uses g_y (N=1024)
// ---------------------------------------------------------------------------
template<int N, int MODE>
__global__ __launch_bounds__(256)
void gemm128(const float* __restrict__ A,
             const float* __restrict__ W,
             const float* __restrict__ bias,
             float* __restrict__ out)
{
    __shared__ float As[16][132];   // transposed A tile, padded
    __shared__ float Bs[16][128];

    const int tid = threadIdx.x;
    const int m0 = blockIdx.y * 128;
    const int n0 = blockIdx.x * 128;

    // A-load indexing: 128x16 tile, 2 float4 per thread
    const int ar = tid >> 2;          // 0..63
    const int ac = (tid & 3) << 2;    // 0,4,8,12
    // B-load indexing: 16x128 tile, 2 float4 per thread
    const int br = tid >> 5;          // 0..7
    const int bc = (tid & 31) << 2;   // 0..124

    const int tx = tid & 15;          // col fragment
    const int ty = tid >> 4;          // row fragment

    const float* Ap = (MODE == 0) ? A : (const float*)g_y;

    float acc[8][8];
    #pragma unroll
    for (int i = 0; i < 8; i++)
        #pragma unroll
        for (int j = 0; j < 8; j++) acc[i][j] = 0.0f;

    const float* Aptr = Ap + (m0 + ar) * 1024 + ac;
    const float* Wptr = W + br * N + n0 + bc;

    for (int k0 = 0; k0 < 1024; k0 += 16) {
        float4 a0 = *(const float4*)(Aptr + k0);
        float4 a1 = *(const float4*)(Aptr + 64 * 1024 + k0);
        float4 b0 = *(const float4*)(Wptr + (size_t)k0 * N);
        float4 b1 = *(const float4*)(Wptr + (size_t)(k0 + 8) * N);

        As[ac + 0][ar] = a0.x; As[ac + 1][ar] = a0.y;
        As[ac + 2][ar] = a0.z; As[ac + 3][ar] = a0.w;
        As[ac + 0][ar + 64] = a1.x; As[ac + 1][ar + 64] = a1.y;
        As[ac + 2][ar + 64] = a1.z; As[ac + 3][ar + 64] = a1.w;
        *(float4*)&Bs[br][bc]     = b0;
        *(float4*)&Bs[br + 8][bc] = b1;
        __syncthreads();

        #pragma unroll
        for (int k = 0; k < 16; k++) {
            float a[8], b[8];
            *(float4*)&a[0] = *(const float4*)&As[k][ty * 8];
            *(float4*)&a[4] = *(const float4*)&As[k][ty * 8 + 4];
            *(float4*)&b[0] = *(const float4*)&Bs[k][tx * 8];
            *(float4*)&b[4] = *(const float4*)&Bs[k][tx * 8 + 4];
            #pragma unroll
            for (int i = 0; i < 8; i++)
                #pragma unroll
                for (int j = 0; j < 8; j++)
                    acc[i][j] = fmaf(a[i], b[j], acc[i][j]);
        }
        __syncthreads();
    }

    if (MODE == 0) {
        // scatter QKV into [B,H,S,D]
        #pragma unroll
        for (int i = 0; i < 8; i++) {
            int m = m0 + ty * 8 + i;
            int b_ = m >> 11;           // /2048
            int s  = m & 2047;
            #pragma unroll
            for (int j = 0; j < 8; j++) {
                int n = n0 + tx * 8 + j;
                float v = acc[i][j] + __ldg(&bias[n]);
                int sec = n >> 10;      // 0:q 1:k 2:v
                int e   = n & 1023;
                int h   = e >> 6;
                int d   = e & 63;
                float* dst = (sec == 0) ? g_q : ((sec == 1) ? g_k : g_v);
                dst[(((b_ * HEADS + h) * SEQ) + s) * HD + d] = v;
            }
        }
    } else {
        #pragma unroll
        for (int i = 0; i < 8; i++) {
            int m = m0 + ty * 8 + i;
            float* orow = out + (size_t)m * N + n0 + tx * 8;
            float4 v0, v1;
            v0.x = acc[i][0] + __ldg(&bias[n0 + tx * 8 + 0]);
            v0.y = acc[i][1] + __ldg(&bias[n0 + tx * 8 + 1]);
            v0.z = acc[i][2] + __ldg(&bias[n0 + tx * 8 + 2]);
            v0.w = acc[i][3] + __ldg(&bias[n0 + tx * 8 + 3]);
            v1.x = acc[i][4] + __ldg(&bias[n0 + tx * 8 + 4]);
            v1.y = acc[i][5] + __ldg(&bias[n0 + tx * 8 + 5]);
            v1.z = acc[i][6] + __ldg(&bias[n0 + tx * 8 + 6]);
            v1.w = acc[i][7] + __ldg(&bias[n0 + tx * 8 + 7]);
            *(float4*)&orow[0] = v0;
            *(float4*)&orow[4] = v1;
        }
    }
}

// ---------------------------------------------------------------------------
// Causal flash attention, fp32, D=64, tiles 64x64, 128 threads.
// Thread (tr=tid/8, tc=tid%8): rows {tr+16i}, cols/dims {tc+8j}.
// Row-stride 68 floats => float4 reads across the 8 tc-lanes land on bank
// offsets 0,16,..,112 bytes (mod 128): conflict-free.
// ---------------------------------------------------------------------------
#define FST 68   // smem row stride (floats)

__global__ __launch_bounds__(128)
void flash_attn()
{
    extern __shared__ float sm[];
    float* Qs = sm;
    float* Ks = sm + 64 * FST;
    float* Vt = sm + 2 * 64 * FST;   // transposed: Vt[d][keypos]
    float* Ps = sm + 3 * 64 * FST;

    const int tid = threadIdx.x;
    const int qi = blockIdx.x;   // 0..31
    const int h  = blockIdx.y;   // 0..15
    const int b  = blockIdx.z;   // 0..3

    const int tr = tid >> 3;     // 0..15
    const int tc = tid & 7;      // 0..7

    const float* qbase = g_q + (size_t)((b * HEADS + h) * SEQ) * HD;
    const float* kbase = g_k + (size_t)((b * HEADS + h) * SEQ) * HD;
    const float* vbase = g_v + (size_t)((b * HEADS + h) * SEQ) * HD;

    // load Q tile, pre-scaled by 1/sqrt(64)
    #pragma unroll
    for (int l = 0; l < 8; l++) {
        int pos = tid + l * 128;        // float4 index, 0..1023
        int r = pos >> 4;
        int c = (pos & 15) << 2;
        float4 q = *(const float4*)(qbase + (qi * 64 + r) * 64 + c);
        q.x *= 0.125f; q.y *= 0.125f; q.z *= 0.125f; q.w *= 0.125f;
        *(float4*)&Qs[r * FST + c] = q;
    }

    float m_i[4], l_i[4], acc[4][8];
    #pragma unroll
    for (int i = 0; i < 4; i++) {
        m_i[i] = -1e30f; l_i[i] = 0.0f;
        #pragma unroll
        for (int j = 0; j < 8; j++) acc[i][j] = 0.0f;
    }

    for (int kj = 0; kj <= qi; kj++) {
        __syncthreads();   // protect Ks/Vt (prev PV) and Qs (first iter)

        const float* kp = kbase + (size_t)kj * 64 * 64;
        const float* vp = vbase + (size_t)kj * 64 * 64;
        #pragma unroll
        for (int l = 0; l < 8; l++) {
            int pos = tid + l * 128;
            int r = pos >> 4;
            int c = (pos & 15) << 2;
            *(float4*)&Ks[r * FST + c] = *(const float4*)(kp + r * 64 + c);
            float4 v = *(const float4*)(vp + r * 64 + c);
            Vt[(c + 0) * FST + r] = v.x;
            Vt[(c + 1) * FST + r] = v.y;
            Vt[(c + 2) * FST + r] = v.z;
            Vt[(c + 3) * FST + r] = v.w;
        }
        __syncthreads();

        // scores: S = Q @ K^T (pre-scaled)
        float s[4][8];
        #pragma unroll
        for (int i = 0; i < 4; i++)
            #pragma unroll
            for (int j = 0; j < 8; j++) s[i][j] = 0.0f;

        #pragma unroll
        for (int k = 0; k < 64; k += 4) {
            float4 qa[4], kb[8];
            #pragma unroll
            for (int i = 0; i < 4; i++)
                qa[i] = *(const float4*)&Qs[(tr + 16 * i) * FST + k];
            #pragma unroll
            for (int j = 0; j < 8; j++)
                kb[j] = *(const float4*)&Ks[(tc + 8 * j) * FST + k];
            #pragma unroll
            for (int i = 0; i < 4; i++)
                #pragma unroll
                for (int j = 0; j < 8; j++) {
                    s[i][j] = fmaf(qa[i].x, kb[j].x, s[i][j]);
                    s[i][j] = fmaf(qa[i].y, kb[j].y, s[i][j]);
                    s[i][j] = fmaf(qa[i].z, kb[j].z, s[i][j]);
                    s[i][j] = fmaf(qa[i].w, kb[j].w, s[i][j]);
                }
        }

        // causal mask on diagonal tile
        if (kj == qi) {
            #pragma unroll
            for (int i = 0; i < 4; i++) {
                int qrow = tr + 16 * i;
                #pragma unroll
                for (int j = 0; j < 8; j++) {
                    if (tc + 8 * j > qrow) s[i][j] = -1e30f;
                }
            }
        }

        // online softmax update + write P tile
        #pragma unroll
        for (int i = 0; i < 4; i++) {
            float mx = s[i][0];
            #pragma unroll
            for (int j = 1; j < 8; j++) mx = fmaxf(mx, s[i][j]);
            mx = fmaxf(mx, __shfl_xor_sync(0xffffffffu, mx, 1));
            mx = fmaxf(mx, __shfl_xor_sync(0xffffffffu, mx, 2));
            mx = fmaxf(mx, __shfl_xor_sync(0xffffffffu, mx, 4));
            float mn = fmaxf(m_i[i], mx);
            float alpha = __expf(m_i[i] - mn);
            m_i[i] = mn;
            float rs = 0.0f;
            #pragma unroll
            for (int j = 0; j < 8; j++) {
                float p = __expf(s[i][j] - mn);
                s[i][j] = p;
                rs += p;
            }
            rs += __shfl_xor_sync(0xffffffffu, rs, 1);
            rs += __shfl_xor_sync(0xffffffffu, rs, 2);
            rs += __shfl_xor_sync(0xffffffffu, rs, 4);
            l_i[i] = l_i[i] * alpha + rs;
            #pragma unroll
            for (int j = 0; j < 8; j++) {
                acc[i][j] *= alpha;
                Ps[(tr + 16 * i) * FST + tc + 8 * j] = s[i][j];
            }
        }
        __syncthreads();

        // PV: acc += P @ V   (Vt is [d][keypos])
        #pragma unroll
        for (int k = 0; k < 64; k += 4) {
            float4 pa[4], vb[8];
            #pragma unroll
            for (int i = 0; i < 4; i++)
                pa[i] = *(const float4*)&Ps[(tr + 16 * i) * FST + k];
            #pragma unroll
            for (int j = 0; j < 8; j++)
                vb[j] = *(const float4*)&Vt[(tc + 8 * j) * FST + k];
            #pragma unroll
            for (int i = 0; i < 4; i++)
                #pragma unroll
                for (int j = 0; j < 8; j++) {
                    acc[i][j] = fmaf(pa[i].x, vb[j].x, acc[i][j]);
                    acc[i][j] = fmaf(pa[i].y, vb[j].y, acc[i][j]);
                    acc[i][j] = fmaf(pa[i].z, vb[j].z, acc[i][j]);
                    acc[i][j] = fmaf(pa[i].w, vb[j].w, acc[i][j]);
                }
        }
    }

    // normalize + write y in [B,S,E] layout
    #pragma unroll
    for (int i = 0; i < 4; i++) {
        float inv = 1.0f / l_i[i];
        int srow = qi * 64 + tr + 16 * i;
        float* yrow = g_y + ((size_t)(b * SEQ + srow)) * E_DIM + h * HD;
        #pragma unroll
        for (int j = 0; j < 8; j++)
            yrow[tc + 8 * j] = acc[i][j] * inv;
    }
}

// ---------------------------------------------------------------------------
extern "C" void kernel_launch(void* const* d_in, const int* in_sizes, int n_in,
                              void* d_out, int out_size)
{
    const float* x      = (const float*)d_in[0];
    const float* W_attn = (const float*)d_in[1];
    const float* b_attn = (const float*)d_in[2];
    const float* W_proj = (const float*)d_in[3];
    const float* b_proj = (const float*)d_in[4];
    float* out = (float*)d_out;

    const int FLASH_SMEM = 4 * 64 * FST * sizeof(float);   // 69632 B
    cudaFuncSetAttribute(flash_attn,
                         cudaFuncAttributeMaxDynamicSharedMemorySize,
                         FLASH_SMEM);

    // 1) QKV GEMM + bias + reshape
    {
        dim3 grid(3072 / 128, BS / 128);
        gemm128<3072, 0><<<grid, 256>>>(x, W_attn, b_attn, nullptr);
    }

    // 2) Causal flash attention
    {
        dim3 grid(SEQ / 64, HEADS, BATCH);
        flash_attn<<<grid, 128, FLASH_SMEM>>>();
    }

    // 3) Output projection
    {
        dim3 grid(1024 / 128, BS / 128);
        gemm128<1024, 1><<<grid, 256>>>(nullptr, W_proj, b_proj, out);
    }
}

// round 3
// speedup vs baseline: 1.6972x; 1.6972x over previous
#include <cuda_runtime.h>
#include <cuda_bf16.h>
#include <cstdint>

#define E_DIM 1024
#define HEADS 16
#define HD 64
#define BATCH 4
#define SEQ 2048
#define BS (BATCH*SEQ)   // 8192

// ---------------- scratch (device globals: allocation-guard safe) ----------
__device__ float g_q[BATCH*HEADS*SEQ*HD];
__device__ float g_k[BATCH*HEADS*SEQ*HD];
__device__ float g_v[BATCH*HEADS*SEQ*HD];
__device__ float g_y[BS*E_DIM];

__device__ __align__(16) __nv_bfloat16 g_xh[BS*E_DIM];
__device__ __align__(16) __nv_bfloat16 g_xl[BS*E_DIM];
__device__ __align__(16) __nv_bfloat16 g_yh[BS*E_DIM];
__device__ __align__(16) __nv_bfloat16 g_yl[BS*E_DIM];
__device__ __align__(16) __nv_bfloat16 g_wah[3*E_DIM*E_DIM];  // W_attn^T hi [3072,1024]
__device__ __align__(16) __nv_bfloat16 g_wal[3*E_DIM*E_DIM];  // W_attn^T lo
__device__ __align__(16) __nv_bfloat16 g_wph[E_DIM*E_DIM];    // W_proj^T hi [1024,1024]
__device__ __align__(16) __nv_bfloat16 g_wpl[E_DIM*E_DIM];    // W_proj^T lo

// ---------------- PTX helpers (all valid at compute_103) --------------------
__device__ __forceinline__ uint32_t smem_u32(const void* p) {
    uint32_t a;
    asm("{ .reg .u64 t; cvta.to.shared.u64 t, %1; cvt.u32.u64 %0, t; }"
        : "=r"(a) : "l"(p));
    return a;
}
#define CP_ASYNC16(sa, ga) \
    asm volatile("cp.async.cg.shared.global [%0], [%1], 16;" :: "r"(sa), "l"(ga))
#define CP_COMMIT() asm volatile("cp.async.commit_group;" ::: "memory")
#define CP_WAIT0()  asm volatile("cp.async.wait_group 0;" ::: "memory")

__device__ __forceinline__ void ldsm_x4(uint32_t& r0, uint32_t& r1,
                                        uint32_t& r2, uint32_t& r3, uint32_t addr) {
    asm volatile("ldmatrix.sync.aligned.m8n8.x4.shared.b16 {%0,%1,%2,%3}, [%4];"
                 : "=r"(r0), "=r"(r1), "=r"(r2), "=r"(r3) : "r"(addr));
}
__device__ __forceinline__ void mma16816(float* d, const uint32_t* a, const uint32_t* b) {
    asm volatile(
        "mma.sync.aligned.m16n8k16.row.col.f32.bf16.bf16.f32 "
        "{%0,%1,%2,%3}, {%4,%5,%6,%7}, {%8,%9}, {%0,%1,%2,%3};"
        : "+f"(d[0]), "+f"(d[1]), "+f"(d[2]), "+f"(d[3])
        : "r"(a[0]), "r"(a[1]), "r"(a[2]), "r"(a[3]), "r"(b[0]), "r"(b[1]));
}

// ---------------- prep kernels ---------------------------------------------
__global__ __launch_bounds__(256)
void split_f32(const float* __restrict__ src,
               __nv_bfloat16* __restrict__ hi, __nv_bfloat16* __restrict__ lo)
{
    int i = (blockIdx.x * 256 + threadIdx.x) * 4;
    float4 v = *(const float4*)(src + i);
    __nv_bfloat16 h0 = __float2bfloat16(v.x), h1 = __float2bfloat16(v.y);
    __nv_bfloat16 h2 = __float2bfloat16(v.z), h3 = __float2bfloat16(v.w);
    __nv_bfloat162 H0 = {h0, h1}, H1 = {h2, h3};
    __nv_bfloat162 L0 = {__float2bfloat16(v.x - __bfloat162float(h0)),
                         __float2bfloat16(v.y - __bfloat162float(h1))};
    __nv_bfloat162 L1 = {__float2bfloat16(v.z - __bfloat162float(h2)),
                         __float2bfloat16(v.w - __bfloat162float(h3))};
    *(__nv_bfloat162*)(hi + i)     = H0;
    *(__nv_bfloat162*)(hi + i + 2) = H1;
    *(__nv_bfloat162*)(lo + i)     = L0;
    *(__nv_bfloat162*)(lo + i + 2) = L1;
}

// W [1024, N] row-major -> Wt hi/lo [N, 1024]
__global__ __launch_bounds__(256)
void wsplit_t(const float* __restrict__ W,
              __nv_bfloat16* __restrict__ Wh, __nv_bfloat16* __restrict__ Wl, int N)
{
    __shared__ float tile[32][33];
    int c0 = blockIdx.x * 32;
    int r0 = blockIdx.y * 32;
    int tx = threadIdx.x & 31, ty = threadIdx.x >> 5;
    #pragma unroll
    for (int i = ty; i < 32; i += 8)
        tile[i][tx] = W[(size_t)(r0 + i) * N + c0 + tx];
    __syncthreads();
    #pragma unroll
    for (int i = ty; i < 32; i += 8) {
        float v = tile[tx][i];
        __nv_bfloat16 h = __float2bfloat16(v);
        size_t o = (size_t)(c0 + i) * 1024 + r0 + tx;
        Wh[o] = h;
        Wl[o] = __float2bfloat16(v - __bfloat162float(h));
    }
}

// ---------------- HMMA GEMM -------------------------------------------------
// C[8192, NTOT] = A[8192,1024] @ Wt^T + bias, Wt stored [NTOT,1024] K-major.
// C = Ah*Bh + Ah*Bl + Al*Bh via mma.sync m16n8k16 bf16, fp32 accum.
// CTA 128x128, 8 warps (2x4), warp 64x32, K-chunk 32, double-buffered cp.async.
// Buffer layout (per 32KB buffer): Ah(8K) Al(8K) Bh(8K) Bl(8K).
// Row = 64B = 4 segs of 16B; swizzle: seg ^= (row>>1)&3.
#define GEMM_SMEM 65536

template<int NTOT, int MODE>
__global__ __launch_bounds__(256)
void gemm_mma(const __nv_bfloat16* __restrict__ Ah, const __nv_bfloat16* __restrict__ Al,
              const __nv_bfloat16* __restrict__ Bh, const __nv_bfloat16* __restrict__ Bl,
              const float* __restrict__ bias, float* __restrict__ out)
{
    extern __shared__ char smem[];
    const uint32_t sb = smem_u32(smem);
    const int tid  = threadIdx.x;
    const int wid  = tid >> 5;
    const int lane = tid & 31;
    const int m0 = blockIdx.y * 128;
    const int n0 = blockIdx.x * 128;

    const int wm = wid & 1;     // 0..1  (64 rows each)
    const int wn = wid >> 1;    // 0..3  (32 cols each)
    const int lr = lane & 7;
    const int lg = lane >> 3;

    float acc[4][4][4];
    #pragma unroll
    for (int i = 0; i < 4; i++)
        #pragma unroll
        for (int j = 0; j < 4; j++)
            #pragma unroll
            for (int r = 0; r < 4; r++) acc[i][j][r] = 0.0f;

    // loader: 512 16B-chunks per operand tile, 2 per thread per operand
    auto load_chunk = [&](int c) {
        const int k0 = c * 32;
        const uint32_t sbase = sb + (uint32_t)(c & 1) * 32768u;
        #pragma unroll
        for (int t = 0; t < 2; t++) {
            int u = tid + t * 256;
            int r = u >> 2, seg = u & 3;
            uint32_t soff = (uint32_t)(r * 64 + ((seg ^ ((r >> 1) & 3)) << 4));
            size_t ga = (size_t)(m0 + r) * 1024 + k0 + seg * 8;
            size_t gb = (size_t)(n0 + r) * 1024 + k0 + seg * 8;
            CP_ASYNC16(sbase + soff,          Ah + ga);
            CP_ASYNC16(sbase + 8192  + soff,  Al + ga);
            CP_ASYNC16(sbase + 16384 + soff,  Bh + gb);
            CP_ASYNC16(sbase + 24576 + soff,  Bl + gb);
        }
        CP_COMMIT();
    };

    load_chunk(0);

    for (int c = 0; c < 32; c++) {
        CP_WAIT0();
        __syncthreads();
        if (c + 1 < 32) load_chunk(c + 1);

        const uint32_t sbase = sb + (uint32_t)(c & 1) * 32768u;
        #pragma unroll
        for (int s = 0; s < 2; s++) {
            uint32_t ah[4][4], al[4][4], bh[4][2], bl[4][2];
            // A fragments: 4 m16 tiles
            #pragma unroll
            for (int i = 0; i < 4; i++) {
                int row = wm * 64 + i * 16 + lr + (lg & 1) * 8;
                int seg = 2 * s + (lg >> 1);
                uint32_t ad = sbase + (uint32_t)(row * 64 +
                              ((seg ^ ((row >> 1) & 3)) << 4));
                ldsm_x4(ah[i][0], ah[i][1], ah[i][2], ah[i][3], ad);
                ldsm_x4(al[i][0], al[i][1], al[i][2], al[i][3], ad + 8192);
            }
            // B fragments: 4 n8 tiles via 2 x ldmatrix.x4
            #pragma unroll
            for (int p = 0; p < 2; p++) {
                int row = wn * 32 + p * 16 + lr + (lg >> 1) * 8;
                int seg = 2 * s + (lg & 1);
                uint32_t bd = sbase + 16384u + (uint32_t)(row * 64 +
                              ((seg ^ ((row >> 1) & 3)) << 4));
                uint32_t r0, r1, r2, r3;
                ldsm_x4(r0, r1, r2, r3, bd);
                bh[2*p][0] = r0; bh[2*p][1] = r1;
                bh[2*p+1][0] = r2; bh[2*p+1][1] = r3;
                ldsm_x4(r0, r1, r2, r3, bd + 8192);
                bl[2*p][0] = r0; bl[2*p][1] = r1;
                bl[2*p+1][0] = r2; bl[2*p+1][1] = r3;
            }
            #pragma unroll
            for (int i = 0; i < 4; i++)
                #pragma unroll
                for (int j = 0; j < 4; j++) {
                    mma16816(acc[i][j], ah[i], bh[j]);
                    mma16816(acc[i][j], ah[i], bl[j]);
                    mma16816(acc[i][j], al[i], bh[j]);
                }
        }
    }

    // epilogue: fragment c0,c1 -> (row, col..col+1); c2,c3 -> (row+8, ...)
    const int mrow = m0 + wm * 64 + (lane >> 2);
    const int ncol = n0 + wn * 32 + (lane & 3) * 2;
    #pragma unroll
    for (int i = 0; i < 4; i++) {
        #pragma unroll
        for (int j = 0; j < 4; j++) {
            int m = mrow + i * 16;
            int n = ncol + j * 8;
            float b0 = __ldg(&bias[n]), b1 = __ldg(&bias[n + 1]);
            float2 v0 = {acc[i][j][0] + b0, acc[i][j][1] + b1};
            float2 v1 = {acc[i][j][2] + b0, acc[i][j][3] + b1};
            if (MODE == 0) {
                int sec = n >> 10;
                int e   = n & 1023;
                int h   = e >> 6;
                int d   = e & 63;
                float* q = (sec == 0) ? g_q : ((sec == 1) ? g_k : g_v);
                int b_ = m >> 11, s_ = m & 2047;
                float* dst0 = q + ((size_t)((b_ * HEADS + h) * SEQ) + s_) * HD + d;
                *(float2*)dst0 = v0;
                float* dst1 = q + ((size_t)((b_ * HEADS + h) * SEQ) + s_ + 8) * HD + d;
                *(float2*)dst1 = v1;
            } else {
                *(float2*)(out + (size_t)m * 1024 + n) = v0;
                *(float2*)(out + (size_t)(m + 8) * 1024 + n) = v1;
            }
        }
    }
}

// ---------------- flash attention (proven fp32 version) ---------------------
#define FST 68

__global__ __launch_bounds__(128)
void flash_attn()
{
    extern __shared__ float sm[];
    float* Qs = sm;
    float* Ks = sm + 64 * FST;
    float* Vt = sm + 2 * 64 * FST;
    float* Ps = sm + 3 * 64 * FST;

    const int tid = threadIdx.x;
    const int qi = blockIdx.x;
    const int h  = blockIdx.y;
    const int b  = blockIdx.z;

    const int tr = tid >> 3;
    const int tc = tid & 7;

    const float* qbase = g_q + (size_t)((b * HEADS + h) * SEQ) * HD;
    const float* kbase = g_k + (size_t)((b * HEADS + h) * SEQ) * HD;
    const float* vbase = g_v + (size_t)((b * HEADS + h) * SEQ) * HD;

    #pragma unroll
    for (int l = 0; l < 8; l++) {
        int pos = tid + l * 128;
        int r = pos >> 4;
        int c = (pos & 15) << 2;
        float4 q = *(const float4*)(qbase + (qi * 64 + r) * 64 + c);
        q.x *= 0.125f; q.y *= 0.125f; q.z *= 0.125f; q.w *= 0.125f;
        *(float4*)&Qs[r * FST + c] = q;
    }

    float m_i[4], l_i[4], acc[4][8];
    #pragma unroll
    for (int i = 0; i < 4; i++) {
        m_i[i] = -1e30f; l_i[i] = 0.0f;
        #pragma unroll
        for (int j = 0; j < 8; j++) acc[i][j] = 0.0f;
    }

    for (int kj = 0; kj <= qi; kj++) {
        __syncthreads();
        const float* kp = kbase + (size_t)kj * 64 * 64;
        const float* vp = vbase + (size_t)kj * 64 * 64;
        #pragma unroll
        for (int l = 0; l < 8; l++) {
            int pos = tid + l * 128;
            int r = pos >> 4;
            int c = (pos & 15) << 2;
            *(float4*)&Ks[r * FST + c] = *(const float4*)(kp + r * 64 + c);
            float4 v = *(const float4*)(vp + r * 64 + c);
            Vt[(c + 0) * FST + r] = v.x;
            Vt[(c + 1) * FST + r] = v.y;
            Vt[(c + 2) * FST + r] = v.z;
            Vt[(c + 3) * FST + r] = v.w;
        }
        __syncthreads();

        float s[4][8];
        #pragma unroll
        for (int i = 0; i < 4; i++)
            #pragma unroll
            for (int j = 0; j < 8; j++) s[i][j] = 0.0f;

        #pragma unroll
        for (int k = 0; k < 64; k += 4) {
            float4 qa[4], kb[8];
            #pragma unroll
            for (int i = 0; i < 4; i++)
                qa[i] = *(const float4*)&Qs[(tr + 16 * i) * FST + k];
            #pragma unroll
            for (int j = 0; j < 8; j++)
                kb[j] = *(const float4*)&Ks[(tc + 8 * j) * FST + k];
            #pragma unroll
            for (int i = 0; i < 4; i++)
                #pragma unroll
                for (int j = 0; j < 8; j++) {
                    s[i][j] = fmaf(qa[i].x, kb[j].x, s[i][j]);
                    s[i][j] = fmaf(qa[i].y, kb[j].y, s[i][j]);
                    s[i][j] = fmaf(qa[i].z, kb[j].z, s[i][j]);
                    s[i][j] = fmaf(qa[i].w, kb[j].w, s[i][j]);
                }
        }

        if (kj == qi) {
            #pragma unroll
            for (int i = 0; i < 4; i++) {
                int qrow = tr + 16 * i;
                #pragma unroll
                for (int j = 0; j < 8; j++)
                    if (tc + 8 * j > qrow) s[i][j] = -1e30f;
            }
        }

        #pragma unroll
        for (int i = 0; i < 4; i++) {
            float mx = s[i][0];
            #pragma unroll
            for (int j = 1; j < 8; j++) mx = fmaxf(mx, s[i][j]);
            mx = fmaxf(mx, __shfl_xor_sync(0xffffffffu, mx, 1));
            mx = fmaxf(mx, __shfl_xor_sync(0xffffffffu, mx, 2));
            mx = fmaxf(mx, __shfl_xor_sync(0xffffffffu, mx, 4));
            float mn = fmaxf(m_i[i], mx);
            float alpha = __expf(m_i[i] - mn);
            m_i[i] = mn;
            float rs = 0.0f;
            #pragma unroll
            for (int j = 0; j < 8; j++) {
                float p = __expf(s[i][j] - mn);
                s[i][j] = p;
                rs += p;
            }
            rs += __shfl_xor_sync(0xffffffffu, rs, 1);
            rs += __shfl_xor_sync(0xffffffffu, rs, 2);
            rs += __shfl_xor_sync(0xffffffffu, rs, 4);
            l_i[i] = l_i[i] * alpha + rs;
            #pragma unroll
            for (int j = 0; j < 8; j++) {
                acc[i][j] *= alpha;
                Ps[(tr + 16 * i) * FST + tc + 8 * j] = s[i][j];
            }
        }
        __syncthreads();

        #pragma unroll
        for (int k = 0; k < 64; k += 4) {
            float4 pa[4], vb[8];
            #pragma unroll
            for (int i = 0; i < 4; i++)
                pa[i] = *(const float4*)&Ps[(tr + 16 * i) * FST + k];
            #pragma unroll
            for (int j = 0; j < 8; j++)
                vb[j] = *(const float4*)&Vt[(tc + 8 * j) * FST + k];
            #pragma unroll
            for (int i = 0; i < 4; i++)
                #pragma unroll
                for (int j = 0; j < 8; j++) {
                    acc[i][j] = fmaf(pa[i].x, vb[j].x, acc[i][j]);
                    acc[i][j] = fmaf(pa[i].y, vb[j].y, acc[i][j]);
                    acc[i][j] = fmaf(pa[i].z, vb[j].z, acc[i][j]);
                    acc[i][j] = fmaf(pa[i].w, vb[j].w, acc[i][j]);
                }
        }
    }

    #pragma unroll
    for (int i = 0; i < 4; i++) {
        float inv = 1.0f / l_i[i];
        int srow = qi * 64 + tr + 16 * i;
        float* yrow = g_y + ((size_t)(b * SEQ + srow)) * E_DIM + h * HD;
        #pragma unroll
        for (int j = 0; j < 8; j++)
            yrow[tc + 8 * j] = acc[i][j] * inv;
    }
}

// ---------------------------------------------------------------------------
extern "C" void kernel_launch(void* const* d_in, const int* in_sizes, int n_in,
                              void* d_out, int out_size)
{
    const float* x      = (const float*)d_in[0];
    const float* W_attn = (const float*)d_in[1];
    const float* b_attn = (const float*)d_in[2];
    const float* W_proj = (const float*)d_in[3];
    const float* b_proj = (const float*)d_in[4];
    float* out = (float*)d_out;

    cudaFuncSetAttribute(flash_attn,
                         cudaFuncAttributeMaxDynamicSharedMemorySize,
                         4 * 64 * FST * sizeof(float));
    cudaFuncSetAttribute(gemm_mma<3072, 0>,
                         cudaFuncAttributeMaxDynamicSharedMemorySize, GEMM_SMEM);
    cudaFuncSetAttribute(gemm_mma<1024, 1>,
                         cudaFuncAttributeMaxDynamicSharedMemorySize, GEMM_SMEM);

    __nv_bfloat16 *xh, *xl, *yh, *yl, *wah, *wal, *wph, *wpl;
    cudaGetSymbolAddress((void**)&xh,  g_xh);
    cudaGetSymbolAddress((void**)&xl,  g_xl);
    cudaGetSymbolAddress((void**)&yh,  g_yh);
    cudaGetSymbolAddress((void**)&yl,  g_yl);
    cudaGetSymbolAddress((void**)&wah, g_wah);
    cudaGetSymbolAddress((void**)&wal, g_wal);
    cudaGetSymbolAddress((void**)&wph, g_wph);
    cudaGetSymbolAddress((void**)&wpl, g_wpl);
    float* y;
    cudaGetSymbolAddress((void**)&y, g_y);

    // prep: split x, transpose+split weights
    split_f32<<<BS * E_DIM / 1024, 256>>>(x, xh, xl);
    {
        dim3 g(3 * E_DIM / 32, E_DIM / 32);
        wsplit_t<<<g, 256>>>(W_attn, wah, wal, 3 * E_DIM);
    }
    {
        dim3 g(E_DIM / 32, E_DIM / 32);
        wsplit_t<<<g, 256>>>(W_proj, wph, wpl, E_DIM);
    }

    // 1) QKV GEMM (tensor cores) -> g_q/g_k/g_v
    {
        dim3 grid(3 * E_DIM / 128, BS / 128);
        gemm_mma<3072, 0><<<grid, 256, GEMM_SMEM>>>(xh, xl, wah, wal, b_attn, nullptr);
    }

    // 2) causal flash attention -> g_y
    {
        dim3 grid(SEQ / 64, HEADS, BATCH);
        flash_attn<<<grid, 128, 4 * 64 * FST * sizeof(float)>>>();
    }

    // 3) split y, proj GEMM -> out
    split_f32<<<BS * E_DIM / 1024, 256>>>(y, yh, yl);
    {
        dim3 grid(E_DIM / 128, BS / 128);
        gemm_mma<1024, 1><<<grid, 256, GEMM_SMEM>>>(yh, yl, wph, wpl, b_proj, out);
    }
}

// round 4
// speedup vs baseline: 2.2159x; 1.3056x over previous
#include <cuda_runtime.h>
#include <cuda_bf16.h>
#include <cstdint>

#define E_DIM 1024
#define HEADS 16
#define HD 64
#define BATCH 4
#define SEQ 2048
#define BS (BATCH*SEQ)   // 8192

// ---------------- scratch (device globals: allocation-guard safe) ----------
__device__ __align__(16) __nv_bfloat16 g_qh[BATCH*HEADS*SEQ*HD];
__device__ __align__(16) __nv_bfloat16 g_ql[BATCH*HEADS*SEQ*HD];
__device__ __align__(16) __nv_bfloat16 g_kh[BATCH*HEADS*SEQ*HD];
__device__ __align__(16) __nv_bfloat16 g_kl[BATCH*HEADS*SEQ*HD];
__device__ __align__(16) __nv_bfloat16 g_vh[BATCH*HEADS*SEQ*HD];
__device__ __align__(16) __nv_bfloat16 g_vl[BATCH*HEADS*SEQ*HD];

__device__ __align__(16) __nv_bfloat16 g_xh[BS*E_DIM];
__device__ __align__(16) __nv_bfloat16 g_xl[BS*E_DIM];
__device__ __align__(16) __nv_bfloat16 g_yh[BS*E_DIM];
__device__ __align__(16) __nv_bfloat16 g_yl[BS*E_DIM];
__device__ __align__(16) __nv_bfloat16 g_wah[3*E_DIM*E_DIM];  // W_attn^T hi [3072,1024]
__device__ __align__(16) __nv_bfloat16 g_wal[3*E_DIM*E_DIM];  // W_attn^T lo
__device__ __align__(16) __nv_bfloat16 g_wph[E_DIM*E_DIM];    // W_proj^T hi [1024,1024]
__device__ __align__(16) __nv_bfloat16 g_wpl[E_DIM*E_DIM];    // W_proj^T lo

// ---------------- PTX helpers (all valid at compute_103) --------------------
__device__ __forceinline__ uint32_t smem_u32(const void* p) {
    uint32_t a;
    asm("{ .reg .u64 t; cvta.to.shared.u64 t, %1; cvt.u32.u64 %0, t; }"
        : "=r"(a) : "l"(p));
    return a;
}
#define CP_ASYNC16(sa, ga) \
    asm volatile("cp.async.cg.shared.global [%0], [%1], 16;" :: "r"(sa), "l"(ga))
#define CP_COMMIT() asm volatile("cp.async.commit_group;" ::: "memory")
#define CP_WAIT0()  asm volatile("cp.async.wait_group 0;" ::: "memory")

__device__ __forceinline__ void ldsm_x4(uint32_t& r0, uint32_t& r1,
                                        uint32_t& r2, uint32_t& r3, uint32_t addr) {
    asm volatile("ldmatrix.sync.aligned.m8n8.x4.shared.b16 {%0,%1,%2,%3}, [%4];"
                 : "=r"(r0), "=r"(r1), "=r"(r2), "=r"(r3) : "r"(addr));
}
__device__ __forceinline__ void ldsm_x4t(uint32_t& r0, uint32_t& r1,
                                         uint32_t& r2, uint32_t& r3, uint32_t addr) {
    asm volatile("ldmatrix.sync.aligned.m8n8.x4.trans.shared.b16 {%0,%1,%2,%3}, [%4];"
                 : "=r"(r0), "=r"(r1), "=r"(r2), "=r"(r3) : "r"(addr));
}
__device__ __forceinline__ void mma16816(float* d, const uint32_t* a, const uint32_t* b) {
    asm volatile(
        "mma.sync.aligned.m16n8k16.row.col.f32.bf16.bf16.f32 "
        "{%0,%1,%2,%3}, {%4,%5,%6,%7}, {%8,%9}, {%0,%1,%2,%3};"
        : "+f"(d[0]), "+f"(d[1]), "+f"(d[2]), "+f"(d[3])
        : "r"(a[0]), "r"(a[1]), "r"(a[2]), "r"(a[3]), "r"(b[0]), "r"(b[1]));
}
__device__ __forceinline__ void mma2(float* d, const uint32_t* a, uint32_t b0, uint32_t b1) {
    asm volatile(
        "mma.sync.aligned.m16n8k16.row.col.f32.bf16.bf16.f32 "
        "{%0,%1,%2,%3}, {%4,%5,%6,%7}, {%8,%9}, {%0,%1,%2,%3};"
        : "+f"(d[0]), "+f"(d[1]), "+f"(d[2]), "+f"(d[3])
        : "r"(a[0]), "r"(a[1]), "r"(a[2]), "r"(a[3]), "r"(b0), "r"(b1));
}
__device__ __forceinline__ uint32_t pack_bf(float lo, float hi) {
    __nv_bfloat162 v = __floats2bfloat162_rn(lo, hi);
    return *reinterpret_cast<uint32_t*>(&v);
}

// ---------------- prep kernels ---------------------------------------------
__global__ __launch_bounds__(256)
void split_f32(const float* __restrict__ src,
               __nv_bfloat16* __restrict__ hi, __nv_bfloat16* __restrict__ lo)
{
    int i = (blockIdx.x * 256 + threadIdx.x) * 4;
    float4 v = *(const float4*)(src + i);
    __nv_bfloat16 h0 = __float2bfloat16(v.x), h1 = __float2bfloat16(v.y);
    __nv_bfloat16 h2 = __float2bfloat16(v.z), h3 = __float2bfloat16(v.w);
    __nv_bfloat162 H0 = {h0, h1}, H1 = {h2, h3};
    __nv_bfloat162 L0 = {__float2bfloat16(v.x - __bfloat162float(h0)),
                         __float2bfloat16(v.y - __bfloat162float(h1))};
    __nv_bfloat162 L1 = {__float2bfloat16(v.z - __bfloat162float(h2)),
                         __float2bfloat16(v.w - __bfloat162float(h3))};
    *(__nv_bfloat162*)(hi + i)     = H0;
    *(__nv_bfloat162*)(hi + i + 2) = H1;
    *(__nv_bfloat162*)(lo + i)     = L0;
    *(__nv_bfloat162*)(lo + i + 2) = L1;
}

// W [1024, N] row-major -> Wt hi/lo [N, 1024]
__global__ __launch_bounds__(256)
void wsplit_t(const float* __restrict__ W,
              __nv_bfloat16* __restrict__ Wh, __nv_bfloat16* __restrict__ Wl, int N)
{
    __shared__ float tile[32][33];
    int c0 = blockIdx.x * 32;
    int r0 = blockIdx.y * 32;
    int tx = threadIdx.x & 31, ty = threadIdx.x >> 5;
    #pragma unroll
    for (int i = ty; i < 32; i += 8)
        tile[i][tx] = W[(size_t)(r0 + i) * N + c0 + tx];
    __syncthreads();
    #pragma unroll
    for (int i = ty; i < 32; i += 8) {
        float v = tile[tx][i];
        __nv_bfloat16 h = __float2bfloat16(v);
        size_t o = (size_t)(c0 + i) * 1024 + r0 + tx;
        Wh[o] = h;
        Wl[o] = __float2bfloat16(v - __bfloat162float(h));
    }
}

// ---------------- HMMA GEMM -------------------------------------------------
// C[8192, NTOT] = A[8192,1024] @ Wt^T + bias, Wt stored [NTOT,1024] K-major.
// C = Ah*Bh + Ah*Bl + Al*Bh via mma.sync m16n8k16 bf16, fp32 accum.
// MODE 0: epilogue -> q/k/v bf16 hi/lo in [B,H,S,D] (q pre-scaled by 1/8)
// MODE 1: epilogue -> out fp32 [8192,1024]
#define GEMM_SMEM 65536

template<int NTOT, int MODE>
__global__ __launch_bounds__(256)
void gemm_mma(const __nv_bfloat16* __restrict__ Ah, const __nv_bfloat16* __restrict__ Al,
              const __nv_bfloat16* __restrict__ Bh, const __nv_bfloat16* __restrict__ Bl,
              const float* __restrict__ bias, float* __restrict__ out)
{
    extern __shared__ char smem[];
    const uint32_t sb = smem_u32(smem);
    const int tid  = threadIdx.x;
    const int wid  = tid >> 5;
    const int lane = tid & 31;
    const int m0 = blockIdx.y * 128;
    const int n0 = blockIdx.x * 128;

    const int wm = wid & 1;
    const int wn = wid >> 1;
    const int lr = lane & 7;
    const int lg = lane >> 3;

    float acc[4][4][4];
    #pragma unroll
    for (int i = 0; i < 4; i++)
        #pragma unroll
        for (int j = 0; j < 4; j++)
            #pragma unroll
            for (int r = 0; r < 4; r++) acc[i][j][r] = 0.0f;

    auto load_chunk = [&](int c) {
        const int k0 = c * 32;
        const uint32_t sbase = sb + (uint32_t)(c & 1) * 32768u;
        #pragma unroll
        for (int t = 0; t < 2; t++) {
            int u = tid + t * 256;
            int r = u >> 2, seg = u & 3;
            uint32_t soff = (uint32_t)(r * 64 + ((seg ^ ((r >> 1) & 3)) << 4));
            size_t ga = (size_t)(m0 + r) * 1024 + k0 + seg * 8;
            size_t gb = (size_t)(n0 + r) * 1024 + k0 + seg * 8;
            CP_ASYNC16(sbase + soff,          Ah + ga);
            CP_ASYNC16(sbase + 8192  + soff,  Al + ga);
            CP_ASYNC16(sbase + 16384 + soff,  Bh + gb);
            CP_ASYNC16(sbase + 24576 + soff,  Bl + gb);
        }
        CP_COMMIT();
    };

    load_chunk(0);

    for (int c = 0; c < 32; c++) {
        CP_WAIT0();
        __syncthreads();
        if (c + 1 < 32) load_chunk(c + 1);

        const uint32_t sbase = sb + (uint32_t)(c & 1) * 32768u;
        #pragma unroll
        for (int s = 0; s < 2; s++) {
            uint32_t ah[4][4], al[4][4], bh[4][2], bl[4][2];
            #pragma unroll
            for (int i = 0; i < 4; i++) {
                int row = wm * 64 + i * 16 + lr + (lg & 1) * 8;
                int seg = 2 * s + (lg >> 1);
                uint32_t ad = sbase + (uint32_t)(row * 64 +
                              ((seg ^ ((row >> 1) & 3)) << 4));
                ldsm_x4(ah[i][0], ah[i][1], ah[i][2], ah[i][3], ad);
                ldsm_x4(al[i][0], al[i][1], al[i][2], al[i][3], ad + 8192);
            }
            #pragma unroll
            for (int p = 0; p < 2; p++) {
                int row = wn * 32 + p * 16 + lr + (lg >> 1) * 8;
                int seg = 2 * s + (lg & 1);
                uint32_t bd = sbase + 16384u + (uint32_t)(row * 64 +
                              ((seg ^ ((row >> 1) & 3)) << 4));
                uint32_t r0, r1, r2, r3;
                ldsm_x4(r0, r1, r2, r3, bd);
                bh[2*p][0] = r0; bh[2*p][1] = r1;
                bh[2*p+1][0] = r2; bh[2*p+1][1] = r3;
                ldsm_x4(r0, r1, r2, r3, bd + 8192);
                bl[2*p][0] = r0; bl[2*p][1] = r1;
                bl[2*p+1][0] = r2; bl[2*p+1][1] = r3;
            }
            #pragma unroll
            for (int i = 0; i < 4; i++)
                #pragma unroll
                for (int j = 0; j < 4; j++) {
                    mma16816(acc[i][j], ah[i], bh[j]);
                    mma16816(acc[i][j], ah[i], bl[j]);
                    mma16816(acc[i][j], al[i], bh[j]);
                }
        }
    }

    const int mrow = m0 + wm * 64 + (lane >> 2);
    const int ncol = n0 + wn * 32 + (lane & 3) * 2;
    #pragma unroll
    for (int i = 0; i < 4; i++) {
        #pragma unroll
        for (int j = 0; j < 4; j++) {
            int m = mrow + i * 16;
            int n = ncol + j * 8;
            float b0 = __ldg(&bias[n]), b1 = __ldg(&bias[n + 1]);
            float f0 = acc[i][j][0] + b0, f1 = acc[i][j][1] + b1;
            float f2 = acc[i][j][2] + b0, f3 = acc[i][j][3] + b1;
            if (MODE == 0) {
                int sec = n >> 10;
                int e   = n & 1023;
                int hh  = e >> 6;
                int d   = e & 63;
                float sc = (sec == 0) ? 0.125f : 1.0f;
                f0 *= sc; f1 *= sc; f2 *= sc; f3 *= sc;
                __nv_bfloat16 *dh, *dl;
                if (sec == 0)      { dh = g_qh; dl = g_ql; }
                else if (sec == 1) { dh = g_kh; dl = g_kl; }
                else               { dh = g_vh; dl = g_vl; }
                int b_ = m >> 11, s_ = m & 2047;
                size_t o0 = ((size_t)((b_ * HEADS + hh) * SEQ) + s_) * HD + d;
                size_t o1 = o0 + 8 * HD;
                __nv_bfloat162 h0 = __floats2bfloat162_rn(f0, f1);
                __nv_bfloat162 h1 = __floats2bfloat162_rn(f2, f3);
                __nv_bfloat162 l0 = __floats2bfloat162_rn(
                    f0 - __bfloat162float(h0.x), f1 - __bfloat162float(h0.y));
                __nv_bfloat162 l1 = __floats2bfloat162_rn(
                    f2 - __bfloat162float(h1.x), f3 - __bfloat162float(h1.y));
                *(__nv_bfloat162*)(dh + o0) = h0;
                *(__nv_bfloat162*)(dl + o0) = l0;
                *(__nv_bfloat162*)(dh + o1) = h1;
                *(__nv_bfloat162*)(dl + o1) = l1;
            } else {
                *(float2*)(out + (size_t)m * 1024 + n) = {f0, f1};
                *(float2*)(out + (size_t)(m + 8) * 1024 + n) = {f2, f3};
            }
        }
    }
}

// ---------------- HMMA flash attention --------------------------------------
// 64x64 tiles, 4 warps, warp = 16 q rows. QK^T and PV on tensor cores with
// hi/lo bf16 split (3 products each). P stays in registers (C->A fragment).
// smem: Qh(8K) Ql(8K) + 2 x [Kh Kl Vh Vl](8K each).
#define ATT_SMEM (16384 + 2*32768)   // 81920

__global__ __launch_bounds__(128)
void flash_attn_mma()
{
    extern __shared__ char smc[];
    const uint32_t sb = smem_u32(smc);
    const int tid  = threadIdx.x;
    const int wid  = tid >> 5;
    const int lane = tid & 31;
    const int lr = lane & 7;
    const int lg = lane >> 3;
    const int g  = lane >> 2;
    const int t2 = (lane & 3) * 2;

    const int qi = (int)gridDim.x - 1 - (int)blockIdx.x;   // heavy blocks first
    const int hh = blockIdx.y;
    const int bb = blockIdx.z;
    const size_t bhof = ((size_t)(bb * HEADS + hh)) * SEQ * HD;

    const __nv_bfloat16* qh_g = g_qh + bhof;
    const __nv_bfloat16* ql_g = g_ql + bhof;
    const __nv_bfloat16* kh_g = g_kh + bhof;
    const __nv_bfloat16* kl_g = g_kl + bhof;
    const __nv_bfloat16* vh_g = g_vh + bhof;
    const __nv_bfloat16* vl_g = g_vl + bhof;

    const uint32_t QH = sb, QL = sb + 8192;
    const uint32_t BUF0 = sb + 16384;

    // Q tile load (hi/lo), rows qi*64..+63
    #pragma unroll
    for (int u = tid; u < 512; u += 128) {
        int row = u >> 3, seg = u & 7;
        uint32_t so = (uint32_t)(row * 128 + ((seg ^ (row & 7)) << 4));
        size_t go = (size_t)(qi * 64 + row) * 64 + seg * 8;
        CP_ASYNC16(QH + so, qh_g + go);
        CP_ASYNC16(QL + so, ql_g + go);
    }

    auto load_kv = [&](int kj2) {
        uint32_t base = BUF0 + (uint32_t)(kj2 & 1) * 32768u;
        #pragma unroll
        for (int u = tid; u < 512; u += 128) {
            int row = u >> 3, seg = u & 7;
            uint32_t so = (uint32_t)(row * 128 + ((seg ^ (row & 7)) << 4));
            size_t go = (size_t)(kj2 * 64 + row) * 64 + seg * 8;
            CP_ASYNC16(base + so,          kh_g + go);
            CP_ASYNC16(base + 8192  + so,  kl_g + go);
            CP_ASYNC16(base + 16384 + so,  vh_g + go);
            CP_ASYNC16(base + 24576 + so,  vl_g + go);
        }
    };
    load_kv(0);
    CP_COMMIT();

    uint32_t qfh[4][4], qfl[4][4];
    float y[8][4];
    #pragma unroll
    for (int j = 0; j < 8; j++)
        #pragma unroll
        for (int r = 0; r < 4; r++) y[j][r] = 0.0f;
    float m0 = -1e30f, m1 = -1e30f, l0 = 0.0f, l1 = 0.0f;
    bool qloaded = false;

    for (int kj = 0; kj <= qi; kj++) {
        CP_WAIT0();
        __syncthreads();
        if (kj + 1 <= qi) { load_kv(kj + 1); CP_COMMIT(); }

        if (!qloaded) {
            qloaded = true;
            #pragma unroll
            for (int kc = 0; kc < 4; kc++) {
                int row = wid * 16 + lr + (lg & 1) * 8;
                int seg = 2 * kc + (lg >> 1);
                uint32_t so = (uint32_t)(row * 128 + ((seg ^ (row & 7)) << 4));
                ldsm_x4(qfh[kc][0], qfh[kc][1], qfh[kc][2], qfh[kc][3], QH + so);
                ldsm_x4(qfl[kc][0], qfl[kc][1], qfl[kc][2], qfl[kc][3], QL + so);
            }
        }

        const uint32_t B = BUF0 + (uint32_t)(kj & 1) * 32768u;

        // ---- S = Q K^T ----
        float s[8][4];
        #pragma unroll
        for (int j = 0; j < 8; j++)
            #pragma unroll
            for (int r = 0; r < 4; r++) s[j][r] = 0.0f;

        #pragma unroll
        for (int p = 0; p < 4; p++) {
            #pragma unroll
            for (int kc = 0; kc < 4; kc++) {
                int row = p * 16 + lr + (lg >> 1) * 8;
                int seg = 2 * kc + (lg & 1);
                uint32_t so = (uint32_t)(row * 128 + ((seg ^ (row & 7)) << 4));
                uint32_t kh0, kh1, kh2, kh3, kl0, kl1, kl2, kl3;
                ldsm_x4(kh0, kh1, kh2, kh3, B + so);
                ldsm_x4(kl0, kl1, kl2, kl3, B + 8192 + so);
                mma2(s[2*p],   qfh[kc], kh0, kh1);
                mma2(s[2*p],   qfh[kc], kl0, kl1);
                mma2(s[2*p],   qfl[kc], kh0, kh1);
                mma2(s[2*p+1], qfh[kc], kh2, kh3);
                mma2(s[2*p+1], qfh[kc], kl2, kl3);
                mma2(s[2*p+1], qfl[kc], kh2, kh3);
            }
        }

        // ---- causal mask (diagonal tile) ----
        if (kj == qi) {
            int qr0 = wid * 16 + g;
            #pragma unroll
            for (int j = 0; j < 8; j++) {
                int c0 = j * 8 + t2;
                if (c0     > qr0)     s[j][0] = -1e30f;
                if (c0 + 1 > qr0)     s[j][1] = -1e30f;
                if (c0     > qr0 + 8) s[j][2] = -1e30f;
                if (c0 + 1 > qr0 + 8) s[j][3] = -1e30f;
            }
        }

        // ---- online softmax ----
        float mx0 = -1e30f, mx1 = -1e30f;
        #pragma unroll
        for (int j = 0; j < 8; j++) {
            mx0 = fmaxf(mx0, fmaxf(s[j][0], s[j][1]));
            mx1 = fmaxf(mx1, fmaxf(s[j][2], s[j][3]));
        }
        mx0 = fmaxf(mx0, __shfl_xor_sync(0xffffffffu, mx0, 1));
        mx0 = fmaxf(mx0, __shfl_xor_sync(0xffffffffu, mx0, 2));
        mx1 = fmaxf(mx1, __shfl_xor_sync(0xffffffffu, mx1, 1));
        mx1 = fmaxf(mx1, __shfl_xor_sync(0xffffffffu, mx1, 2));
        float mn0 = fmaxf(m0, mx0), mn1 = fmaxf(m1, mx1);
        float a0 = __expf(m0 - mn0), a1 = __expf(m1 - mn1);
        m0 = mn0; m1 = mn1;

        float s0 = 0.0f, s1 = 0.0f;
        uint32_t ph[4][4], pl[4][4];
        #pragma unroll
        for (int j = 0; j < 8; j++) {
            float p00 = __expf(s[j][0] - mn0);
            float p01 = __expf(s[j][1] - mn0);
            float p10 = __expf(s[j][2] - mn1);
            float p11 = __expf(s[j][3] - mn1);
            s0 += p00 + p01;
            s1 += p10 + p11;
            __nv_bfloat16 b00 = __float2bfloat16_rn(p00);
            __nv_bfloat16 b01 = __float2bfloat16_rn(p01);
            __nv_bfloat16 b10 = __float2bfloat16_rn(p10);
            __nv_bfloat16 b11 = __float2bfloat16_rn(p11);
            uint32_t hA, hB, lA, lB;
            { __nv_bfloat162 v = {b00, b01}; hA = *(uint32_t*)&v; }
            { __nv_bfloat162 v = {b10, b11}; hB = *(uint32_t*)&v; }
            lA = pack_bf(p00 - __bfloat162float(b00), p01 - __bfloat162float(b01));
            lB = pack_bf(p10 - __bfloat162float(b10), p11 - __bfloat162float(b11));
            int kc = j >> 1;
            if ((j & 1) == 0) {
                ph[kc][0] = hA; ph[kc][1] = hB;
                pl[kc][0] = lA; pl[kc][1] = lB;
            } else {
                ph[kc][2] = hA; ph[kc][3] = hB;
                pl[kc][2] = lA; pl[kc][3] = lB;
            }
        }
        s0 += __shfl_xor_sync(0xffffffffu, s0, 1);
        s0 += __shfl_xor_sync(0xffffffffu, s0, 2);
        s1 += __shfl_xor_sync(0xffffffffu, s1, 1);
        s1 += __shfl_xor_sync(0xffffffffu, s1, 2);
        l0 = l0 * a0 + s0;
        l1 = l1 * a1 + s1;
        #pragma unroll
        for (int j = 0; j < 8; j++) {
            y[j][0] *= a0; y[j][1] *= a0;
            y[j][2] *= a1; y[j][3] *= a1;
        }

        // ---- Y += P V ----
        #pragma unroll
        for (int dg = 0; dg < 4; dg++) {
            #pragma unroll
            for (int kc = 0; kc < 4; kc++) {
                int row = kc * 16 + (lg & 1) * 8 + lr;
                int seg = 2 * dg + (lg >> 1);
                uint32_t so = (uint32_t)(row * 128 + ((seg ^ (row & 7)) << 4));
                uint32_t vh0, vh1, vh2, vh3, vl0, vl1, vl2, vl3;
                ldsm_x4t(vh0, vh1, vh2, vh3, B + 16384 + so);
                ldsm_x4t(vl0, vl1, vl2, vl3, B + 24576 + so);
                mma2(y[2*dg],   ph[kc], vh0, vh1);
                mma2(y[2*dg],   ph[kc], vl0, vl1);
                mma2(y[2*dg],   pl[kc], vh0, vh1);
                mma2(y[2*dg+1], ph[kc], vh2, vh3);
                mma2(y[2*dg+1], ph[kc], vl2, vl3);
                mma2(y[2*dg+1], pl[kc], vh2, vh3);
            }
        }
    }

    // ---- epilogue: normalize + split hi/lo -> g_yh / g_yl [B,S,E] ----
    const float i0 = 1.0f / l0, i1 = 1.0f / l1;
    const int r0 = qi * 64 + wid * 16 + g;
    const int r1 = r0 + 8;
    const size_t rb0 = ((size_t)(bb * SEQ + r0)) * E_DIM + hh * HD;
    const size_t rb1 = ((size_t)(bb * SEQ + r1)) * E_DIM + hh * HD;
    #pragma unroll
    for (int j = 0; j < 8; j++) {
        int col = j * 8 + t2;
        float f0 = y[j][0] * i0, f1 = y[j][1] * i0;
        float f2 = y[j][2] * i1, f3 = y[j][3] * i1;
        __nv_bfloat162 h0 = __floats2bfloat162_rn(f0, f1);
        __nv_bfloat162 h1 = __floats2bfloat162_rn(f2, f3);
        __nv_bfloat162 l0p = __floats2bfloat162_rn(
            f0 - __bfloat162float(h0.x), f1 - __bfloat162float(h0.y));
        __nv_bfloat162 l1p = __floats2bfloat162_rn(
            f2 - __bfloat162float(h1.x), f3 - __bfloat162float(h1.y));
        *(__nv_bfloat162*)(g_yh + rb0 + col) = h0;
        *(__nv_bfloat162*)(g_yl + rb0 + col) = l0p;
        *(__nv_bfloat162*)(g_yh + rb1 + col) = h1;
        *(__nv_bfloat162*)(g_yl + rb1 + col) = l1p;
    }
}

// ---------------------------------------------------------------------------
extern "C" void kernel_launch(void* const* d_in, const int* in_sizes, int n_in,
                              void* d_out, int out_size)
{
    const float* x      = (const float*)d_in[0];
    const float* W_attn = (const float*)d_in[1];
    const float* b_attn = (const float*)d_in[2];
    const float* W_proj = (const float*)d_in[3];
    const float* b_proj = (const float*)d_in[4];
    float* out = (float*)d_out;

    cudaFuncSetAttribute(flash_attn_mma,
                         cudaFuncAttributeMaxDynamicSharedMemorySize, ATT_SMEM);
    cudaFuncSetAttribute(gemm_mma<3072, 0>,
                         cudaFuncAttributeMaxDynamicSharedMemorySize, GEMM_SMEM);
    cudaFuncSetAttribute(gemm_mma<1024, 1>,
                         cudaFuncAttributeMaxDynamicSharedMemorySize, GEMM_SMEM);

    __nv_bfloat16 *xh, *xl, *yh, *yl, *wah, *wal, *wph, *wpl;
    cudaGetSymbolAddress((void**)&xh,  g_xh);
    cudaGetSymbolAddress((void**)&xl,  g_xl);
    cudaGetSymbolAddress((void**)&yh,  g_yh);
    cudaGetSymbolAddress((void**)&yl,  g_yl);
    cudaGetSymbolAddress((void**)&wah, g_wah);
    cudaGetSymbolAddress((void**)&wal, g_wal);
    cudaGetSymbolAddress((void**)&wph, g_wph);
    cudaGetSymbolAddress((void**)&wpl, g_wpl);

    // prep
    split_f32<<<BS * E_DIM / 1024, 256>>>(x, xh, xl);
    {
        dim3 g(3 * E_DIM / 32, E_DIM / 32);
        wsplit_t<<<g, 256>>>(W_attn, wah, wal, 3 * E_DIM);
    }
    {
        dim3 g(E_DIM / 32, E_DIM / 32);
        wsplit_t<<<g, 256>>>(W_proj, wph, wpl, E_DIM);
    }

    // 1) QKV GEMM -> q/k/v bf16 hi/lo (q pre-scaled)
    {
        dim3 grid(3 * E_DIM / 128, BS / 128);
        gemm_mma<3072, 0><<<grid, 256, GEMM_SMEM>>>(xh, xl, wah, wal, b_attn, nullptr);
    }

    // 2) causal flash attention (HMMA) -> yh/yl
    {
        dim3 grid(SEQ / 64, HEADS, BATCH);
        flash_attn_mma<<<grid, 128, ATT_SMEM>>>();
    }

    // 3) proj GEMM -> out
    {
        dim3 grid(E_DIM / 128, BS / 128);
        gemm_mma<1024, 1><<<grid, 256, GEMM_SMEM>>>(yh, yl, wph, wpl, b_proj, out);
    }
}

// round 5
// speedup vs baseline: 3.4420x; 1.5533x over previous
#include <cuda_runtime.h>
#include <cuda_bf16.h>
#include <cstdint>

#define E_DIM 1024
#define HEADS 16
#define HD 64
#define BATCH 4
#define SEQ 2048
#define BS (BATCH*SEQ)   // 8192

// ---------------- scratch (device globals: allocation-guard safe) ----------
__device__ __align__(16) float g_q[BATCH*HEADS*SEQ*HD];
__device__ __align__(16) float g_k[BATCH*HEADS*SEQ*HD];
__device__ __align__(16) float g_v[BATCH*HEADS*SEQ*HD];

__device__ __align__(16) __nv_bfloat16 g_qh[BATCH*HEADS*SEQ*HD];
__device__ __align__(16) __nv_bfloat16 g_ql[BATCH*HEADS*SEQ*HD];
__device__ __align__(16) __nv_bfloat16 g_kh[BATCH*HEADS*SEQ*HD];
__device__ __align__(16) __nv_bfloat16 g_kl[BATCH*HEADS*SEQ*HD];
__device__ __align__(16) __nv_bfloat16 g_vh[BATCH*HEADS*SEQ*HD];
__device__ __align__(16) __nv_bfloat16 g_vl[BATCH*HEADS*SEQ*HD];

__device__ __align__(16) __nv_bfloat16 g_xh[BS*E_DIM];
__device__ __align__(16) __nv_bfloat16 g_xl[BS*E_DIM];
__device__ __align__(16) __nv_bfloat16 g_yh[BS*E_DIM];
__device__ __align__(16) __nv_bfloat16 g_yl[BS*E_DIM];
__device__ __align__(16) __nv_bfloat16 g_wah[3*E_DIM*E_DIM];
__device__ __align__(16) __nv_bfloat16 g_wal[3*E_DIM*E_DIM];
__device__ __align__(16) __nv_bfloat16 g_wph[E_DIM*E_DIM];
__device__ __align__(16) __nv_bfloat16 g_wpl[E_DIM*E_DIM];

// ---------------- PTX helpers (all valid at compute_103) --------------------
__device__ __forceinline__ uint32_t smem_u32(const void* p) {
    uint32_t a;
    asm("{ .reg .u64 t; cvta.to.shared.u64 t, %1; cvt.u32.u64 %0, t; }"
        : "=r"(a) : "l"(p));
    return a;
}
#define CP_ASYNC16(sa, ga) \
    asm volatile("cp.async.cg.shared.global [%0], [%1], 16;" :: "r"(sa), "l"(ga))
#define CP_COMMIT() asm volatile("cp.async.commit_group;" ::: "memory")
#define CP_WAIT0()  asm volatile("cp.async.wait_group 0;" ::: "memory")

__device__ __forceinline__ void ldsm_x4(uint32_t& r0, uint32_t& r1,
                                        uint32_t& r2, uint32_t& r3, uint32_t addr) {
    asm volatile("ldmatrix.sync.aligned.m8n8.x4.shared.b16 {%0,%1,%2,%3}, [%4];"
                 : "=r"(r0), "=r"(r1), "=r"(r2), "=r"(r3) : "r"(addr));
}
__device__ __forceinline__ void ldsm_x4t(uint32_t& r0, uint32_t& r1,
                                         uint32_t& r2, uint32_t& r3, uint32_t addr) {
    asm volatile("ldmatrix.sync.aligned.m8n8.x4.trans.shared.b16 {%0,%1,%2,%3}, [%4];"
                 : "=r"(r0), "=r"(r1), "=r"(r2), "=r"(r3) : "r"(addr));
}
__device__ __forceinline__ void mma16816(float* d, const uint32_t* a, const uint32_t* b) {
    asm volatile(
        "mma.sync.aligned.m16n8k16.row.col.f32.bf16.bf16.f32 "
        "{%0,%1,%2,%3}, {%4,%5,%6,%7}, {%8,%9}, {%0,%1,%2,%3};"
        : "+f"(d[0]), "+f"(d[1]), "+f"(d[2]), "+f"(d[3])
        : "r"(a[0]), "r"(a[1]), "r"(a[2]), "r"(a[3]), "r"(b[0]), "r"(b[1]));
}
__device__ __forceinline__ void mma2(float* d, const uint32_t* a, uint32_t b0, uint32_t b1) {
    asm volatile(
        "mma.sync.aligned.m16n8k16.row.col.f32.bf16.bf16.f32 "
        "{%0,%1,%2,%3}, {%4,%5,%6,%7}, {%8,%9}, {%0,%1,%2,%3};"
        : "+f"(d[0]), "+f"(d[1]), "+f"(d[2]), "+f"(d[3])
        : "r"(a[0]), "r"(a[1]), "r"(a[2]), "r"(a[3]), "r"(b0), "r"(b1));
}
__device__ __forceinline__ uint32_t pack_bf(float lo, float hi) {
    __nv_bfloat162 v = __floats2bfloat162_rn(lo, hi);
    return *reinterpret_cast<uint32_t*>(&v);
}

// ---------------- prep kernels ---------------------------------------------
__global__ __launch_bounds__(256)
void split_scale(const float* __restrict__ src,
                 __nv_bfloat16* __restrict__ hi, __nv_bfloat16* __restrict__ lo,
                 float sc)
{
    int i = (blockIdx.x * 256 + threadIdx.x) * 4;
    float4 v = *(const float4*)(src + i);
    v.x *= sc; v.y *= sc; v.z *= sc; v.w *= sc;
    __nv_bfloat16 h0 = __float2bfloat16(v.x), h1 = __float2bfloat16(v.y);
    __nv_bfloat16 h2 = __float2bfloat16(v.z), h3 = __float2bfloat16(v.w);
    __nv_bfloat162 H0 = {h0, h1}, H1 = {h2, h3};
    __nv_bfloat162 L0 = {__float2bfloat16(v.x - __bfloat162float(h0)),
                         __float2bfloat16(v.y - __bfloat162float(h1))};
    __nv_bfloat162 L1 = {__float2bfloat16(v.z - __bfloat162float(h2)),
                         __float2bfloat16(v.w - __bfloat162float(h3))};
    *(__nv_bfloat162*)(hi + i)     = H0;
    *(__nv_bfloat162*)(hi + i + 2) = H1;
    *(__nv_bfloat162*)(lo + i)     = L0;
    *(__nv_bfloat162*)(lo + i + 2) = L1;
}

// W [1024, N] row-major -> Wt hi/lo [N, 1024]
__global__ __launch_bounds__(256)
void wsplit_t(const float* __restrict__ W,
              __nv_bfloat16* __restrict__ Wh, __nv_bfloat16* __restrict__ Wl, int N)
{
    __shared__ float tile[32][33];
    int c0 = blockIdx.x * 32;
    int r0 = blockIdx.y * 32;
    int tx = threadIdx.x & 31, ty = threadIdx.x >> 5;
    #pragma unroll
    for (int i = ty; i < 32; i += 8)
        tile[i][tx] = W[(size_t)(r0 + i) * N + c0 + tx];
    __syncthreads();
    #pragma unroll
    for (int i = ty; i < 32; i += 8) {
        float v = tile[tx][i];
        __nv_bfloat16 h = __float2bfloat16(v);
        size_t o = (size_t)(c0 + i) * 1024 + r0 + tx;
        Wh[o] = h;
        Wl[o] = __float2bfloat16(v - __bfloat162float(h));
    }
}

// ---------------- HMMA GEMM (proven R3 shape: 121 regs, 2 CTA/SM) -----------
#define GEMM_SMEM 65536

template<int NTOT, int MODE>
__global__ __launch_bounds__(256)
void gemm_mma(const __nv_bfloat16* __restrict__ Ah, const __nv_bfloat16* __restrict__ Al,
              const __nv_bfloat16* __restrict__ Bh, const __nv_bfloat16* __restrict__ Bl,
              const float* __restrict__ bias, float* __restrict__ out)
{
    extern __shared__ char smem[];
    const uint32_t sb = smem_u32(smem);
    const int tid  = threadIdx.x;
    const int wid  = tid >> 5;
    const int lane = tid & 31;
    const int m0 = blockIdx.y * 128;
    const int n0 = blockIdx.x * 128;

    const int wm = wid & 1;
    const int wn = wid >> 1;
    const int lr = lane & 7;
    const int lg = lane >> 3;

    float acc[4][4][4];
    #pragma unroll
    for (int i = 0; i < 4; i++)
        #pragma unroll
        for (int j = 0; j < 4; j++)
            #pragma unroll
            for (int r = 0; r < 4; r++) acc[i][j][r] = 0.0f;

    auto load_chunk = [&](int c) {
        const int k0 = c * 32;
        const uint32_t sbase = sb + (uint32_t)(c & 1) * 32768u;
        #pragma unroll
        for (int t = 0; t < 2; t++) {
            int u = tid + t * 256;
            int r = u >> 2, seg = u & 3;
            uint32_t soff = (uint32_t)(r * 64 + ((seg ^ ((r >> 1) & 3)) << 4));
            size_t ga = (size_t)(m0 + r) * 1024 + k0 + seg * 8;
            size_t gb = (size_t)(n0 + r) * 1024 + k0 + seg * 8;
            CP_ASYNC16(sbase + soff,          Ah + ga);
            CP_ASYNC16(sbase + 8192  + soff,  Al + ga);
            CP_ASYNC16(sbase + 16384 + soff,  Bh + gb);
            CP_ASYNC16(sbase + 24576 + soff,  Bl + gb);
        }
        CP_COMMIT();
    };

    load_chunk(0);

    for (int c = 0; c < 32; c++) {
        CP_WAIT0();
        __syncthreads();
        if (c + 1 < 32) load_chunk(c + 1);

        const uint32_t sbase = sb + (uint32_t)(c & 1) * 32768u;
        #pragma unroll
        for (int s = 0; s < 2; s++) {
            uint32_t ah[4][4], al[4][4], bh[4][2], bl[4][2];
            #pragma unroll
            for (int i = 0; i < 4; i++) {
                int row = wm * 64 + i * 16 + lr + (lg & 1) * 8;
                int seg = 2 * s + (lg >> 1);
                uint32_t ad = sbase + (uint32_t)(row * 64 +
                              ((seg ^ ((row >> 1) & 3)) << 4));
                ldsm_x4(ah[i][0], ah[i][1], ah[i][2], ah[i][3], ad);
                ldsm_x4(al[i][0], al[i][1], al[i][2], al[i][3], ad + 8192);
            }
            #pragma unroll
            for (int p = 0; p < 2; p++) {
                int row = wn * 32 + p * 16 + lr + (lg >> 1) * 8;
                int seg = 2 * s + (lg & 1);
                uint32_t bd = sbase + 16384u + (uint32_t)(row * 64 +
                              ((seg ^ ((row >> 1) & 3)) << 4));
                uint32_t r0, r1, r2, r3;
                ldsm_x4(r0, r1, r2, r3, bd);
                bh[2*p][0] = r0; bh[2*p][1] = r1;
                bh[2*p+1][0] = r2; bh[2*p+1][1] = r3;
                ldsm_x4(r0, r1, r2, r3, bd + 8192);
                bl[2*p][0] = r0; bl[2*p][1] = r1;
                bl[2*p+1][0] = r2; bl[2*p+1][1] = r3;
            }
            #pragma unroll
            for (int i = 0; i < 4; i++)
                #pragma unroll
                for (int j = 0; j < 4; j++) {
                    mma16816(acc[i][j], ah[i], bh[j]);
                    mma16816(acc[i][j], ah[i], bl[j]);
                    mma16816(acc[i][j], al[i], bh[j]);
                }
        }
    }

    // epilogue: plain fp32 writes (low register pressure)
    const int mrow = m0 + wm * 64 + (lane >> 2);
    const int ncol = n0 + wn * 32 + (lane & 3) * 2;
    #pragma unroll
    for (int i = 0; i < 4; i++) {
        #pragma unroll
        for (int j = 0; j < 4; j++) {
            int m = mrow + i * 16;
            int n = ncol + j * 8;
            float b0 = __ldg(&bias[n]), b1 = __ldg(&bias[n + 1]);
            float2 v0 = {acc[i][j][0] + b0, acc[i][j][1] + b1};
            float2 v1 = {acc[i][j][2] + b0, acc[i][j][3] + b1};
            if (MODE == 0) {
                int sec = n >> 10;
                int e   = n & 1023;
                int h   = e >> 6;
                int d   = e & 63;
                float* q = (sec == 0) ? g_q : ((sec == 1) ? g_k : g_v);
                int b_ = m >> 11, s_ = m & 2047;
                *(float2*)(q + ((size_t)((b_ * HEADS + h) * SEQ) + s_) * HD + d) = v0;
                *(float2*)(q + ((size_t)((b_ * HEADS + h) * SEQ) + s_ + 8) * HD + d) = v1;
            } else {
                *(float2*)(out + (size_t)m * 1024 + n) = v0;
                *(float2*)(out + (size_t)(m + 8) * 1024 + n) = v1;
            }
        }
    }
}

// ---------------- HMMA flash attention --------------------------------------
// 128 q rows per CTA, 8 warps (16 rows each), KV tiles of 64 keys,
// double-buffered cp.async. Fully-masked warp-tiles are skipped.
// smem: Qh(16K) Ql(16K) + 2 x [Kh Kl Vh Vl](8K each) = 96K.
#define ATT_SMEM (32768 + 2*32768)   // 98304

__global__ __launch_bounds__(256, 2)
void flash_attn_mma()
{
    extern __shared__ char smc[];
    const uint32_t sb = smem_u32(smc);
    const int tid  = threadIdx.x;
    const int wid  = tid >> 5;       // 0..7
    const int lane = tid & 31;
    const int lr = lane & 7;
    const int lg = lane >> 3;
    const int g  = lane >> 2;
    const int t2 = (lane & 3) * 2;

    const int qi = (int)gridDim.x - 1 - (int)blockIdx.x;   // heavy blocks first
    const int qb = qi * 128;
    const int hh = blockIdx.y;
    const int bb = blockIdx.z;
    const size_t bhof = ((size_t)(bb * HEADS + hh)) * SEQ * HD;

    const __nv_bfloat16* qh_g = g_qh + bhof;
    const __nv_bfloat16* ql_g = g_ql + bhof;
    const __nv_bfloat16* kh_g = g_kh + bhof;
    const __nv_bfloat16* kl_g = g_kl + bhof;
    const __nv_bfloat16* vh_g = g_vh + bhof;
    const __nv_bfloat16* vl_g = g_vl + bhof;

    const uint32_t QH = sb, QL = sb + 16384;
    const uint32_t BUF0 = sb + 32768;

    // Q tile load (hi/lo), rows qb..qb+127
    #pragma unroll
    for (int u = tid; u < 1024; u += 256) {
        int row = u >> 3, seg = u & 7;
        uint32_t so = (uint32_t)(row * 128 + ((seg ^ (row & 7)) << 4));
        size_t go = (size_t)(qb + row) * 64 + seg * 8;
        CP_ASYNC16(QH + so, qh_g + go);
        CP_ASYNC16(QL + so, ql_g + go);
    }

    auto load_kv = [&](int kj) {
        uint32_t base = BUF0 + (uint32_t)(kj & 1) * 32768u;
        #pragma unroll
        for (int u = tid; u < 512; u += 256) {
            int row = u >> 3, seg = u & 7;
            uint32_t so = (uint32_t)(row * 128 + ((seg ^ (row & 7)) << 4));
            size_t go = (size_t)(kj * 64 + row) * 64 + seg * 8;
            CP_ASYNC16(base + so,          kh_g + go);
            CP_ASYNC16(base + 8192  + so,  kl_g + go);
            CP_ASYNC16(base + 16384 + so,  vh_g + go);
            CP_ASYNC16(base + 24576 + so,  vl_g + go);
        }
    };
    load_kv(0);
    CP_COMMIT();

    uint32_t qfh[4][4];
    float y[8][4];
    #pragma unroll
    for (int j = 0; j < 8; j++)
        #pragma unroll
        for (int r = 0; r < 4; r++) y[j][r] = 0.0f;
    float m0 = -1e30f, m1 = -1e30f, l0 = 0.0f, l1 = 0.0f;
    bool qloaded = false;

    const int nkj = 2 * qi + 2;
    const int wr0 = qb + wid * 16;   // warp's first q row (global)

    for (int kj = 0; kj < nkj; kj++) {
        CP_WAIT0();
        __syncthreads();
        if (kj + 1 < nkj) { load_kv(kj + 1); CP_COMMIT(); }

        if (!qloaded) {
            qloaded = true;
            #pragma unroll
            for (int kc = 0; kc < 4; kc++) {
                int row = wid * 16 + lr + (lg & 1) * 8;
                int seg = 2 * kc + (lg >> 1);
                uint32_t so = (uint32_t)(row * 128 + ((seg ^ (row & 7)) << 4));
                ldsm_x4(qfh[kc][0], qfh[kc][1], qfh[kc][2], qfh[kc][3], QH + so);
            }
        }

        const int c0t = kj * 64;                 // tile's first key col (global)
        if (c0t > wr0 + 15) continue;            // fully masked for this warp

        // reload Q-lo fragments (kept out of persistent registers)
        uint32_t qfl[4][4];
        #pragma unroll
        for (int kc = 0; kc < 4; kc++) {
            int row = wid * 16 + lr + (lg & 1) * 8;
            int seg = 2 * kc + (lg >> 1);
            uint32_t so = (uint32_t)(row * 128 + ((seg ^ (row & 7)) << 4));
            ldsm_x4(qfl[kc][0], qfl[kc][1], qfl[kc][2], qfl[kc][3], QL + so);
        }

        const uint32_t B = BUF0 + (uint32_t)(kj & 1) * 32768u;

        // ---- S = Q K^T ----
        float s[8][4];
        #pragma unroll
        for (int j = 0; j < 8; j++)
            #pragma unroll
            for (int r = 0; r < 4; r++) s[j][r] = 0.0f;

        #pragma unroll
        for (int p = 0; p < 4; p++) {
            #pragma unroll
            for (int kc = 0; kc < 4; kc++) {
                int row = p * 16 + lr + (lg >> 1) * 8;
                int seg = 2 * kc + (lg & 1);
                uint32_t so = (uint32_t)(row * 128 + ((seg ^ (row & 7)) << 4));
                uint32_t kh0, kh1, kh2, kh3, kl0, kl1, kl2, kl3;
                ldsm_x4(kh0, kh1, kh2, kh3, B + so);
                ldsm_x4(kl0, kl1, kl2, kl3, B + 8192 + so);
                mma2(s[2*p],   qfh[kc], kh0, kh1);
                mma2(s[2*p],   qfh[kc], kl0, kl1);
                mma2(s[2*p],   qfl[kc], kh0, kh1);
                mma2(s[2*p+1], qfh[kc], kh2, kh3);
                mma2(s[2*p+1], qfh[kc], kl2, kl3);
                mma2(s[2*p+1], qfl[kc], kh2, kh3);
            }
        }

        // ---- causal mask (global coords) ----
        if (c0t + 63 > wr0) {
            int R0 = wr0 + g, R1 = wr0 + g + 8;
            #pragma unroll
            for (int j = 0; j < 8; j++) {
                int cg = c0t + j * 8 + t2;
                if (cg     > R0) s[j][0] = -1e30f;
                if (cg + 1 > R0) s[j][1] = -1e30f;
                if (cg     > R1) s[j][2] = -1e30f;
                if (cg + 1 > R1) s[j][3] = -1e30f;
            }
        }

        // ---- online softmax ----
        float mx0 = -1e30f, mx1 = -1e30f;
        #pragma unroll
        for (int j = 0; j < 8; j++) {
            mx0 = fmaxf(mx0, fmaxf(s[j][0], s[j][1]));
            mx1 = fmaxf(mx1, fmaxf(s[j][2], s[j][3]));
        }
        mx0 = fmaxf(mx0, __shfl_xor_sync(0xffffffffu, mx0, 1));
        mx0 = fmaxf(mx0, __shfl_xor_sync(0xffffffffu, mx0, 2));
        mx1 = fmaxf(mx1, __shfl_xor_sync(0xffffffffu, mx1, 1));
        mx1 = fmaxf(mx1, __shfl_xor_sync(0xffffffffu, mx1, 2));
        float mn0 = fmaxf(m0, mx0), mn1 = fmaxf(m1, mx1);
        float a0 = __expf(m0 - mn0), a1 = __expf(m1 - mn1);
        m0 = mn0; m1 = mn1;

        float s0 = 0.0f, s1 = 0.0f;
        uint32_t ph[4][4], pl[4][4];
        #pragma unroll
        for (int j = 0; j < 8; j++) {
            float p00 = __expf(s[j][0] - mn0);
            float p01 = __expf(s[j][1] - mn0);
            float p10 = __expf(s[j][2] - mn1);
            float p11 = __expf(s[j][3] - mn1);
            s0 += p00 + p01;
            s1 += p10 + p11;
            __nv_bfloat16 b00 = __float2bfloat16_rn(p00);
            __nv_bfloat16 b01 = __float2bfloat16_rn(p01);
            __nv_bfloat16 b10 = __float2bfloat16_rn(p10);
            __nv_bfloat16 b11 = __float2bfloat16_rn(p11);
            uint32_t hA, hB, lA, lB;
            { __nv_bfloat162 v = {b00, b01}; hA = *(uint32_t*)&v; }
            { __nv_bfloat162 v = {b10, b11}; hB = *(uint32_t*)&v; }
            lA = pack_bf(p00 - __bfloat162float(b00), p01 - __bfloat162float(b01));
            lB = pack_bf(p10 - __bfloat162float(b10), p11 - __bfloat162float(b11));
            int kc = j >> 1;
            if ((j & 1) == 0) {
                ph[kc][0] = hA; ph[kc][1] = hB;
                pl[kc][0] = lA; pl[kc][1] = lB;
            } else {
                ph[kc][2] = hA; ph[kc][3] = hB;
                pl[kc][2] = lA; pl[kc][3] = lB;
            }
        }
        s0 += __shfl_xor_sync(0xffffffffu, s0, 1);
        s0 += __shfl_xor_sync(0xffffffffu, s0, 2);
        s1 += __shfl_xor_sync(0xffffffffu, s1, 1);
        s1 += __shfl_xor_sync(0xffffffffu, s1, 2);
        l0 = l0 * a0 + s0;
        l1 = l1 * a1 + s1;
        #pragma unroll
        for (int j = 0; j < 8; j++) {
            y[j][0] *= a0; y[j][1] *= a0;
            y[j][2] *= a1; y[j][3] *= a1;
        }

        // ---- Y += P V ----
        #pragma unroll
        for (int dg = 0; dg < 4; dg++) {
            #pragma unroll
            for (int kc = 0; kc < 4; kc++) {
                int row = kc * 16 + (lg & 1) * 8 + lr;
                int seg = 2 * dg + (lg >> 1);
                uint32_t so = (uint32_t)(row * 128 + ((seg ^ (row & 7)) << 4));
                uint32_t vh0, vh1, vh2, vh3, vl0, vl1, vl2, vl3;
                ldsm_x4t(vh0, vh1, vh2, vh3, B + 16384 + so);
                ldsm_x4t(vl0, vl1, vl2, vl3, B + 24576 + so);
                mma2(y[2*dg],   ph[kc], vh0, vh1);
                mma2(y[2*dg],   ph[kc], vl0, vl1);
                mma2(y[2*dg],   pl[kc], vh0, vh1);
                mma2(y[2*dg+1], ph[kc], vh2, vh3);
                mma2(y[2*dg+1], ph[kc], vl2, vl3);
                mma2(y[2*dg+1], pl[kc], vh2, vh3);
            }
        }
    }

    // ---- epilogue: normalize + split hi/lo -> g_yh / g_yl [B,S,E] ----
    const float i0 = 1.0f / l0, i1 = 1.0f / l1;
    const int r0 = wr0 + g;
    const int r1 = r0 + 8;
    const size_t rb0 = ((size_t)(bb * SEQ + r0)) * E_DIM + hh * HD;
    const size_t rb1 = ((size_t)(bb * SEQ + r1)) * E_DIM + hh * HD;
    #pragma unroll
    for (int j = 0; j < 8; j++) {
        int col = j * 8 + t2;
        float f0 = y[j][0] * i0, f1 = y[j][1] * i0;
        float f2 = y[j][2] * i1, f3 = y[j][3] * i1;
        __nv_bfloat162 h0 = __floats2bfloat162_rn(f0, f1);
        __nv_bfloat162 h1 = __floats2bfloat162_rn(f2, f3);
        __nv_bfloat162 l0p = __floats2bfloat162_rn(
            f0 - __bfloat162float(h0.x), f1 - __bfloat162float(h0.y));
        __nv_bfloat162 l1p = __floats2bfloat162_rn(
            f2 - __bfloat162float(h1.x), f3 - __bfloat162float(h1.y));
        *(__nv_bfloat162*)(g_yh + rb0 + col) = h0;
        *(__nv_bfloat162*)(g_yl + rb0 + col) = l0p;
        *(__nv_bfloat162*)(g_yh + rb1 + col) = h1;
        *(__nv_bfloat162*)(g_yl + rb1 + col) = l1p;
    }
}

// ---------------------------------------------------------------------------
extern "C" void kernel_launch(void* const* d_in, const int* in_sizes, int n_in,
                              void* d_out, int out_size)
{
    const float* x      = (const float*)d_in[0];
    const float* W_attn = (const float*)d_in[1];
    const float* b_attn = (const float*)d_in[2];
    const float* W_proj = (const float*)d_in[3];
    const float* b_proj = (const float*)d_in[4];
    float* out = (float*)d_out;

    cudaFuncSetAttribute(flash_attn_mma,
                         cudaFuncAttributeMaxDynamicSharedMemorySize, ATT_SMEM);
    cudaFuncSetAttribute(gemm_mma<3072, 0>,
                         cudaFuncAttributeMaxDynamicSharedMemorySize, GEMM_SMEM);
    cudaFuncSetAttribute(gemm_mma<1024, 1>,
                         cudaFuncAttributeMaxDynamicSharedMemorySize, GEMM_SMEM);

    __nv_bfloat16 *xh, *xl, *yh, *yl, *wah, *wal, *wph, *wpl;
    __nv_bfloat16 *qh, *ql, *kh, *kl, *vh, *vl;
    float *qf, *kf, *vf;
    cudaGetSymbolAddress((void**)&xh,  g_xh);
    cudaGetSymbolAddress((void**)&xl,  g_xl);
    cudaGetSymbolAddress((void**)&yh,  g_yh);
    cudaGetSymbolAddress((void**)&yl,  g_yl);
    cudaGetSymbolAddress((void**)&wah, g_wah);
    cudaGetSymbolAddress((void**)&wal, g_wal);
    cudaGetSymbolAddress((void**)&wph, g_wph);
    cudaGetSymbolAddress((void**)&wpl, g_wpl);
    cudaGetSymbolAddress((void**)&qh,  g_qh);
    cudaGetSymbolAddress((void**)&ql,  g_ql);
    cudaGetSymbolAddress((void**)&kh,  g_kh);
    cudaGetSymbolAddress((void**)&kl,  g_kl);
    cudaGetSymbolAddress((void**)&vh,  g_vh);
    cudaGetSymbolAddress((void**)&vl,  g_vl);
    cudaGetSymbolAddress((void**)&qf,  g_q);
    cudaGetSymbolAddress((void**)&kf,  g_k);
    cudaGetSymbolAddress((void**)&vf,  g_v);

    // prep: split x, transpose+split weights
    split_scale<<<BS * E_DIM / 1024, 256>>>(x, xh, xl, 1.0f);
    {
        dim3 g(3 * E_DIM / 32, E_DIM / 32);
        wsplit_t<<<g, 256>>>(W_attn, wah, wal, 3 * E_DIM);
    }
    {
        dim3 g(E_DIM / 32, E_DIM / 32);
        wsplit_t<<<g, 256>>>(W_proj, wph, wpl, E_DIM);
    }

    // 1) QKV GEMM -> q/k/v fp32 [B,H,S,D]
    {
        dim3 grid(3 * E_DIM / 128, BS / 128);
        gemm_mma<3072, 0><<<grid, 256, GEMM_SMEM>>>(xh, xl, wah, wal, b_attn, nullptr);
    }

    // 1b) split q/k/v to bf16 hi/lo (q pre-scaled by 1/sqrt(64))
    const int QKV_N = BATCH * HEADS * SEQ * HD;   // 8388608
    split_scale<<<QKV_N / 1024, 256>>>(qf, qh, ql, 0.125f);
    split_scale<<<QKV_N / 1024, 256>>>(kf, kh, kl, 1.0f);
    split_scale<<<QKV_N / 1024, 256>>>(vf, vh, vl, 1.0f);

    // 2) causal flash attention (HMMA) -> yh/yl
    {
        dim3 grid(SEQ / 128, HEADS, BATCH);
        flash_attn_mma<<<grid, 256, ATT_SMEM>>>();
    }

    // 3) proj GEMM -> out
    {
        dim3 grid(E_DIM / 128, BS / 128);
        gemm_mma<1024, 1><<<grid, 256, GEMM_SMEM>>>(yh, yl, wph, wpl, b_proj, out);
    }
}

// round 6
// speedup vs baseline: 3.4750x; 1.0096x over previous
#include <cuda_runtime.h>
#include <cuda_bf16.h>
#include <cstdint>

#define E_DIM 1024
#define HEADS 16
#define HD 64
#define BATCH 4
#define SEQ 2048
#define BS (BATCH*SEQ)   // 8192

// ---------------- scratch (device globals: allocation-guard safe) ----------
__device__ __align__(16) float g_q[BATCH*HEADS*SEQ*HD];
__device__ __align__(16) float g_k[BATCH*HEADS*SEQ*HD];
__device__ __align__(16) float g_v[BATCH*HEADS*SEQ*HD];

__device__ __align__(16) __nv_bfloat16 g_qh[BATCH*HEADS*SEQ*HD];
__device__ __align__(16) __nv_bfloat16 g_ql[BATCH*HEADS*SEQ*HD];
__device__ __align__(16) __nv_bfloat16 g_kh[BATCH*HEADS*SEQ*HD];
__device__ __align__(16) __nv_bfloat16 g_kl[BATCH*HEADS*SEQ*HD];
__device__ __align__(16) __nv_bfloat16 g_vh[BATCH*HEADS*SEQ*HD];
__device__ __align__(16) __nv_bfloat16 g_vl[BATCH*HEADS*SEQ*HD];

__device__ __align__(16) __nv_bfloat16 g_xh[BS*E_DIM];
__device__ __align__(16) __nv_bfloat16 g_xl[BS*E_DIM];
__device__ __align__(16) __nv_bfloat16 g_yh[BS*E_DIM];
__device__ __align__(16) __nv_bfloat16 g_yl[BS*E_DIM];
__device__ __align__(16) __nv_bfloat16 g_wah[3*E_DIM*E_DIM];
__device__ __align__(16) __nv_bfloat16 g_wal[3*E_DIM*E_DIM];
__device__ __align__(16) __nv_bfloat16 g_wph[E_DIM*E_DIM];
__device__ __align__(16) __nv_bfloat16 g_wpl[E_DIM*E_DIM];

// ---------------- PTX helpers (all valid at compute_103) --------------------
__device__ __forceinline__ uint32_t smem_u32(const void* p) {
    uint32_t a;
    asm("{ .reg .u64 t; cvta.to.shared.u64 t, %1; cvt.u32.u64 %0, t; }"
        : "=r"(a) : "l"(p));
    return a;
}
#define CP_ASYNC16(sa, ga) \
    asm volatile("cp.async.cg.shared.global [%0], [%1], 16;" :: "r"(sa), "l"(ga))
#define CP_COMMIT() asm volatile("cp.async.commit_group;" ::: "memory")
#define CP_WAIT0()  asm volatile("cp.async.wait_group 0;" ::: "memory")

__device__ __forceinline__ void ldsm_x4(uint32_t& r0, uint32_t& r1,
                                        uint32_t& r2, uint32_t& r3, uint32_t addr) {
    asm volatile("ldmatrix.sync.aligned.m8n8.x4.shared.b16 {%0,%1,%2,%3}, [%4];"
                 : "=r"(r0), "=r"(r1), "=r"(r2), "=r"(r3) : "r"(addr));
}
__device__ __forceinline__ void ldsm_x4t(uint32_t& r0, uint32_t& r1,
                                         uint32_t& r2, uint32_t& r3, uint32_t addr) {
    asm volatile("ldmatrix.sync.aligned.m8n8.x4.trans.shared.b16 {%0,%1,%2,%3}, [%4];"
                 : "=r"(r0), "=r"(r1), "=r"(r2), "=r"(r3) : "r"(addr));
}
__device__ __forceinline__ void mma16816(float* d, const uint32_t* a, const uint32_t* b) {
    asm volatile(
        "mma.sync.aligned.m16n8k16.row.col.f32.bf16.bf16.f32 "
        "{%0,%1,%2,%3}, {%4,%5,%6,%7}, {%8,%9}, {%0,%1,%2,%3};"
        : "+f"(d[0]), "+f"(d[1]), "+f"(d[2]), "+f"(d[3])
        : "r"(a[0]), "r"(a[1]), "r"(a[2]), "r"(a[3]), "r"(b[0]), "r"(b[1]));
}
__device__ __forceinline__ void mma2(float* d, const uint32_t* a, uint32_t b0, uint32_t b1) {
    asm volatile(
        "mma.sync.aligned.m16n8k16.row.col.f32.bf16.bf16.f32 "
        "{%0,%1,%2,%3}, {%4,%5,%6,%7}, {%8,%9}, {%0,%1,%2,%3};"
        : "+f"(d[0]), "+f"(d[1]), "+f"(d[2]), "+f"(d[3])
        : "r"(a[0]), "r"(a[1]), "r"(a[2]), "r"(a[3]), "r"(b0), "r"(b1));
}
__device__ __forceinline__ uint32_t pack_bf(float lo, float hi) {
    __nv_bfloat162 v = __floats2bfloat162_rn(lo, hi);
    return *reinterpret_cast<uint32_t*>(&v);
}

// ---------------- prep kernels ---------------------------------------------
__global__ __launch_bounds__(256)
void split_scale(const float* __restrict__ src,
                 __nv_bfloat16* __restrict__ hi, __nv_bfloat16* __restrict__ lo,
                 float sc)
{
    int i = (blockIdx.x * 256 + threadIdx.x) * 4;
    float4 v = *(const float4*)(src + i);
    v.x *= sc; v.y *= sc; v.z *= sc; v.w *= sc;
    __nv_bfloat16 h0 = __float2bfloat16(v.x), h1 = __float2bfloat16(v.y);
    __nv_bfloat16 h2 = __float2bfloat16(v.z), h3 = __float2bfloat16(v.w);
    __nv_bfloat162 H0 = {h0, h1}, H1 = {h2, h3};
    __nv_bfloat162 L0 = {__float2bfloat16(v.x - __bfloat162float(h0)),
                         __float2bfloat16(v.y - __bfloat162float(h1))};
    __nv_bfloat162 L1 = {__float2bfloat16(v.z - __bfloat162float(h2)),
                         __float2bfloat16(v.w - __bfloat162float(h3))};
    *(__nv_bfloat162*)(hi + i)     = H0;
    *(__nv_bfloat162*)(hi + i + 2) = H1;
    *(__nv_bfloat162*)(lo + i)     = L0;
    *(__nv_bfloat162*)(lo + i + 2) = L1;
}

// W [1024, N] row-major -> Wt hi/lo [N, 1024]
__global__ __launch_bounds__(256)
void wsplit_t(const float* __restrict__ W,
              __nv_bfloat16* __restrict__ Wh, __nv_bfloat16* __restrict__ Wl, int N)
{
    __shared__ float tile[32][33];
    int c0 = blockIdx.x * 32;
    int r0 = blockIdx.y * 32;
    int tx = threadIdx.x & 31, ty = threadIdx.x >> 5;
    #pragma unroll
    for (int i = ty; i < 32; i += 8)
        tile[i][tx] = W[(size_t)(r0 + i) * N + c0 + tx];
    __syncthreads();
    #pragma unroll
    for (int i = ty; i < 32; i += 8) {
        float v = tile[tx][i];
        __nv_bfloat16 h = __float2bfloat16(v);
        size_t o = (size_t)(c0 + i) * 1024 + r0 + tx;
        Wh[o] = h;
        Wl[o] = __float2bfloat16(v - __bfloat162float(h));
    }
}

// ---------------- HMMA GEMM -------------------------------------------------
#define GEMM_SMEM 65536

template<int NTOT, int MODE>
__global__ __launch_bounds__(256)
void gemm_mma(const __nv_bfloat16* __restrict__ Ah, const __nv_bfloat16* __restrict__ Al,
              const __nv_bfloat16* __restrict__ Bh, const __nv_bfloat16* __restrict__ Bl,
              const float* __restrict__ bias, float* __restrict__ out)
{
    extern __shared__ char smem[];
    const uint32_t sb = smem_u32(smem);
    const int tid  = threadIdx.x;
    const int wid  = tid >> 5;
    const int lane = tid & 31;
    const int m0 = blockIdx.y * 128;
    const int n0 = blockIdx.x * 128;

    const int wm = wid & 1;
    const int wn = wid >> 1;
    const int lr = lane & 7;
    const int lg = lane >> 3;

    float acc[4][4][4];
    #pragma unroll
    for (int i = 0; i < 4; i++)
        #pragma unroll
        for (int j = 0; j < 4; j++)
            #pragma unroll
            for (int r = 0; r < 4; r++) acc[i][j][r] = 0.0f;

    auto load_chunk = [&](int c) {
        const int k0 = c * 32;
        const uint32_t sbase = sb + (uint32_t)(c & 1) * 32768u;
        #pragma unroll
        for (int t = 0; t < 2; t++) {
            int u = tid + t * 256;
            int r = u >> 2, seg = u & 3;
            uint32_t soff = (uint32_t)(r * 64 + ((seg ^ ((r >> 1) & 3)) << 4));
            size_t ga = (size_t)(m0 + r) * 1024 + k0 + seg * 8;
            size_t gb = (size_t)(n0 + r) * 1024 + k0 + seg * 8;
            CP_ASYNC16(sbase + soff,          Ah + ga);
            CP_ASYNC16(sbase + 8192  + soff,  Al + ga);
            CP_ASYNC16(sbase + 16384 + soff,  Bh + gb);
            CP_ASYNC16(sbase + 24576 + soff,  Bl + gb);
        }
        CP_COMMIT();
    };

    load_chunk(0);

    for (int c = 0; c < 32; c++) {
        CP_WAIT0();
        __syncthreads();
        if (c + 1 < 32) load_chunk(c + 1);

        const uint32_t sbase = sb + (uint32_t)(c & 1) * 32768u;
        #pragma unroll
        for (int s = 0; s < 2; s++) {
            uint32_t ah[4][4], al[4][4], bh[4][2], bl[4][2];
            #pragma unroll
            for (int i = 0; i < 4; i++) {
                int row = wm * 64 + i * 16 + lr + (lg & 1) * 8;
                int seg = 2 * s + (lg >> 1);
                uint32_t ad = sbase + (uint32_t)(row * 64 +
                              ((seg ^ ((row >> 1) & 3)) << 4));
                ldsm_x4(ah[i][0], ah[i][1], ah[i][2], ah[i][3], ad);
                ldsm_x4(al[i][0], al[i][1], al[i][2], al[i][3], ad + 8192);
            }
            #pragma unroll
            for (int p = 0; p < 2; p++) {
                int row = wn * 32 + p * 16 + lr + (lg >> 1) * 8;
                int seg = 2 * s + (lg & 1);
                uint32_t bd = sbase + 16384u + (uint32_t)(row * 64 +
                              ((seg ^ ((row >> 1) & 3)) << 4));
                uint32_t r0, r1, r2, r3;
                ldsm_x4(r0, r1, r2, r3, bd);
                bh[2*p][0] = r0; bh[2*p][1] = r1;
                bh[2*p+1][0] = r2; bh[2*p+1][1] = r3;
                ldsm_x4(r0, r1, r2, r3, bd + 8192);
                bl[2*p][0] = r0; bl[2*p][1] = r1;
                bl[2*p+1][0] = r2; bl[2*p+1][1] = r3;
            }
            // product-pass ordering: same-accumulator reuse distance = 16
            #pragma unroll
            for (int i = 0; i < 4; i++)
                #pragma unroll
                for (int j = 0; j < 4; j++)
                    mma16816(acc[i][j], ah[i], bh[j]);
            #pragma unroll
            for (int i = 0; i < 4; i++)
                #pragma unroll
                for (int j = 0; j < 4; j++)
                    mma16816(acc[i][j], ah[i], bl[j]);
            #pragma unroll
            for (int i = 0; i < 4; i++)
                #pragma unroll
                for (int j = 0; j < 4; j++)
                    mma16816(acc[i][j], al[i], bh[j]);
        }
    }

    const int mrow = m0 + wm * 64 + (lane >> 2);
    const int ncol = n0 + wn * 32 + (lane & 3) * 2;
    #pragma unroll
    for (int i = 0; i < 4; i++) {
        #pragma unroll
        for (int j = 0; j < 4; j++) {
            int m = mrow + i * 16;
            int n = ncol + j * 8;
            float b0 = __ldg(&bias[n]), b1 = __ldg(&bias[n + 1]);
            float2 v0 = {acc[i][j][0] + b0, acc[i][j][1] + b1};
            float2 v1 = {acc[i][j][2] + b0, acc[i][j][3] + b1};
            if (MODE == 0) {
                int sec = n >> 10;
                int e   = n & 1023;
                int h   = e >> 6;
                int d   = e & 63;
                float* q = (sec == 0) ? g_q : ((sec == 1) ? g_k : g_v);
                int b_ = m >> 11, s_ = m & 2047;
                *(float2*)(q + ((size_t)((b_ * HEADS + h) * SEQ) + s_) * HD + d) = v0;
                *(float2*)(q + ((size_t)((b_ * HEADS + h) * SEQ) + s_ + 8) * HD + d) = v1;
            } else {
                *(float2*)(out + (size_t)m * 1024 + n) = v0;
                *(float2*)(out + (size_t)(m + 8) * 1024 + n) = v1;
            }
        }
    }
}

// ---------------- HMMA flash attention --------------------------------------
#define ATT_SMEM (32768 + 2*32768)   // 98304

__global__ __launch_bounds__(256, 2)
void flash_attn_mma()
{
    extern __shared__ char smc[];
    const uint32_t sb = smem_u32(smc);
    const int tid  = threadIdx.x;
    const int wid  = tid >> 5;       // 0..7
    const int lane = tid & 31;
    const int lr = lane & 7;
    const int lg = lane >> 3;
    const int g  = lane >> 2;
    const int t2 = (lane & 3) * 2;

    const int qi = (int)gridDim.x - 1 - (int)blockIdx.x;
    const int qb = qi * 128;
    const int hh = blockIdx.y;
    const int bb = blockIdx.z;
    const size_t bhof = ((size_t)(bb * HEADS + hh)) * SEQ * HD;

    const __nv_bfloat16* qh_g = g_qh + bhof;
    const __nv_bfloat16* ql_g = g_ql + bhof;
    const __nv_bfloat16* kh_g = g_kh + bhof;
    const __nv_bfloat16* kl_g = g_kl + bhof;
    const __nv_bfloat16* vh_g = g_vh + bhof;
    const __nv_bfloat16* vl_g = g_vl + bhof;

    const uint32_t QH = sb, QL = sb + 16384;
    const uint32_t BUF0 = sb + 32768;

    #pragma unroll
    for (int u = tid; u < 1024; u += 256) {
        int row = u >> 3, seg = u & 7;
        uint32_t so = (uint32_t)(row * 128 + ((seg ^ (row & 7)) << 4));
        size_t go = (size_t)(qb + row) * 64 + seg * 8;
        CP_ASYNC16(QH + so, qh_g + go);
        CP_ASYNC16(QL + so, ql_g + go);
    }

    auto load_kv = [&](int kj) {
        uint32_t base = BUF0 + (uint32_t)(kj & 1) * 32768u;
        #pragma unroll
        for (int u = tid; u < 512; u += 256) {
            int row = u >> 3, seg = u & 7;
            uint32_t so = (uint32_t)(row * 128 + ((seg ^ (row & 7)) << 4));
            size_t go = (size_t)(kj * 64 + row) * 64 + seg * 8;
            CP_ASYNC16(base + so,          kh_g + go);
            CP_ASYNC16(base + 8192  + so,  kl_g + go);
            CP_ASYNC16(base + 16384 + so,  vh_g + go);
            CP_ASYNC16(base + 24576 + so,  vl_g + go);
        }
    };
    load_kv(0);
    CP_COMMIT();

    uint32_t qfh[4][4];
    float y[8][4];
    #pragma unroll
    for (int j = 0; j < 8; j++)
        #pragma unroll
        for (int r = 0; r < 4; r++) y[j][r] = 0.0f;
    float m0 = -1e30f, m1 = -1e30f, l0 = 0.0f, l1 = 0.0f;
    bool qloaded = false;

    const int nkj = 2 * qi + 2;
    const int wr0 = qb + wid * 16;

    for (int kj = 0; kj < nkj; kj++) {
        CP_WAIT0();
        __syncthreads();
        if (kj + 1 < nkj) { load_kv(kj + 1); CP_COMMIT(); }

        if (!qloaded) {
            qloaded = true;
            #pragma unroll
            for (int kc = 0; kc < 4; kc++) {
                int row = wid * 16 + lr + (lg & 1) * 8;
                int seg = 2 * kc + (lg >> 1);
                uint32_t so = (uint32_t)(row * 128 + ((seg ^ (row & 7)) << 4));
                ldsm_x4(qfh[kc][0], qfh[kc][1], qfh[kc][2], qfh[kc][3], QH + so);
            }
        }

        const int c0t = kj * 64;
        if (c0t > wr0 + 15) continue;

        uint32_t qfl[4][4];
        #pragma unroll
        for (int kc = 0; kc < 4; kc++) {
            int row = wid * 16 + lr + (lg & 1) * 8;
            int seg = 2 * kc + (lg >> 1);
            uint32_t so = (uint32_t)(row * 128 + ((seg ^ (row & 7)) << 4));
            ldsm_x4(qfl[kc][0], qfl[kc][1], qfl[kc][2], qfl[kc][3], QL + so);
        }

        const uint32_t B = BUF0 + (uint32_t)(kj & 1) * 32768u;

        // ---- S = Q K^T  (product-pass ordering, same-acc distance 8) ----
        float s[8][4];
        #pragma unroll
        for (int j = 0; j < 8; j++)
            #pragma unroll
            for (int r = 0; r < 4; r++) s[j][r] = 0.0f;

        #pragma unroll
        for (int kc = 0; kc < 4; kc++) {
            uint32_t kh[4][4], kl[4][4];
            #pragma unroll
            for (int p = 0; p < 4; p++) {
                int row = p * 16 + lr + (lg >> 1) * 8;
                int seg = 2 * kc + (lg & 1);
                uint32_t so = (uint32_t)(row * 128 + ((seg ^ (row & 7)) << 4));
                ldsm_x4(kh[p][0], kh[p][1], kh[p][2], kh[p][3], B + so);
                ldsm_x4(kl[p][0], kl[p][1], kl[p][2], kl[p][3], B + 8192 + so);
            }
            #pragma unroll
            for (int p = 0; p < 4; p++) {
                mma2(s[2*p],   qfh[kc], kh[p][0], kh[p][1]);
                mma2(s[2*p+1], qfh[kc], kh[p][2], kh[p][3]);
            }
            #pragma unroll
            for (int p = 0; p < 4; p++) {
                mma2(s[2*p],   qfh[kc], kl[p][0], kl[p][1]);
                mma2(s[2*p+1], qfh[kc], kl[p][2], kl[p][3]);
            }
            #pragma unroll
            for (int p = 0; p < 4; p++) {
                mma2(s[2*p],   qfl[kc], kh[p][0], kh[p][1]);
                mma2(s[2*p+1], qfl[kc], kh[p][2], kh[p][3]);
            }
        }

        // ---- causal mask ----
        if (c0t + 63 > wr0) {
            int R0 = wr0 + g, R1 = wr0 + g + 8;
            #pragma unroll
            for (int j = 0; j < 8; j++) {
                int cg = c0t + j * 8 + t2;
                if (cg     > R0) s[j][0] = -1e30f;
                if (cg + 1 > R0) s[j][1] = -1e30f;
                if (cg     > R1) s[j][2] = -1e30f;
                if (cg + 1 > R1) s[j][3] = -1e30f;
            }
        }

        // ---- online softmax ----
        float mx0 = -1e30f, mx1 = -1e30f;
        #pragma unroll
        for (int j = 0; j < 8; j++) {
            mx0 = fmaxf(mx0, fmaxf(s[j][0], s[j][1]));
            mx1 = fmaxf(mx1, fmaxf(s[j][2], s[j][3]));
        }
        mx0 = fmaxf(mx0, __shfl_xor_sync(0xffffffffu, mx0, 1));
        mx0 = fmaxf(mx0, __shfl_xor_sync(0xffffffffu, mx0, 2));
        mx1 = fmaxf(mx1, __shfl_xor_sync(0xffffffffu, mx1, 1));
        mx1 = fmaxf(mx1, __shfl_xor_sync(0xffffffffu, mx1, 2));
        float mn0 = fmaxf(m0, mx0), mn1 = fmaxf(m1, mx1);
        float a0 = __expf(m0 - mn0), a1 = __expf(m1 - mn1);
        m0 = mn0; m1 = mn1;

        float s0 = 0.0f, s1 = 0.0f;
        uint32_t ph[4][4], pl[4][4];
        #pragma unroll
        for (int j = 0; j < 8; j++) {
            float p00 = __expf(s[j][0] - mn0);
            float p01 = __expf(s[j][1] - mn0);
            float p10 = __expf(s[j][2] - mn1);
            float p11 = __expf(s[j][3] - mn1);
            s0 += p00 + p01;
            s1 += p10 + p11;
            __nv_bfloat16 b00 = __float2bfloat16_rn(p00);
            __nv_bfloat16 b01 = __float2bfloat16_rn(p01);
            __nv_bfloat16 b10 = __float2bfloat16_rn(p10);
            __nv_bfloat16 b11 = __float2bfloat16_rn(p11);
            uint32_t hA, hB, lA, lB;
            { __nv_bfloat162 v = {b00, b01}; hA = *(uint32_t*)&v; }
            { __nv_bfloat162 v = {b10, b11}; hB = *(uint32_t*)&v; }
            lA = pack_bf(p00 - __bfloat162float(b00), p01 - __bfloat162float(b01));
            lB = pack_bf(p10 - __bfloat162float(b10), p11 - __bfloat162float(b11));
            int kc = j >> 1;
            if ((j & 1) == 0) {
                ph[kc][0] = hA; ph[kc][1] = hB;
                pl[kc][0] = lA; pl[kc][1] = lB;
            } else {
                ph[kc][2] = hA; ph[kc][3] = hB;
                pl[kc][2] = lA; pl[kc][3] = lB;
            }
        }
        s0 += __shfl_xor_sync(0xffffffffu, s0, 1);
        s0 += __shfl_xor_sync(0xffffffffu, s0, 2);
        s1 += __shfl_xor_sync(0xffffffffu, s1, 1);
        s1 += __shfl_xor_sync(0xffffffffu, s1, 2);
        l0 = l0 * a0 + s0;
        l1 = l1 * a1 + s1;
        #pragma unroll
        for (int j = 0; j < 8; j++) {
            y[j][0] *= a0; y[j][1] *= a0;
            y[j][2] *= a1; y[j][3] *= a1;
        }

        // ---- Y += P V  (product-pass ordering, same-acc distance 8) ----
        #pragma unroll
        for (int kc = 0; kc < 4; kc++) {
            uint32_t vh[4][4], vl[4][4];
            #pragma unroll
            for (int dg = 0; dg < 4; dg++) {
                int row = kc * 16 + (lg & 1) * 8 + lr;
                int seg = 2 * dg + (lg >> 1);
                uint32_t so = (uint32_t)(row * 128 + ((seg ^ (row & 7)) << 4));
                ldsm_x4t(vh[dg][0], vh[dg][1], vh[dg][2], vh[dg][3], B + 16384 + so);
                ldsm_x4t(vl[dg][0], vl[dg][1], vl[dg][2], vl[dg][3], B + 24576 + so);
            }
            #pragma unroll
            for (int dg = 0; dg < 4; dg++) {
                mma2(y[2*dg],   ph[kc], vh[dg][0], vh[dg][1]);
                mma2(y[2*dg+1], ph[kc], vh[dg][2], vh[dg][3]);
            }
            #pragma unroll
            for (int dg = 0; dg < 4; dg++) {
                mma2(y[2*dg],   ph[kc], vl[dg][0], vl[dg][1]);
                mma2(y[2*dg+1], ph[kc], vl[dg][2], vl[dg][3]);
            }
            #pragma unroll
            for (int dg = 0; dg < 4; dg++) {
                mma2(y[2*dg],   pl[kc], vh[dg][0], vh[dg][1]);
                mma2(y[2*dg+1], pl[kc], vh[dg][2], vh[dg][3]);
            }
        }
    }

    // ---- epilogue ----
    const float i0 = 1.0f / l0, i1 = 1.0f / l1;
    const int r0 = wr0 + g;
    const int r1 = r0 + 8;
    const size_t rb0 = ((size_t)(bb * SEQ + r0)) * E_DIM + hh * HD;
    const size_t rb1 = ((size_t)(bb * SEQ + r1)) * E_DIM + hh * HD;
    #pragma unroll
    for (int j = 0; j < 8; j++) {
        int col = j * 8 + t2;
        float f0 = y[j][0] * i0, f1 = y[j][1] * i0;
        float f2 = y[j][2] * i1, f3 = y[j][3] * i1;
        __nv_bfloat162 h0 = __floats2bfloat162_rn(f0, f1);
        __nv_bfloat162 h1 = __floats2bfloat162_rn(f2, f3);
        __nv_bfloat162 l0p = __floats2bfloat162_rn(
            f0 - __bfloat162float(h0.x), f1 - __bfloat162float(h0.y));
        __nv_bfloat162 l1p = __floats2bfloat162_rn(
            f2 - __bfloat162float(h1.x), f3 - __bfloat162float(h1.y));
        *(__nv_bfloat162*)(g_yh + rb0 + col) = h0;
        *(__nv_bfloat162*)(g_yl + rb0 + col) = l0p;
        *(__nv_bfloat162*)(g_yh + rb1 + col) = h1;
        *(__nv_bfloat162*)(g_yl + rb1 + col) = l1p;
    }
}

// ---------------------------------------------------------------------------
extern "C" void kernel_launch(void* const* d_in, const int* in_sizes, int n_in,
                              void* d_out, int out_size)
{
    const float* x      = (const float*)d_in[0];
    const float* W_attn = (const float*)d_in[1];
    const float* b_attn = (const float*)d_in[2];
    const float* W_proj = (const float*)d_in[3];
    const float* b_proj = (const float*)d_in[4];
    float* out = (float*)d_out;

    cudaFuncSetAttribute(flash_attn_mma,
                         cudaFuncAttributeMaxDynamicSharedMemorySize, ATT_SMEM);
    cudaFuncSetAttribute(gemm_mma<3072, 0>,
                         cudaFuncAttributeMaxDynamicSharedMemorySize, GEMM_SMEM);
    cudaFuncSetAttribute(gemm_mma<1024, 1>,
                         cudaFuncAttributeMaxDynamicSharedMemorySize, GEMM_SMEM);

    __nv_bfloat16 *xh, *xl, *yh, *yl, *wah, *wal, *wph, *wpl;
    __nv_bfloat16 *qh, *ql, *kh, *kl, *vh, *vl;
    float *qf, *kf, *vf;
    cudaGetSymbolAddress((void**)&xh,  g_xh);
    cudaGetSymbolAddress((void**)&xl,  g_xl);
    cudaGetSymbolAddress((void**)&yh,  g_yh);
    cudaGetSymbolAddress((void**)&yl,  g_yl);
    cudaGetSymbolAddress((void**)&wah, g_wah);
    cudaGetSymbolAddress((void**)&wal, g_wal);
    cudaGetSymbolAddress((void**)&wph, g_wph);
    cudaGetSymbolAddress((void**)&wpl, g_wpl);
    cudaGetSymbolAddress((void**)&qh,  g_qh);
    cudaGetSymbolAddress((void**)&ql,  g_ql);
    cudaGetSymbolAddress((void**)&kh,  g_kh);
    cudaGetSymbolAddress((void**)&kl,  g_kl);
    cudaGetSymbolAddress((void**)&vh,  g_vh);
    cudaGetSymbolAddress((void**)&vl,  g_vl);
    cudaGetSymbolAddress((void**)&qf,  g_q);
    cudaGetSymbolAddress((void**)&kf,  g_k);
    cudaGetSymbolAddress((void**)&vf,  g_v);

    split_scale<<<BS * E_DIM / 1024, 256>>>(x, xh, xl, 1.0f);
    {
        dim3 g(3 * E_DIM / 32, E_DIM / 32);
        wsplit_t<<<g, 256>>>(W_attn, wah, wal, 3 * E_DIM);
    }
    {
        dim3 g(E_DIM / 32, E_DIM / 32);
        wsplit_t<<<g, 256>>>(W_proj, wph, wpl, E_DIM);
    }

    {
        dim3 grid(3 * E_DIM / 128, BS / 128);
        gemm_mma<3072, 0><<<grid, 256, GEMM_SMEM>>>(xh, xl, wah, wal, b_attn, nullptr);
    }

    const int QKV_N = BATCH * HEADS * SEQ * HD;
    split_scale<<<QKV_N / 1024, 256>>>(qf, qh, ql, 0.125f);
    split_scale<<<QKV_N / 1024, 256>>>(kf, kh, kl, 1.0f);
    split_scale<<<QKV_N / 1024, 256>>>(vf, vh, vl, 1.0f);

    {
        dim3 grid(SEQ / 128, HEADS, BATCH);
        flash_attn_mma<<<grid, 256, ATT_SMEM>>>();
    }

    {
        dim3 grid(E_DIM / 128, BS / 128);
        gemm_mma<1024, 1><<<grid, 256, GEMM_SMEM>>>(yh, yl, wph, wpl, b_proj, out);
    }
}

// round 7
// speedup vs baseline: 3.5537x; 1.0226x over previous
#include <cuda_runtime.h>
#include <cuda_bf16.h>
#include <cstdint>

#define E_DIM 1024
#define HEADS 16
#define HD 64
#define BATCH 4
#define SEQ 2048
#define BS (BATCH*SEQ)   // 8192

// q scale with log2(e) folded in: softmax done in exp2 domain
#define QSCALE 0.18033688011112042f   // 0.125 * log2(e)

// ---------------- scratch (device globals: allocation-guard safe) ----------
__device__ __align__(16) __nv_bfloat16 g_qh[BATCH*HEADS*SEQ*HD];
__device__ __align__(16) __nv_bfloat16 g_ql[BATCH*HEADS*SEQ*HD];
__device__ __align__(16) __nv_bfloat16 g_kh[BATCH*HEADS*SEQ*HD];
__device__ __align__(16) __nv_bfloat16 g_kl[BATCH*HEADS*SEQ*HD];
__device__ __align__(16) __nv_bfloat16 g_vh[BATCH*HEADS*SEQ*HD];
__device__ __align__(16) __nv_bfloat16 g_vl[BATCH*HEADS*SEQ*HD];

__device__ __align__(16) __nv_bfloat16 g_xh[BS*E_DIM];
__device__ __align__(16) __nv_bfloat16 g_xl[BS*E_DIM];
__device__ __align__(16) __nv_bfloat16 g_yh[BS*E_DIM];
__device__ __align__(16) __nv_bfloat16 g_yl[BS*E_DIM];
__device__ __align__(16) __nv_bfloat16 g_wah[3*E_DIM*E_DIM];
__device__ __align__(16) __nv_bfloat16 g_wal[3*E_DIM*E_DIM];
__device__ __align__(16) __nv_bfloat16 g_wph[E_DIM*E_DIM];
__device__ __align__(16) __nv_bfloat16 g_wpl[E_DIM*E_DIM];

// ---------------- PTX helpers (all valid at compute_103) --------------------
__device__ __forceinline__ uint32_t smem_u32(const void* p) {
    uint32_t a;
    asm("{ .reg .u64 t; cvta.to.shared.u64 t, %1; cvt.u32.u64 %0, t; }"
        : "=r"(a) : "l"(p));
    return a;
}
#define CP_ASYNC16(sa, ga) \
    asm volatile("cp.async.cg.shared.global [%0], [%1], 16;" :: "r"(sa), "l"(ga))
#define CP_COMMIT() asm volatile("cp.async.commit_group;" ::: "memory")
#define CP_WAIT0()  asm volatile("cp.async.wait_group 0;" ::: "memory")

__device__ __forceinline__ void ldsm_x4(uint32_t& r0, uint32_t& r1,
                                        uint32_t& r2, uint32_t& r3, uint32_t addr) {
    asm volatile("ldmatrix.sync.aligned.m8n8.x4.shared.b16 {%0,%1,%2,%3}, [%4];"
                 : "=r"(r0), "=r"(r1), "=r"(r2), "=r"(r3) : "r"(addr));
}
__device__ __forceinline__ void ldsm_x4t(uint32_t& r0, uint32_t& r1,
                                         uint32_t& r2, uint32_t& r3, uint32_t addr) {
    asm volatile("ldmatrix.sync.aligned.m8n8.x4.trans.shared.b16 {%0,%1,%2,%3}, [%4];"
                 : "=r"(r0), "=r"(r1), "=r"(r2), "=r"(r3) : "r"(addr));
}
__device__ __forceinline__ void mma16816(float* d, const uint32_t* a, const uint32_t* b) {
    asm volatile(
        "mma.sync.aligned.m16n8k16.row.col.f32.bf16.bf16.f32 "
        "{%0,%1,%2,%3}, {%4,%5,%6,%7}, {%8,%9}, {%0,%1,%2,%3};"
        : "+f"(d[0]), "+f"(d[1]), "+f"(d[2]), "+f"(d[3])
        : "r"(a[0]), "r"(a[1]), "r"(a[2]), "r"(a[3]), "r"(b[0]), "r"(b[1]));
}
__device__ __forceinline__ void mma2(float* d, const uint32_t* a, uint32_t b0, uint32_t b1) {
    asm volatile(
        "mma.sync.aligned.m16n8k16.row.col.f32.bf16.bf16.f32 "
        "{%0,%1,%2,%3}, {%4,%5,%6,%7}, {%8,%9}, {%0,%1,%2,%3};"
        : "+f"(d[0]), "+f"(d[1]), "+f"(d[2]), "+f"(d[3])
        : "r"(a[0]), "r"(a[1]), "r"(a[2]), "r"(a[3]), "r"(b0), "r"(b1));
}
__device__ __forceinline__ uint32_t pack_bf(float lo, float hi) {
    __nv_bfloat162 v = __floats2bfloat162_rn(lo, hi);
    return *reinterpret_cast<uint32_t*>(&v);
}

// ---------------- prep kernels ---------------------------------------------
__global__ __launch_bounds__(256)
void split_scale(const float* __restrict__ src,
                 __nv_bfloat16* __restrict__ hi, __nv_bfloat16* __restrict__ lo,
                 float sc)
{
    int i = (blockIdx.x * 256 + threadIdx.x) * 4;
    float4 v = *(const float4*)(src + i);
    v.x *= sc; v.y *= sc; v.z *= sc; v.w *= sc;
    __nv_bfloat16 h0 = __float2bfloat16(v.x), h1 = __float2bfloat16(v.y);
    __nv_bfloat16 h2 = __float2bfloat16(v.z), h3 = __float2bfloat16(v.w);
    __nv_bfloat162 H0 = {h0, h1}, H1 = {h2, h3};
    __nv_bfloat162 L0 = {__float2bfloat16(v.x - __bfloat162float(h0)),
                         __float2bfloat16(v.y - __bfloat162float(h1))};
    __nv_bfloat162 L1 = {__float2bfloat16(v.z - __bfloat162float(h2)),
                         __float2bfloat16(v.w - __bfloat162float(h3))};
    *(__nv_bfloat162*)(hi + i)     = H0;
    *(__nv_bfloat162*)(hi + i + 2) = H1;
    *(__nv_bfloat162*)(lo + i)     = L0;
    *(__nv_bfloat162*)(lo + i + 2) = L1;
}

// W [1024, N] row-major -> Wt hi/lo [N, 1024]
__global__ __launch_bounds__(256)
void wsplit_t(const float* __restrict__ W,
              __nv_bfloat16* __restrict__ Wh, __nv_bfloat16* __restrict__ Wl, int N)
{
    __shared__ float tile[32][33];
    int c0 = blockIdx.x * 32;
    int r0 = blockIdx.y * 32;
    int tx = threadIdx.x & 31, ty = threadIdx.x >> 5;
    #pragma unroll
    for (int i = ty; i < 32; i += 8)
        tile[i][tx] = W[(size_t)(r0 + i) * N + c0 + tx];
    __syncthreads();
    #pragma unroll
    for (int i = ty; i < 32; i += 8) {
        float v = tile[tx][i];
        __nv_bfloat16 h = __float2bfloat16(v);
        size_t o = (size_t)(c0 + i) * 1024 + r0 + tx;
        Wh[o] = h;
        Wl[o] = __float2bfloat16(v - __bfloat162float(h));
    }
}

// ---------------- HMMA GEMM -------------------------------------------------
// MODE 0: epilogue -> q/k/v bf16 hi/lo in [B,H,S,D] (q scaled by QSCALE)
// MODE 1: epilogue -> out fp32 [8192,1024]
// __launch_bounds__(256,2) pins regs <=128 so occupancy stays 2 CTA/SM.
#define GEMM_SMEM 65536

template<int NTOT, int MODE>
__global__ __launch_bounds__(256, 2)
void gemm_mma(const __nv_bfloat16* __restrict__ Ah, const __nv_bfloat16* __restrict__ Al,
              const __nv_bfloat16* __restrict__ Bh, const __nv_bfloat16* __restrict__ Bl,
              const float* __restrict__ bias, float* __restrict__ out)
{
    extern __shared__ char smem[];
    const uint32_t sb = smem_u32(smem);
    const int tid  = threadIdx.x;
    const int wid  = tid >> 5;
    const int lane = tid & 31;
    const int m0 = blockIdx.y * 128;
    const int n0 = blockIdx.x * 128;

    const int wm = wid & 1;
    const int wn = wid >> 1;
    const int lr = lane & 7;
    const int lg = lane >> 3;

    float acc[4][4][4];
    #pragma unroll
    for (int i = 0; i < 4; i++)
        #pragma unroll
        for (int j = 0; j < 4; j++)
            #pragma unroll
            for (int r = 0; r < 4; r++) acc[i][j][r] = 0.0f;

    auto load_chunk = [&](int c) {
        const int k0 = c * 32;
        const uint32_t sbase = sb + (uint32_t)(c & 1) * 32768u;
        #pragma unroll
        for (int t = 0; t < 2; t++) {
            int u = tid + t * 256;
            int r = u >> 2, seg = u & 3;
            uint32_t soff = (uint32_t)(r * 64 + ((seg ^ ((r >> 1) & 3)) << 4));
            size_t ga = (size_t)(m0 + r) * 1024 + k0 + seg * 8;
            size_t gb = (size_t)(n0 + r) * 1024 + k0 + seg * 8;
            CP_ASYNC16(sbase + soff,          Ah + ga);
            CP_ASYNC16(sbase + 8192  + soff,  Al + ga);
            CP_ASYNC16(sbase + 16384 + soff,  Bh + gb);
            CP_ASYNC16(sbase + 24576 + soff,  Bl + gb);
        }
        CP_COMMIT();
    };

    load_chunk(0);

    for (int c = 0; c < 32; c++) {
        CP_WAIT0();
        __syncthreads();
        if (c + 1 < 32) load_chunk(c + 1);

        const uint32_t sbase = sb + (uint32_t)(c & 1) * 32768u;
        #pragma unroll
        for (int s = 0; s < 2; s++) {
            uint32_t ah[4][4], al[4][4], bh[4][2], bl[4][2];
            #pragma unroll
            for (int i = 0; i < 4; i++) {
                int row = wm * 64 + i * 16 + lr + (lg & 1) * 8;
                int seg = 2 * s + (lg >> 1);
                uint32_t ad = sbase + (uint32_t)(row * 64 +
                              ((seg ^ ((row >> 1) & 3)) << 4));
                ldsm_x4(ah[i][0], ah[i][1], ah[i][2], ah[i][3], ad);
                ldsm_x4(al[i][0], al[i][1], al[i][2], al[i][3], ad + 8192);
            }
            #pragma unroll
            for (int p = 0; p < 2; p++) {
                int row = wn * 32 + p * 16 + lr + (lg >> 1) * 8;
                int seg = 2 * s + (lg & 1);
                uint32_t bd = sbase + 16384u + (uint32_t)(row * 64 +
                              ((seg ^ ((row >> 1) & 3)) << 4));
                uint32_t r0, r1, r2, r3;
                ldsm_x4(r0, r1, r2, r3, bd);
                bh[2*p][0] = r0; bh[2*p][1] = r1;
                bh[2*p+1][0] = r2; bh[2*p+1][1] = r3;
                ldsm_x4(r0, r1, r2, r3, bd + 8192);
                bl[2*p][0] = r0; bl[2*p][1] = r1;
                bl[2*p+1][0] = r2; bl[2*p+1][1] = r3;
            }
            #pragma unroll
            for (int i = 0; i < 4; i++)
                #pragma unroll
                for (int j = 0; j < 4; j++)
                    mma16816(acc[i][j], ah[i], bh[j]);
            #pragma unroll
            for (int i = 0; i < 4; i++)
                #pragma unroll
                for (int j = 0; j < 4; j++)
                    mma16816(acc[i][j], ah[i], bl[j]);
            #pragma unroll
            for (int i = 0; i < 4; i++)
                #pragma unroll
                for (int j = 0; j < 4; j++)
                    mma16816(acc[i][j], al[i], bh[j]);
        }
    }

    const int mrow = m0 + wm * 64 + (lane >> 2);
    const int ncol = n0 + wn * 32 + (lane & 3) * 2;
    #pragma unroll
    for (int i = 0; i < 4; i++) {
        #pragma unroll
        for (int j = 0; j < 4; j++) {
            int m = mrow + i * 16;
            int n = ncol + j * 8;
            float b0 = __ldg(&bias[n]), b1 = __ldg(&bias[n + 1]);
            float f0 = acc[i][j][0] + b0, f1 = acc[i][j][1] + b1;
            float f2 = acc[i][j][2] + b0, f3 = acc[i][j][3] + b1;
            if (MODE == 0) {
                int sec = n >> 10;
                int e   = n & 1023;
                int hh  = e >> 6;
                int d   = e & 63;
                __nv_bfloat16 *dh, *dl;
                float sc;
                if (sec == 0)      { dh = g_qh; dl = g_ql; sc = QSCALE; }
                else if (sec == 1) { dh = g_kh; dl = g_kl; sc = 1.0f; }
                else               { dh = g_vh; dl = g_vl; sc = 1.0f; }
                f0 *= sc; f1 *= sc; f2 *= sc; f3 *= sc;
                int b_ = m >> 11, s_ = m & 2047;
                size_t o0 = ((size_t)((b_ * HEADS + hh) * SEQ) + s_) * HD + d;
                size_t o1 = o0 + 8 * HD;
                __nv_bfloat162 h0 = __floats2bfloat162_rn(f0, f1);
                __nv_bfloat162 h1 = __floats2bfloat162_rn(f2, f3);
                __nv_bfloat162 l0 = __floats2bfloat162_rn(
                    f0 - __bfloat162float(h0.x), f1 - __bfloat162float(h0.y));
                __nv_bfloat162 l1 = __floats2bfloat162_rn(
                    f2 - __bfloat162float(h1.x), f3 - __bfloat162float(h1.y));
                *(__nv_bfloat162*)(dh + o0) = h0;
                *(__nv_bfloat162*)(dl + o0) = l0;
                *(__nv_bfloat162*)(dh + o1) = h1;
                *(__nv_bfloat162*)(dl + o1) = l1;
            } else {
                *(float2*)(out + (size_t)m * 1024 + n) = {f0, f1};
                *(float2*)(out + (size_t)(m + 8) * 1024 + n) = {f2, f3};
            }
        }
    }
}

// ---------------- HMMA flash attention --------------------------------------
#define ATT_SMEM (32768 + 2*32768)   // 98304

__global__ __launch_bounds__(256, 2)
void flash_attn_mma()
{
    extern __shared__ char smc[];
    const uint32_t sb = smem_u32(smc);
    const int tid  = threadIdx.x;
    const int wid  = tid >> 5;       // 0..7
    const int lane = tid & 31;
    const int lr = lane & 7;
    const int lg = lane >> 3;
    const int g  = lane >> 2;
    const int t2 = (lane & 3) * 2;

    const int qi = (int)gridDim.x - 1 - (int)blockIdx.x;
    const int qb = qi * 128;
    const int hh = blockIdx.y;
    const int bb = blockIdx.z;
    const size_t bhof = ((size_t)(bb * HEADS + hh)) * SEQ * HD;

    const __nv_bfloat16* qh_g = g_qh + bhof;
    const __nv_bfloat16* ql_g = g_ql + bhof;
    const __nv_bfloat16* kh_g = g_kh + bhof;
    const __nv_bfloat16* kl_g = g_kl + bhof;
    const __nv_bfloat16* vh_g = g_vh + bhof;
    const __nv_bfloat16* vl_g = g_vl + bhof;

    const uint32_t QH = sb, QL = sb + 16384;
    const uint32_t BUF0 = sb + 32768;

    #pragma unroll
    for (int u = tid; u < 1024; u += 256) {
        int row = u >> 3, seg = u & 7;
        uint32_t so = (uint32_t)(row * 128 + ((seg ^ (row & 7)) << 4));
        size_t go = (size_t)(qb + row) * 64 + seg * 8;
        CP_ASYNC16(QH + so, qh_g + go);
        CP_ASYNC16(QL + so, ql_g + go);
    }

    auto load_kv = [&](int kj) {
        uint32_t base = BUF0 + (uint32_t)(kj & 1) * 32768u;
        #pragma unroll
        for (int u = tid; u < 512; u += 256) {
            int row = u >> 3, seg = u & 7;
            uint32_t so = (uint32_t)(row * 128 + ((seg ^ (row & 7)) << 4));
            size_t go = (size_t)(kj * 64 + row) * 64 + seg * 8;
            CP_ASYNC16(base + so,          kh_g + go);
            CP_ASYNC16(base + 8192  + so,  kl_g + go);
            CP_ASYNC16(base + 16384 + so,  vh_g + go);
            CP_ASYNC16(base + 24576 + so,  vl_g + go);
        }
    };
    load_kv(0);
    CP_COMMIT();

    uint32_t qfh[4][4];
    float y[8][4];
    #pragma unroll
    for (int j = 0; j < 8; j++)
        #pragma unroll
        for (int r = 0; r < 4; r++) y[j][r] = 0.0f;
    float m0 = -1e30f, m1 = -1e30f, l0 = 0.0f, l1 = 0.0f;
    bool qloaded = false;

    const int nkj = 2 * qi + 2;
    const int wr0 = qb + wid * 16;

    for (int kj = 0; kj < nkj; kj++) {
        CP_WAIT0();
        __syncthreads();
        if (kj + 1 < nkj) { load_kv(kj + 1); CP_COMMIT(); }

        if (!qloaded) {
            qloaded = true;
            #pragma unroll
            for (int kc = 0; kc < 4; kc++) {
                int row = wid * 16 + lr + (lg & 1) * 8;
                int seg = 2 * kc + (lg >> 1);
                uint32_t so = (uint32_t)(row * 128 + ((seg ^ (row & 7)) << 4));
                ldsm_x4(qfh[kc][0], qfh[kc][1], qfh[kc][2], qfh[kc][3], QH + so);
            }
        }

        const int c0t = kj * 64;
        if (c0t > wr0 + 15) continue;

        uint32_t qfl[4][4];
        #pragma unroll
        for (int kc = 0; kc < 4; kc++) {
            int row = wid * 16 + lr + (lg & 1) * 8;
            int seg = 2 * kc + (lg >> 1);
            uint32_t so = (uint32_t)(row * 128 + ((seg ^ (row & 7)) << 4));
            ldsm_x4(qfl[kc][0], qfl[kc][1], qfl[kc][2], qfl[kc][3], QL + so);
        }

        const uint32_t B = BUF0 + (uint32_t)(kj & 1) * 32768u;

        // ---- S = Q K^T (scores in log2 domain; QSCALE includes log2e) ----
        float s[8][4];
        #pragma unroll
        for (int j = 0; j < 8; j++)
            #pragma unroll
            for (int r = 0; r < 4; r++) s[j][r] = 0.0f;

        #pragma unroll
        for (int kc = 0; kc < 4; kc++) {
            uint32_t kh[4][4], kl[4][4];
            #pragma unroll
            for (int p = 0; p < 4; p++) {
                int row = p * 16 + lr + (lg >> 1) * 8;
                int seg = 2 * kc + (lg & 1);
                uint32_t so = (uint32_t)(row * 128 + ((seg ^ (row & 7)) << 4));
                ldsm_x4(kh[p][0], kh[p][1], kh[p][2], kh[p][3], B + so);
                ldsm_x4(kl[p][0], kl[p][1], kl[p][2], kl[p][3], B + 8192 + so);
            }
            #pragma unroll
            for (int p = 0; p < 4; p++) {
                mma2(s[2*p],   qfh[kc], kh[p][0], kh[p][1]);
                mma2(s[2*p+1], qfh[kc], kh[p][2], kh[p][3]);
            }
            #pragma unroll
            for (int p = 0; p < 4; p++) {
                mma2(s[2*p],   qfh[kc], kl[p][0], kl[p][1]);
                mma2(s[2*p+1], qfh[kc], kl[p][2], kl[p][3]);
            }
            #pragma unroll
            for (int p = 0; p < 4; p++) {
                mma2(s[2*p],   qfl[kc], kh[p][0], kh[p][1]);
                mma2(s[2*p+1], qfl[kc], kh[p][2], kh[p][3]);
            }
        }

        // ---- causal mask ----
        if (c0t + 63 > wr0) {
            int R0 = wr0 + g, R1 = wr0 + g + 8;
            #pragma unroll
            for (int j = 0; j < 8; j++) {
                int cg = c0t + j * 8 + t2;
                if (cg     > R0) s[j][0] = -1e30f;
                if (cg + 1 > R0) s[j][1] = -1e30f;
                if (cg     > R1) s[j][2] = -1e30f;
                if (cg + 1 > R1) s[j][3] = -1e30f;
            }
        }

        // ---- online softmax (exp2 domain) ----
        float mx0 = -1e30f, mx1 = -1e30f;
        #pragma unroll
        for (int j = 0; j < 8; j++) {
            mx0 = fmaxf(mx0, fmaxf(s[j][0], s[j][1]));
            mx1 = fmaxf(mx1, fmaxf(s[j][2], s[j][3]));
        }
        mx0 = fmaxf(mx0, __shfl_xor_sync(0xffffffffu, mx0, 1));
        mx0 = fmaxf(mx0, __shfl_xor_sync(0xffffffffu, mx0, 2));
        mx1 = fmaxf(mx1, __shfl_xor_sync(0xffffffffu, mx1, 1));
        mx1 = fmaxf(mx1, __shfl_xor_sync(0xffffffffu, mx1, 2));
        float mn0 = fmaxf(m0, mx0), mn1 = fmaxf(m1, mx1);
        float a0 = exp2f(m0 - mn0), a1 = exp2f(m1 - mn1);
        m0 = mn0; m1 = mn1;

        float s0 = 0.0f, s1 = 0.0f;
        uint32_t ph[4][4], pl[4][4];
        #pragma unroll
        for (int j = 0; j < 8; j++) {
            float p00 = exp2f(s[j][0] - mn0);
            float p01 = exp2f(s[j][1] - mn0);
            float p10 = exp2f(s[j][2] - mn1);
            float p11 = exp2f(s[j][3] - mn1);
            s0 += p00 + p01;
            s1 += p10 + p11;
            __nv_bfloat16 b00 = __float2bfloat16_rn(p00);
            __nv_bfloat16 b01 = __float2bfloat16_rn(p01);
            __nv_bfloat16 b10 = __float2bfloat16_rn(p10);
            __nv_bfloat16 b11 = __float2bfloat16_rn(p11);
            uint32_t hA, hB, lA, lB;
            { __nv_bfloat162 v = {b00, b01}; hA = *(uint32_t*)&v; }
            { __nv_bfloat162 v = {b10, b11}; hB = *(uint32_t*)&v; }
            lA = pack_bf(p00 - __bfloat162float(b00), p01 - __bfloat162float(b01));
            lB = pack_bf(p10 - __bfloat162float(b10), p11 - __bfloat162float(b11));
            int kc = j >> 1;
            if ((j & 1) == 0) {
                ph[kc][0] = hA; ph[kc][1] = hB;
                pl[kc][0] = lA; pl[kc][1] = lB;
            } else {
                ph[kc][2] = hA; ph[kc][3] = hB;
                pl[kc][2] = lA; pl[kc][3] = lB;
            }
        }
        s0 += __shfl_xor_sync(0xffffffffu, s0, 1);
        s0 += __shfl_xor_sync(0xffffffffu, s0, 2);
        s1 += __shfl_xor_sync(0xffffffffu, s1, 1);
        s1 += __shfl_xor_sync(0xffffffffu, s1, 2);
        l0 = l0 * a0 + s0;
        l1 = l1 * a1 + s1;
        #pragma unroll
        for (int j = 0; j < 8; j++) {
            y[j][0] *= a0; y[j][1] *= a0;
            y[j][2] *= a1; y[j][3] *= a1;
        }

        // ---- Y += P V ----
        #pragma unroll
        for (int kc = 0; kc < 4; kc++) {
            uint32_t vh[4][4], vl[4][4];
            #pragma unroll
            for (int dg = 0; dg < 4; dg++) {
                int row = kc * 16 + (lg & 1) * 8 + lr;
                int seg = 2 * dg + (lg >> 1);
                uint32_t so = (uint32_t)(row * 128 + ((seg ^ (row & 7)) << 4));
                ldsm_x4t(vh[dg][0], vh[dg][1], vh[dg][2], vh[dg][3], B + 16384 + so);
                ldsm_x4t(vl[dg][0], vl[dg][1], vl[dg][2], vl[dg][3], B + 24576 + so);
            }
            #pragma unroll
            for (int dg = 0; dg < 4; dg++) {
                mma2(y[2*dg],   ph[kc], vh[dg][0], vh[dg][1]);
                mma2(y[2*dg+1], ph[kc], vh[dg][2], vh[dg][3]);
            }
            #pragma unroll
            for (int dg = 0; dg < 4; dg++) {
                mma2(y[2*dg],   ph[kc], vl[dg][0], vl[dg][1]);
                mma2(y[2*dg+1], ph[kc], vl[dg][2], vl[dg][3]);
            }
            #pragma unroll
            for (int dg = 0; dg < 4; dg++) {
                mma2(y[2*dg],   pl[kc], vh[dg][0], vh[dg][1]);
                mma2(y[2*dg+1], pl[kc], vh[dg][2], vh[dg][3]);
            }
        }
    }

    // ---- epilogue ----
    const float i0 = 1.0f / l0, i1 = 1.0f / l1;
    const int r0 = wr0 + g;
    const int r1 = r0 + 8;
    const size_t rb0 = ((size_t)(bb * SEQ + r0)) * E_DIM + hh * HD;
    const size_t rb1 = ((size_t)(bb * SEQ + r1)) * E_DIM + hh * HD;
    #pragma unroll
    for (int j = 0; j < 8; j++) {
        int col = j * 8 + t2;
        float f0 = y[j][0] * i0, f1 = y[j][1] * i0;
        float f2 = y[j][2] * i1, f3 = y[j][3] * i1;
        __nv_bfloat162 h0 = __floats2bfloat162_rn(f0, f1);
        __nv_bfloat162 h1 = __floats2bfloat162_rn(f2, f3);
        __nv_bfloat162 l0p = __floats2bfloat162_rn(
            f0 - __bfloat162float(h0.x), f1 - __bfloat162float(h0.y));
        __nv_bfloat162 l1p = __floats2bfloat162_rn(
            f2 - __bfloat162float(h1.x), f3 - __bfloat162float(h1.y));
        *(__nv_bfloat162*)(g_yh + rb0 + col) = h0;
        *(__nv_bfloat162*)(g_yl + rb0 + col) = l0p;
        *(__nv_bfloat162*)(g_yh + rb1 + col) = h1;
        *(__nv_bfloat162*)(g_yl + rb1 + col) = l1p;
    }
}

// ---------------------------------------------------------------------------
extern "C" void kernel_launch(void* const* d_in, const int* in_sizes, int n_in,
                              void* d_out, int out_size)
{
    const float* x      = (const float*)d_in[0];
    const float* W_attn = (const float*)d_in[1];
    const float* b_attn = (const float*)d_in[2];
    const float* W_proj = (const float*)d_in[3];
    const float* b_proj = (const float*)d_in[4];
    float* out = (float*)d_out;

    cudaFuncSetAttribute(flash_attn_mma,
                         cudaFuncAttributeMaxDynamicSharedMemorySize, ATT_SMEM);
    cudaFuncSetAttribute(gemm_mma<3072, 0>,
                         cudaFuncAttributeMaxDynamicSharedMemorySize, GEMM_SMEM);
    cudaFuncSetAttribute(gemm_mma<1024, 1>,
                         cudaFuncAttributeMaxDynamicSharedMemorySize, GEMM_SMEM);

    __nv_bfloat16 *xh, *xl, *yh, *yl, *wah, *wal, *wph, *wpl;
    cudaGetSymbolAddress((void**)&xh,  g_xh);
    cudaGetSymbolAddress((void**)&xl,  g_xl);
    cudaGetSymbolAddress((void**)&yh,  g_yh);
    cudaGetSymbolAddress((void**)&yl,  g_yl);
    cudaGetSymbolAddress((void**)&wah, g_wah);
    cudaGetSymbolAddress((void**)&wal, g_wal);
    cudaGetSymbolAddress((void**)&wph, g_wph);
    cudaGetSymbolAddress((void**)&wpl, g_wpl);

    split_scale<<<BS * E_DIM / 1024, 256>>>(x, xh, xl, 1.0f);
    {
        dim3 g(3 * E_DIM / 32, E_DIM / 32);
        wsplit_t<<<g, 256>>>(W_attn, wah, wal, 3 * E_DIM);
    }
    {
        dim3 g(E_DIM / 32, E_DIM / 32);
        wsplit_t<<<g, 256>>>(W_proj, wph, wpl, E_DIM);
    }

    // 1) QKV GEMM -> q/k/v bf16 hi/lo directly (q scaled by QSCALE)
    {
        dim3 grid(3 * E_DIM / 128, BS / 128);
        gemm_mma<3072, 0><<<grid, 256, GEMM_SMEM>>>(xh, xl, wah, wal, b_attn, nullptr);
    }

    // 2) causal flash attention (HMMA, exp2 softmax) -> yh/yl
    {
        dim3 grid(SEQ / 128, HEADS, BATCH);
        flash_attn_mma<<<grid, 256, ATT_SMEM>>>();
    }

    // 3) proj GEMM -> out
    {
        dim3 grid(E_DIM / 128, BS / 128);
        gemm_mma<1024, 1><<<grid, 256, GEMM_SMEM>>>(yh, yl, wph, wpl, b_proj, out);
    }
}

// round 8
// speedup vs baseline: 4.9243x; 1.3857x over previous
#include <cuda_runtime.h>
#include <cuda_fp16.h>
#include <cstdint>

#define E_DIM 1024
#define HEADS 16
#define HD 64
#define BATCH 4
#define SEQ 2048
#define BS (BATCH*SEQ)   // 8192

// q scale with log2(e) folded in: softmax done in exp2 domain
#define QSCALE 0.18033688011112042f   // 0.125 * log2(e)

// ---------------- scratch (device globals: allocation-guard safe) ----------
__device__ __align__(16) __half g_qh[BATCH*HEADS*SEQ*HD];
__device__ __align__(16) __half g_ql[BATCH*HEADS*SEQ*HD];
__device__ __align__(16) __half g_kh[BATCH*HEADS*SEQ*HD];
__device__ __align__(16) __half g_vh[BATCH*HEADS*SEQ*HD];

__device__ __align__(16) __half g_xh[BS*E_DIM];
__device__ __align__(16) __half g_xl[BS*E_DIM];
__device__ __align__(16) __half g_yh[BS*E_DIM];
__device__ __align__(16) __half g_yl[BS*E_DIM];
__device__ __align__(16) __half g_wah[3*E_DIM*E_DIM];   // W_attn^T fp16 [3072,1024]
__device__ __align__(16) __half g_wph[E_DIM*E_DIM];     // W_proj^T fp16 [1024,1024]

// ---------------- PTX helpers (all valid at compute_103) --------------------
__device__ __forceinline__ uint32_t smem_u32(const void* p) {
    uint32_t a;
    asm("{ .reg .u64 t; cvta.to.shared.u64 t, %1; cvt.u32.u64 %0, t; }"
        : "=r"(a) : "l"(p));
    return a;
}
#define CP_ASYNC16(sa, ga) \
    asm volatile("cp.async.cg.shared.global [%0], [%1], 16;" :: "r"(sa), "l"(ga))
#define CP_COMMIT() asm volatile("cp.async.commit_group;" ::: "memory")
#define CP_WAIT0()  asm volatile("cp.async.wait_group 0;" ::: "memory")

__device__ __forceinline__ void ldsm_x4(uint32_t& r0, uint32_t& r1,
                                        uint32_t& r2, uint32_t& r3, uint32_t addr) {
    asm volatile("ldmatrix.sync.aligned.m8n8.x4.shared.b16 {%0,%1,%2,%3}, [%4];"
                 : "=r"(r0), "=r"(r1), "=r"(r2), "=r"(r3) : "r"(addr));
}
__device__ __forceinline__ void ldsm_x4t(uint32_t& r0, uint32_t& r1,
                                         uint32_t& r2, uint32_t& r3, uint32_t addr) {
    asm volatile("ldmatrix.sync.aligned.m8n8.x4.trans.shared.b16 {%0,%1,%2,%3}, [%4];"
                 : "=r"(r0), "=r"(r1), "=r"(r2), "=r"(r3) : "r"(addr));
}
__device__ __forceinline__ void mma16816(float* d, const uint32_t* a, const uint32_t* b) {
    asm volatile(
        "mma.sync.aligned.m16n8k16.row.col.f32.f16.f16.f32 "
        "{%0,%1,%2,%3}, {%4,%5,%6,%7}, {%8,%9}, {%0,%1,%2,%3};"
        : "+f"(d[0]), "+f"(d[1]), "+f"(d[2]), "+f"(d[3])
        : "r"(a[0]), "r"(a[1]), "r"(a[2]), "r"(a[3]), "r"(b[0]), "r"(b[1]));
}
__device__ __forceinline__ void mma2(float* d, const uint32_t* a, uint32_t b0, uint32_t b1) {
    asm volatile(
        "mma.sync.aligned.m16n8k16.row.col.f32.f16.f16.f32 "
        "{%0,%1,%2,%3}, {%4,%5,%6,%7}, {%8,%9}, {%0,%1,%2,%3};"
        : "+f"(d[0]), "+f"(d[1]), "+f"(d[2]), "+f"(d[3])
        : "r"(a[0]), "r"(a[1]), "r"(a[2]), "r"(a[3]), "r"(b0), "r"(b1));
}
__device__ __forceinline__ uint32_t pack_h2(float a, float b) {
    __half2 v = __floats2half2_rn(a, b);
    return *reinterpret_cast<uint32_t*>(&v);
}

// ---------------- prep kernels ---------------------------------------------
__global__ __launch_bounds__(256)
void split_scale(const float* __restrict__ src,
                 __half* __restrict__ hi, __half* __restrict__ lo, float sc)
{
    int i = (blockIdx.x * 256 + threadIdx.x) * 4;
    float4 v = *(const float4*)(src + i);
    v.x *= sc; v.y *= sc; v.z *= sc; v.w *= sc;
    __half h0 = __float2half_rn(v.x), h1 = __float2half_rn(v.y);
    __half h2 = __float2half_rn(v.z), h3 = __float2half_rn(v.w);
    __half2 H0 = {h0, h1}, H1 = {h2, h3};
    __half2 L0 = __floats2half2_rn(v.x - __half2float(h0), v.y - __half2float(h1));
    __half2 L1 = __floats2half2_rn(v.z - __half2float(h2), v.w - __half2float(h3));
    *(__half2*)(hi + i)     = H0;
    *(__half2*)(hi + i + 2) = H1;
    *(__half2*)(lo + i)     = L0;
    *(__half2*)(lo + i + 2) = L1;
}

// W [1024, N] row-major -> Wt fp16 [N, 1024]
__global__ __launch_bounds__(256)
void wcast_t(const float* __restrict__ W, __half* __restrict__ Wh, int N)
{
    __shared__ float tile[32][33];
    int c0 = blockIdx.x * 32;
    int r0 = blockIdx.y * 32;
    int tx = threadIdx.x & 31, ty = threadIdx.x >> 5;
    #pragma unroll
    for (int i = ty; i < 32; i += 8)
        tile[i][tx] = W[(size_t)(r0 + i) * N + c0 + tx];
    __syncthreads();
    #pragma unroll
    for (int i = ty; i < 32; i += 8)
        Wh[(size_t)(c0 + i) * 1024 + r0 + tx] = __float2half_rn(tile[tx][i]);
}

// ---------------- HMMA GEMM (fp16 2-product: Ah*Bh + Al*Bh) -----------------
// MODE 0: epilogue -> q fp16 hi/lo (scaled QSCALE), k/v fp16 single, [B,H,S,D]
// MODE 1: epilogue -> out fp32 [8192,1024]
#define BUFB 24576u
#define GEMM_SMEM (2*24576)   // 49152

template<int NTOT, int MODE>
__global__ __launch_bounds__(256, 2)
void gemm_mma(const __half* __restrict__ Ah, const __half* __restrict__ Al,
              const __half* __restrict__ Bh,
              const float* __restrict__ bias, float* __restrict__ out)
{
    extern __shared__ char smem[];
    const uint32_t sb = smem_u32(smem);
    const int tid  = threadIdx.x;
    const int wid  = tid >> 5;
    const int lane = tid & 31;
    const int m0 = blockIdx.y * 128;
    const int n0 = blockIdx.x * 128;

    const int wm = wid & 1;
    const int wn = wid >> 1;
    const int lr = lane & 7;
    const int lg = lane >> 3;

    float acc[4][4][4];
    #pragma unroll
    for (int i = 0; i < 4; i++)
        #pragma unroll
        for (int j = 0; j < 4; j++)
            #pragma unroll
            for (int r = 0; r < 4; r++) acc[i][j][r] = 0.0f;

    auto load_chunk = [&](int c) {
        const int k0 = c * 32;
        const uint32_t sbase = sb + (uint32_t)(c & 1) * BUFB;
        #pragma unroll
        for (int t = 0; t < 2; t++) {
            int u = tid + t * 256;
            int r = u >> 2, seg = u & 3;
            uint32_t soff = (uint32_t)(r * 64 + ((seg ^ ((r >> 1) & 3)) << 4));
            size_t ga = (size_t)(m0 + r) * 1024 + k0 + seg * 8;
            size_t gb = (size_t)(n0 + r) * 1024 + k0 + seg * 8;
            CP_ASYNC16(sbase + soff,          Ah + ga);
            CP_ASYNC16(sbase + 8192  + soff,  Al + ga);
            CP_ASYNC16(sbase + 16384 + soff,  Bh + gb);
        }
        CP_COMMIT();
    };

    load_chunk(0);

    for (int c = 0; c < 32; c++) {
        CP_WAIT0();
        __syncthreads();
        if (c + 1 < 32) load_chunk(c + 1);

        const uint32_t sbase = sb + (uint32_t)(c & 1) * BUFB;
        #pragma unroll
        for (int s = 0; s < 2; s++) {
            uint32_t ah[4][4], al[4][4], bh[4][2];
            #pragma unroll
            for (int i = 0; i < 4; i++) {
                int row = wm * 64 + i * 16 + lr + (lg & 1) * 8;
                int seg = 2 * s + (lg >> 1);
                uint32_t ad = sbase + (uint32_t)(row * 64 +
                              ((seg ^ ((row >> 1) & 3)) << 4));
                ldsm_x4(ah[i][0], ah[i][1], ah[i][2], ah[i][3], ad);
                ldsm_x4(al[i][0], al[i][1], al[i][2], al[i][3], ad + 8192);
            }
            #pragma unroll
            for (int p = 0; p < 2; p++) {
                int row = wn * 32 + p * 16 + lr + (lg >> 1) * 8;
                int seg = 2 * s + (lg & 1);
                uint32_t bd = sbase + 16384u + (uint32_t)(row * 64 +
                              ((seg ^ ((row >> 1) & 3)) << 4));
                uint32_t r0, r1, r2, r3;
                ldsm_x4(r0, r1, r2, r3, bd);
                bh[2*p][0] = r0; bh[2*p][1] = r1;
                bh[2*p+1][0] = r2; bh[2*p+1][1] = r3;
            }
            #pragma unroll
            for (int i = 0; i < 4; i++)
                #pragma unroll
                for (int j = 0; j < 4; j++)
                    mma16816(acc[i][j], ah[i], bh[j]);
            #pragma unroll
            for (int i = 0; i < 4; i++)
                #pragma unroll
                for (int j = 0; j < 4; j++)
                    mma16816(acc[i][j], al[i], bh[j]);
        }
    }

    const int mrow = m0 + wm * 64 + (lane >> 2);
    const int ncol = n0 + wn * 32 + (lane & 3) * 2;
    #pragma unroll
    for (int i = 0; i < 4; i++) {
        #pragma unroll
        for (int j = 0; j < 4; j++) {
            int m = mrow + i * 16;
            int n = ncol + j * 8;
            float b0 = __ldg(&bias[n]), b1 = __ldg(&bias[n + 1]);
            float f0 = acc[i][j][0] + b0, f1 = acc[i][j][1] + b1;
            float f2 = acc[i][j][2] + b0, f3 = acc[i][j][3] + b1;
            if (MODE == 0) {
                int sec = n >> 10;
                int e   = n & 1023;
                int hh  = e >> 6;
                int d   = e & 63;
                int b_ = m >> 11, s_ = m & 2047;
                size_t o0 = ((size_t)((b_ * HEADS + hh) * SEQ) + s_) * HD + d;
                size_t o1 = o0 + 8 * HD;
                if (sec == 0) {
                    f0 *= QSCALE; f1 *= QSCALE; f2 *= QSCALE; f3 *= QSCALE;
                    __half2 h0 = __floats2half2_rn(f0, f1);
                    __half2 h1 = __floats2half2_rn(f2, f3);
                    __half2 l0 = __floats2half2_rn(
                        f0 - __half2float(h0.x), f1 - __half2float(h0.y));
                    __half2 l1 = __floats2half2_rn(
                        f2 - __half2float(h1.x), f3 - __half2float(h1.y));
                    *(__half2*)(g_qh + o0) = h0;
                    *(__half2*)(g_ql + o0) = l0;
                    *(__half2*)(g_qh + o1) = h1;
                    *(__half2*)(g_ql + o1) = l1;
                } else {
                    __half* dst = (sec == 1) ? g_kh : g_vh;
                    *(__half2*)(dst + o0) = __floats2half2_rn(f0, f1);
                    *(__half2*)(dst + o1) = __floats2half2_rn(f2, f3);
                }
            } else {
                *(float2*)(out + (size_t)m * 1024 + n) = {f0, f1};
                *(float2*)(out + (size_t)(m + 8) * 1024 + n) = {f2, f3};
            }
        }
    }
}

// ---------------- HMMA flash attention (fp16 2-product) ---------------------
// smem: Qh(16K) Ql(16K) + 2 x [Kh(8K) Vh(8K)] = 64K
#define ATT_SMEM (32768 + 2*16384)   // 65536

__global__ __launch_bounds__(256, 2)
void flash_attn_mma()
{
    extern __shared__ char smc[];
    const uint32_t sb = smem_u32(smc);
    const int tid  = threadIdx.x;
    const int wid  = tid >> 5;       // 0..7
    const int lane = tid & 31;
    const int lr = lane & 7;
    const int lg = lane >> 3;
    const int g  = lane >> 2;
    const int t2 = (lane & 3) * 2;

    const int qi = (int)gridDim.x - 1 - (int)blockIdx.x;
    const int qb = qi * 128;
    const int hh = blockIdx.y;
    const int bb = blockIdx.z;
    const size_t bhof = ((size_t)(bb * HEADS + hh)) * SEQ * HD;

    const __half* qh_g = g_qh + bhof;
    const __half* ql_g = g_ql + bhof;
    const __half* kh_g = g_kh + bhof;
    const __half* vh_g = g_vh + bhof;

    const uint32_t QH = sb, QL = sb + 16384;
    const uint32_t BUF0 = sb + 32768;

    #pragma unroll
    for (int u = tid; u < 1024; u += 256) {
        int row = u >> 3, seg = u & 7;
        uint32_t so = (uint32_t)(row * 128 + ((seg ^ (row & 7)) << 4));
        size_t go = (size_t)(qb + row) * 64 + seg * 8;
        CP_ASYNC16(QH + so, qh_g + go);
        CP_ASYNC16(QL + so, ql_g + go);
    }

    auto load_kv = [&](int kj) {
        uint32_t base = BUF0 + (uint32_t)(kj & 1) * 16384u;
        #pragma unroll
        for (int u = tid; u < 512; u += 256) {
            int row = u >> 3, seg = u & 7;
            uint32_t so = (uint32_t)(row * 128 + ((seg ^ (row & 7)) << 4));
            size_t go = (size_t)(kj * 64 + row) * 64 + seg * 8;
            CP_ASYNC16(base + so,         kh_g + go);
            CP_ASYNC16(base + 8192 + so,  vh_g + go);
        }
    };
    load_kv(0);
    CP_COMMIT();

    uint32_t qfh[4][4], qfl[4][4];
    float y[8][4];
    #pragma unroll
    for (int j = 0; j < 8; j++)
        #pragma unroll
        for (int r = 0; r < 4; r++) y[j][r] = 0.0f;
    float m0 = -1e30f, m1 = -1e30f, l0 = 0.0f, l1 = 0.0f;
    bool qloaded = false;

    const int nkj = 2 * qi + 2;
    const int wr0 = qb + wid * 16;

    for (int kj = 0; kj < nkj; kj++) {
        CP_WAIT0();
        __syncthreads();
        if (kj + 1 < nkj) { load_kv(kj + 1); CP_COMMIT(); }

        if (!qloaded) {
            qloaded = true;
            #pragma unroll
            for (int kc = 0; kc < 4; kc++) {
                int row = wid * 16 + lr + (lg & 1) * 8;
                int seg = 2 * kc + (lg >> 1);
                uint32_t so = (uint32_t)(row * 128 + ((seg ^ (row & 7)) << 4));
                ldsm_x4(qfh[kc][0], qfh[kc][1], qfh[kc][2], qfh[kc][3], QH + so);
                ldsm_x4(qfl[kc][0], qfl[kc][1], qfl[kc][2], qfl[kc][3], QL + so);
            }
        }

        const int c0t = kj * 64;
        if (c0t > wr0 + 15) continue;

        const uint32_t B = BUF0 + (uint32_t)(kj & 1) * 16384u;

        // ---- S = Q K^T (2-product: qh*kh + ql*kh) ----
        float s[8][4];
        #pragma unroll
        for (int j = 0; j < 8; j++)
            #pragma unroll
            for (int r = 0; r < 4; r++) s[j][r] = 0.0f;

        #pragma unroll
        for (int kc = 0; kc < 4; kc++) {
            uint32_t kh[4][4];
            #pragma unroll
            for (int p = 0; p < 4; p++) {
                int row = p * 16 + lr + (lg >> 1) * 8;
                int seg = 2 * kc + (lg & 1);
                uint32_t so = (uint32_t)(row * 128 + ((seg ^ (row & 7)) << 4));
                ldsm_x4(kh[p][0], kh[p][1], kh[p][2], kh[p][3], B + so);
            }
            #pragma unroll
            for (int p = 0; p < 4; p++) {
                mma2(s[2*p],   qfh[kc], kh[p][0], kh[p][1]);
                mma2(s[2*p+1], qfh[kc], kh[p][2], kh[p][3]);
            }
            #pragma unroll
            for (int p = 0; p < 4; p++) {
                mma2(s[2*p],   qfl[kc], kh[p][0], kh[p][1]);
                mma2(s[2*p+1], qfl[kc], kh[p][2], kh[p][3]);
            }
        }

        // ---- causal mask ----
        if (c0t + 63 > wr0) {
            int R0 = wr0 + g, R1 = wr0 + g + 8;
            #pragma unroll
            for (int j = 0; j < 8; j++) {
                int cg = c0t + j * 8 + t2;
                if (cg     > R0) s[j][0] = -1e30f;
                if (cg + 1 > R0) s[j][1] = -1e30f;
                if (cg     > R1) s[j][2] = -1e30f;
                if (cg + 1 > R1) s[j][3] = -1e30f;
            }
        }

        // ---- online softmax (exp2 domain) ----
        float mx0 = -1e30f, mx1 = -1e30f;
        #pragma unroll
        for (int j = 0; j < 8; j++) {
            mx0 = fmaxf(mx0, fmaxf(s[j][0], s[j][1]));
            mx1 = fmaxf(mx1, fmaxf(s[j][2], s[j][3]));
        }
        mx0 = fmaxf(mx0, __shfl_xor_sync(0xffffffffu, mx0, 1));
        mx0 = fmaxf(mx0, __shfl_xor_sync(0xffffffffu, mx0, 2));
        mx1 = fmaxf(mx1, __shfl_xor_sync(0xffffffffu, mx1, 1));
        mx1 = fmaxf(mx1, __shfl_xor_sync(0xffffffffu, mx1, 2));
        float mn0 = fmaxf(m0, mx0), mn1 = fmaxf(m1, mx1);
        float a0 = exp2f(m0 - mn0), a1 = exp2f(m1 - mn1);
        m0 = mn0; m1 = mn1;

        float s0 = 0.0f, s1 = 0.0f;
        uint32_t ph[4][4], pl[4][4];
        #pragma unroll
        for (int j = 0; j < 8; j++) {
            float p00 = exp2f(s[j][0] - mn0);
            float p01 = exp2f(s[j][1] - mn0);
            float p10 = exp2f(s[j][2] - mn1);
            float p11 = exp2f(s[j][3] - mn1);
            s0 += p00 + p01;
            s1 += p10 + p11;
            __half q00 = __float2half_rn(p00);
            __half q01 = __float2half_rn(p01);
            __half q10 = __float2half_rn(p10);
            __half q11 = __float2half_rn(p11);
            uint32_t hA, hB, lA, lB;
            { __half2 v = {q00, q01}; hA = *(uint32_t*)&v; }
            { __half2 v = {q10, q11}; hB = *(uint32_t*)&v; }
            lA = pack_h2(p00 - __half2float(q00), p01 - __half2float(q01));
            lB = pack_h2(p10 - __half2float(q10), p11 - __half2float(q11));
            int kc = j >> 1;
            if ((j & 1) == 0) {
                ph[kc][0] = hA; ph[kc][1] = hB;
                pl[kc][0] = lA; pl[kc][1] = lB;
            } else {
                ph[kc][2] = hA; ph[kc][3] = hB;
                pl[kc][2] = lA; pl[kc][3] = lB;
            }
        }
        s0 += __shfl_xor_sync(0xffffffffu, s0, 1);
        s0 += __shfl_xor_sync(0xffffffffu, s0, 2);
        s1 += __shfl_xor_sync(0xffffffffu, s1, 1);
        s1 += __shfl_xor_sync(0xffffffffu, s1, 2);
        l0 = l0 * a0 + s0;
        l1 = l1 * a1 + s1;
        #pragma unroll
        for (int j = 0; j < 8; j++) {
            y[j][0] *= a0; y[j][1] *= a0;
            y[j][2] *= a1; y[j][3] *= a1;
        }

        // ---- Y += P V (2-product: ph*vh + pl*vh) ----
        #pragma unroll
        for (int kc = 0; kc < 4; kc++) {
            uint32_t vh[4][4];
            #pragma unroll
            for (int dg = 0; dg < 4; dg++) {
                int row = kc * 16 + (lg & 1) * 8 + lr;
                int seg = 2 * dg + (lg >> 1);
                uint32_t so = (uint32_t)(row * 128 + ((seg ^ (row & 7)) << 4));
                ldsm_x4t(vh[dg][0], vh[dg][1], vh[dg][2], vh[dg][3], B + 8192 + so);
            }
            #pragma unroll
            for (int dg = 0; dg < 4; dg++) {
                mma2(y[2*dg],   ph[kc], vh[dg][0], vh[dg][1]);
                mma2(y[2*dg+1], ph[kc], vh[dg][2], vh[dg][3]);
            }
            #pragma unroll
            for (int dg = 0; dg < 4; dg++) {
                mma2(y[2*dg],   pl[kc], vh[dg][0], vh[dg][1]);
                mma2(y[2*dg+1], pl[kc], vh[dg][2], vh[dg][3]);
            }
        }
    }

    // ---- epilogue: normalize + fp16 hi/lo split -> g_yh / g_yl [B,S,E] ----
    const float i0 = 1.0f / l0, i1 = 1.0f / l1;
    const int r0 = wr0 + g;
    const int r1 = r0 + 8;
    const size_t rb0 = ((size_t)(bb * SEQ + r0)) * E_DIM + hh * HD;
    const size_t rb1 = ((size_t)(bb * SEQ + r1)) * E_DIM + hh * HD;
    #pragma unroll
    for (int j = 0; j < 8; j++) {
        int col = j * 8 + t2;
        float f0 = y[j][0] * i0, f1 = y[j][1] * i0;
        float f2 = y[j][2] * i1, f3 = y[j][3] * i1;
        __half2 h0 = __floats2half2_rn(f0, f1);
        __half2 h1 = __floats2half2_rn(f2, f3);
        __half2 l0p = __floats2half2_rn(
            f0 - __half2float(h0.x), f1 - __half2float(h0.y));
        __half2 l1p = __floats2half2_rn(
            f2 - __half2float(h1.x), f3 - __half2float(h1.y));
        *(__half2*)(g_yh + rb0 + col) = h0;
        *(__half2*)(g_yl + rb0 + col) = l0p;
        *(__half2*)(g_yh + rb1 + col) = h1;
        *(__half2*)(g_yl + rb1 + col) = l1p;
    }
}

// ---------------------------------------------------------------------------
extern "C" void kernel_launch(void* const* d_in, const int* in_sizes, int n_in,
                              void* d_out, int out_size)
{
    const float* x      = (const float*)d_in[0];
    const float* W_attn = (const float*)d_in[1];
    const float* b_attn = (const float*)d_in[2];
    const float* W_proj = (const float*)d_in[3];
    const float* b_proj = (const float*)d_in[4];
    float* out = (float*)d_out;

    cudaFuncSetAttribute(flash_attn_mma,
                         cudaFuncAttributeMaxDynamicSharedMemorySize, ATT_SMEM);
    cudaFuncSetAttribute(gemm_mma<3072, 0>,
                         cudaFuncAttributeMaxDynamicSharedMemorySize, GEMM_SMEM);
    cudaFuncSetAttribute(gemm_mma<1024, 1>,
                         cudaFuncAttributeMaxDynamicSharedMemorySize, GEMM_SMEM);

    __half *xh, *xl, *yh, *yl, *wah, *wph;
    cudaGetSymbolAddress((void**)&xh,  g_xh);
    cudaGetSymbolAddress((void**)&xl,  g_xl);
    cudaGetSymbolAddress((void**)&yh,  g_yh);
    cudaGetSymbolAddress((void**)&yl,  g_yl);
    cudaGetSymbolAddress((void**)&wah, g_wah);
    cudaGetSymbolAddress((void**)&wph, g_wph);

    split_scale<<<BS * E_DIM / 1024, 256>>>(x, xh, xl, 1.0f);
    {
        dim3 g(3 * E_DIM / 32, E_DIM / 32);
        wcast_t<<<g, 256>>>(W_attn, wah, 3 * E_DIM);
    }
    {
        dim3 g(E_DIM / 32, E_DIM / 32);
        wcast_t<<<g, 256>>>(W_proj, wph, E_DIM);
    }

    // 1) QKV GEMM -> q fp16 hi/lo (scaled), k/v fp16, [B,H,S,D]
    {
        dim3 grid(3 * E_DIM / 128, BS / 128);
        gemm_mma<3072, 0><<<grid, 256, GEMM_SMEM>>>(xh, xl, wah, b_attn, nullptr);
    }

    // 2) causal flash attention (HMMA fp16, exp2 softmax) -> yh/yl
    {
        dim3 grid(SEQ / 128, HEADS, BATCH);
        flash_attn_mma<<<grid, 256, ATT_SMEM>>>();
    }

    // 3) proj GEMM -> out
    {
        dim3 grid(E_DIM / 128, BS / 128);
        gemm_mma<1024, 1><<<grid, 256, GEMM_SMEM>>>(yh, yl, wph, b_proj, out);
    }
}

// round 9
// speedup vs baseline: 5.5050x; 1.1179x over previous
#include <cuda_runtime.h>
#include <cuda_fp16.h>
#include <cstdint>

#define E_DIM 1024
#define HEADS 16
#define HD 64
#define BATCH 4
#define SEQ 2048
#define BS (BATCH*SEQ)   // 8192

// q scale with log2(e) folded in: softmax done in exp2 domain
#define QSCALE 0.18033688011112042f   // 0.125 * log2(e)

// ---------------- scratch (device globals: allocation-guard safe) ----------
__device__ __align__(16) __half g_qh[BATCH*HEADS*SEQ*HD];
__device__ __align__(16) __half g_ql[BATCH*HEADS*SEQ*HD];
__device__ __align__(16) __half g_kh[BATCH*HEADS*SEQ*HD];
__device__ __align__(16) __half g_vh[BATCH*HEADS*SEQ*HD];

__device__ __align__(16) __half g_xh[BS*E_DIM];
__device__ __align__(16) __half g_xl[BS*E_DIM];
__device__ __align__(16) __half g_yh[BS*E_DIM];
__device__ __align__(16) __half g_yl[BS*E_DIM];
__device__ __align__(16) __half g_wah[3*E_DIM*E_DIM];   // W_attn^T fp16 [3072,1024]
__device__ __align__(16) __half g_wph[E_DIM*E_DIM];     // W_proj^T fp16 [1024,1024]

// ---------------- PTX helpers (all valid at compute_103) --------------------
__device__ __forceinline__ uint32_t smem_u32(const void* p) {
    uint32_t a;
    asm("{ .reg .u64 t; cvta.to.shared.u64 t, %1; cvt.u32.u64 %0, t; }"
        : "=r"(a) : "l"(p));
    return a;
}
#define CP_ASYNC16(sa, ga) \
    asm volatile("cp.async.cg.shared.global [%0], [%1], 16;" :: "r"(sa), "l"(ga))
#define CP_COMMIT() asm volatile("cp.async.commit_group;" ::: "memory")
#define CP_WAIT0()  asm volatile("cp.async.wait_group 0;" ::: "memory")

__device__ __forceinline__ void ldsm_x4(uint32_t& r0, uint32_t& r1,
                                        uint32_t& r2, uint32_t& r3, uint32_t addr) {
    asm volatile("ldmatrix.sync.aligned.m8n8.x4.shared.b16 {%0,%1,%2,%3}, [%4];"
                 : "=r"(r0), "=r"(r1), "=r"(r2), "=r"(r3) : "r"(addr));
}
__device__ __forceinline__ void ldsm_x4t(uint32_t& r0, uint32_t& r1,
                                         uint32_t& r2, uint32_t& r3, uint32_t addr) {
    asm volatile("ldmatrix.sync.aligned.m8n8.x4.trans.shared.b16 {%0,%1,%2,%3}, [%4];"
                 : "=r"(r0), "=r"(r1), "=r"(r2), "=r"(r3) : "r"(addr));
}
__device__ __forceinline__ void mma16816(float* d, const uint32_t* a, const uint32_t* b) {
    asm volatile(
        "mma.sync.aligned.m16n8k16.row.col.f32.f16.f16.f32 "
        "{%0,%1,%2,%3}, {%4,%5,%6,%7}, {%8,%9}, {%0,%1,%2,%3};"
        : "+f"(d[0]), "+f"(d[1]), "+f"(d[2]), "+f"(d[3])
        : "r"(a[0]), "r"(a[1]), "r"(a[2]), "r"(a[3]), "r"(b[0]), "r"(b[1]));
}
__device__ __forceinline__ void mma2(float* d, const uint32_t* a, uint32_t b0, uint32_t b1) {
    asm volatile(
        "mma.sync.aligned.m16n8k16.row.col.f32.f16.f16.f32 "
        "{%0,%1,%2,%3}, {%4,%5,%6,%7}, {%8,%9}, {%0,%1,%2,%3};"
        : "+f"(d[0]), "+f"(d[1]), "+f"(d[2]), "+f"(d[3])
        : "r"(a[0]), "r"(a[1]), "r"(a[2]), "r"(a[3]), "r"(b0), "r"(b1));
}
__device__ __forceinline__ uint32_t pack_h2(float a, float b) {
    __half2 v = __floats2half2_rn(a, b);
    return *reinterpret_cast<uint32_t*>(&v);
}

// ---------------- prep kernels ---------------------------------------------
__global__ __launch_bounds__(256)
void split_scale(const float* __restrict__ src,
                 __half* __restrict__ hi, __half* __restrict__ lo, float sc)
{
    int i = (blockIdx.x * 256 + threadIdx.x) * 4;
    float4 v = *(const float4*)(src + i);
    v.x *= sc; v.y *= sc; v.z *= sc; v.w *= sc;
    __half h0 = __float2half_rn(v.x), h1 = __float2half_rn(v.y);
    __half h2 = __float2half_rn(v.z), h3 = __float2half_rn(v.w);
    __half2 H0 = {h0, h1}, H1 = {h2, h3};
    __half2 L0 = __floats2half2_rn(v.x - __half2float(h0), v.y - __half2float(h1));
    __half2 L1 = __floats2half2_rn(v.z - __half2float(h2), v.w - __half2float(h3));
    *(__half2*)(hi + i)     = H0;
    *(__half2*)(hi + i + 2) = H1;
    *(__half2*)(lo + i)     = L0;
    *(__half2*)(lo + i + 2) = L1;
}

// W [1024, N] row-major -> Wt fp16 [N, 1024]
__global__ __launch_bounds__(256)
void wcast_t(const float* __restrict__ W, __half* __restrict__ Wh, int N)
{
    __shared__ float tile[32][33];
    int c0 = blockIdx.x * 32;
    int r0 = blockIdx.y * 32;
    int tx = threadIdx.x & 31, ty = threadIdx.x >> 5;
    #pragma unroll
    for (int i = ty; i < 32; i += 8)
        tile[i][tx] = W[(size_t)(r0 + i) * N + c0 + tx];
    __syncthreads();
    #pragma unroll
    for (int i = ty; i < 32; i += 8)
        Wh[(size_t)(c0 + i) * 1024 + r0 + tx] = __float2half_rn(tile[tx][i]);
}

// ---------------- HMMA GEMM -------------------------------------------------
// NPROD=2: Ah*Bh + Al*Bh (for q and proj). NPROD=1: Ah*Bh only (k/v: result
// is stored as single fp16, so the 2nd product's precision would be discarded).
// MODE 0: epilogue -> q fp16 hi/lo (QSCALE) / k / v in [B,H,S,D]
// MODE 1: epilogue -> out fp32 [8192,1024]
#define GEMM_SMEM_MAX (2*24576)   // worst case (NPROD=2)

template<int MODE, int NPROD>
__global__ __launch_bounds__(256, 2)
void gemm_mma(const __half* __restrict__ Ah, const __half* __restrict__ Al,
              const __half* __restrict__ Bh,
              const float* __restrict__ bias, float* __restrict__ out,
              int nbase)
{
    constexpr uint32_t B_OFF = (NPROD == 2) ? 16384u : 8192u;
    constexpr uint32_t BUFB  = (NPROD == 2) ? 24576u : 16384u;

    extern __shared__ char smem[];
    const uint32_t sb = smem_u32(smem);
    const int tid  = threadIdx.x;
    const int wid  = tid >> 5;
    const int lane = tid & 31;
    const int m0 = blockIdx.y * 128;
    const int n0 = nbase + blockIdx.x * 128;

    const int wm = wid & 1;
    const int wn = wid >> 1;
    const int lr = lane & 7;
    const int lg = lane >> 3;

    float acc[4][4][4];
    #pragma unroll
    for (int i = 0; i < 4; i++)
        #pragma unroll
        for (int j = 0; j < 4; j++)
            #pragma unroll
            for (int r = 0; r < 4; r++) acc[i][j][r] = 0.0f;

    auto load_chunk = [&](int c) {
        const int k0 = c * 32;
        const uint32_t sbase = sb + (uint32_t)(c & 1) * BUFB;
        #pragma unroll
        for (int t = 0; t < 2; t++) {
            int u = tid + t * 256;
            int r = u >> 2, seg = u & 3;
            uint32_t soff = (uint32_t)(r * 64 + ((seg ^ ((r >> 1) & 3)) << 4));
            size_t ga = (size_t)(m0 + r) * 1024 + k0 + seg * 8;
            size_t gb = (size_t)(n0 + r) * 1024 + k0 + seg * 8;
            CP_ASYNC16(sbase + soff, Ah + ga);
            if (NPROD == 2) CP_ASYNC16(sbase + 8192 + soff, Al + ga);
            CP_ASYNC16(sbase + B_OFF + soff, Bh + gb);
        }
        CP_COMMIT();
    };

    load_chunk(0);

    for (int c = 0; c < 32; c++) {
        CP_WAIT0();
        __syncthreads();
        if (c + 1 < 32) load_chunk(c + 1);

        const uint32_t sbase = sb + (uint32_t)(c & 1) * BUFB;
        #pragma unroll
        for (int s = 0; s < 2; s++) {
            uint32_t ah[4][4], al[4][4], bh[4][2];
            #pragma unroll
            for (int i = 0; i < 4; i++) {
                int row = wm * 64 + i * 16 + lr + (lg & 1) * 8;
                int seg = 2 * s + (lg >> 1);
                uint32_t ad = sbase + (uint32_t)(row * 64 +
                              ((seg ^ ((row >> 1) & 3)) << 4));
                ldsm_x4(ah[i][0], ah[i][1], ah[i][2], ah[i][3], ad);
                if (NPROD == 2)
                    ldsm_x4(al[i][0], al[i][1], al[i][2], al[i][3], ad + 8192);
            }
            #pragma unroll
            for (int p = 0; p < 2; p++) {
                int row = wn * 32 + p * 16 + lr + (lg >> 1) * 8;
                int seg = 2 * s + (lg & 1);
                uint32_t bd = sbase + B_OFF + (uint32_t)(row * 64 +
                              ((seg ^ ((row >> 1) & 3)) << 4));
                uint32_t r0, r1, r2, r3;
                ldsm_x4(r0, r1, r2, r3, bd);
                bh[2*p][0] = r0; bh[2*p][1] = r1;
                bh[2*p+1][0] = r2; bh[2*p+1][1] = r3;
            }
            #pragma unroll
            for (int i = 0; i < 4; i++)
                #pragma unroll
                for (int j = 0; j < 4; j++)
                    mma16816(acc[i][j], ah[i], bh[j]);
            if (NPROD == 2) {
                #pragma unroll
                for (int i = 0; i < 4; i++)
                    #pragma unroll
                    for (int j = 0; j < 4; j++)
                        mma16816(acc[i][j], al[i], bh[j]);
            }
        }
    }

    const int mrow = m0 + wm * 64 + (lane >> 2);
    const int ncol = n0 + wn * 32 + (lane & 3) * 2;
    #pragma unroll
    for (int i = 0; i < 4; i++) {
        #pragma unroll
        for (int j = 0; j < 4; j++) {
            int m = mrow + i * 16;
            int n = ncol + j * 8;
            float b0 = __ldg(&bias[n]), b1 = __ldg(&bias[n + 1]);
            float f0 = acc[i][j][0] + b0, f1 = acc[i][j][1] + b1;
            float f2 = acc[i][j][2] + b0, f3 = acc[i][j][3] + b1;
            if (MODE == 0) {
                int sec = n >> 10;
                int e   = n & 1023;
                int hh  = e >> 6;
                int d   = e & 63;
                int b_ = m >> 11, s_ = m & 2047;
                size_t o0 = ((size_t)((b_ * HEADS + hh) * SEQ) + s_) * HD + d;
                size_t o1 = o0 + 8 * HD;
                if (sec == 0) {
                    f0 *= QSCALE; f1 *= QSCALE; f2 *= QSCALE; f3 *= QSCALE;
                    __half2 h0 = __floats2half2_rn(f0, f1);
                    __half2 h1 = __floats2half2_rn(f2, f3);
                    __half2 l0 = __floats2half2_rn(
                        f0 - __half2float(h0.x), f1 - __half2float(h0.y));
                    __half2 l1 = __floats2half2_rn(
                        f2 - __half2float(h1.x), f3 - __half2float(h1.y));
                    *(__half2*)(g_qh + o0) = h0;
                    *(__half2*)(g_ql + o0) = l0;
                    *(__half2*)(g_qh + o1) = h1;
                    *(__half2*)(g_ql + o1) = l1;
                } else {
                    __half* dst = (sec == 1) ? g_kh : g_vh;
                    *(__half2*)(dst + o0) = __floats2half2_rn(f0, f1);
                    *(__half2*)(dst + o1) = __floats2half2_rn(f2, f3);
                }
            } else {
                *(float2*)(out + (size_t)m * 1024 + n) = {f0, f1};
                *(float2*)(out + (size_t)(m + 8) * 1024 + n) = {f2, f3};
            }
        }
    }
}

// ---------------- HMMA flash attention (fp16 2-product) ---------------------
// smem: Qh(16K) Ql(16K) + 2 x [Kh(8K) Vh(8K)] = 64K
#define ATT_SMEM (32768 + 2*16384)   // 65536

__global__ __launch_bounds__(256, 2)
void flash_attn_mma()
{
    extern __shared__ char smc[];
    const uint32_t sb = smem_u32(smc);
    const int tid  = threadIdx.x;
    const int wid  = tid >> 5;       // 0..7
    const int lane = tid & 31;
    const int lr = lane & 7;
    const int lg = lane >> 3;
    const int g  = lane >> 2;
    const int t2 = (lane & 3) * 2;

    const int qi = (int)gridDim.x - 1 - (int)blockIdx.x;
    const int qb = qi * 128;
    const int hh = blockIdx.y;
    const int bb = blockIdx.z;
    const size_t bhof = ((size_t)(bb * HEADS + hh)) * SEQ * HD;

    const __half* qh_g = g_qh + bhof;
    const __half* ql_g = g_ql + bhof;
    const __half* kh_g = g_kh + bhof;
    const __half* vh_g = g_vh + bhof;

    const uint32_t QH = sb, QL = sb + 16384;
    const uint32_t BUF0 = sb + 32768;

    #pragma unroll
    for (int u = tid; u < 1024; u += 256) {
        int row = u >> 3, seg = u & 7;
        uint32_t so = (uint32_t)(row * 128 + ((seg ^ (row & 7)) << 4));
        size_t go = (size_t)(qb + row) * 64 + seg * 8;
        CP_ASYNC16(QH + so, qh_g + go);
        CP_ASYNC16(QL + so, ql_g + go);
    }

    auto load_kv = [&](int kj) {
        uint32_t base = BUF0 + (uint32_t)(kj & 1) * 16384u;
        #pragma unroll
        for (int u = tid; u < 512; u += 256) {
            int row = u >> 3, seg = u & 7;
            uint32_t so = (uint32_t)(row * 128 + ((seg ^ (row & 7)) << 4));
            size_t go = (size_t)(kj * 64 + row) * 64 + seg * 8;
            CP_ASYNC16(base + so,         kh_g + go);
            CP_ASYNC16(base + 8192 + so,  vh_g + go);
        }
    };
    load_kv(0);
    CP_COMMIT();

    uint32_t qfh[4][4], qfl[4][4];
    float y[8][4];
    #pragma unroll
    for (int j = 0; j < 8; j++)
        #pragma unroll
        for (int r = 0; r < 4; r++) y[j][r] = 0.0f;
    float m0 = -1e30f, m1 = -1e30f, l0 = 0.0f, l1 = 0.0f;
    bool qloaded = false;

    const int nkj = 2 * qi + 2;
    const int wr0 = qb + wid * 16;

    for (int kj = 0; kj < nkj; kj++) {
        CP_WAIT0();
        __syncthreads();
        if (kj + 1 < nkj) { load_kv(kj + 1); CP_COMMIT(); }

        if (!qloaded) {
            qloaded = true;
            #pragma unroll
            for (int kc = 0; kc < 4; kc++) {
                int row = wid * 16 + lr + (lg & 1) * 8;
                int seg = 2 * kc + (lg >> 1);
                uint32_t so = (uint32_t)(row * 128 + ((seg ^ (row & 7)) << 4));
                ldsm_x4(qfh[kc][0], qfh[kc][1], qfh[kc][2], qfh[kc][3], QH + so);
                ldsm_x4(qfl[kc][0], qfl[kc][1], qfl[kc][2], qfl[kc][3], QL + so);
            }
        }

        const int c0t = kj * 64;
        if (c0t > wr0 + 15) continue;

        const uint32_t B = BUF0 + (uint32_t)(kj & 1) * 16384u;

        // ---- S = Q K^T (2-product: qh*kh + ql*kh) ----
        float s[8][4];
        #pragma unroll
        for (int j = 0; j < 8; j++)
            #pragma unroll
            for (int r = 0; r < 4; r++) s[j][r] = 0.0f;

        #pragma unroll
        for (int kc = 0; kc < 4; kc++) {
            uint32_t kh[4][4];
            #pragma unroll
            for (int p = 0; p < 4; p++) {
                int row = p * 16 + lr + (lg >> 1) * 8;
                int seg = 2 * kc + (lg & 1);
                uint32_t so = (uint32_t)(row * 128 + ((seg ^ (row & 7)) << 4));
                ldsm_x4(kh[p][0], kh[p][1], kh[p][2], kh[p][3], B + so);
            }
            #pragma unroll
            for (int p = 0; p < 4; p++) {
                mma2(s[2*p],   qfh[kc], kh[p][0], kh[p][1]);
                mma2(s[2*p+1], qfh[kc], kh[p][2], kh[p][3]);
            }
            #pragma unroll
            for (int p = 0; p < 4; p++) {
                mma2(s[2*p],   qfl[kc], kh[p][0], kh[p][1]);
                mma2(s[2*p+1], qfl[kc], kh[p][2], kh[p][3]);
            }
        }

        // ---- causal mask ----
        if (c0t + 63 > wr0) {
            int R0 = wr0 + g, R1 = wr0 + g + 8;
            #pragma unroll
            for (int j = 0; j < 8; j++) {
                int cg = c0t + j * 8 + t2;
                if (cg     > R0) s[j][0] = -1e30f;
                if (cg + 1 > R0) s[j][1] = -1e30f;
                if (cg     > R1) s[j][2] = -1e30f;
                if (cg + 1 > R1) s[j][3] = -1e30f;
            }
        }

        // ---- online softmax (exp2 domain) ----
        float mx0 = -1e30f, mx1 = -1e30f;
        #pragma unroll
        for (int j = 0; j < 8; j++) {
            mx0 = fmaxf(mx0, fmaxf(s[j][0], s[j][1]));
            mx1 = fmaxf(mx1, fmaxf(s[j][2], s[j][3]));
        }
        mx0 = fmaxf(mx0, __shfl_xor_sync(0xffffffffu, mx0, 1));
        mx0 = fmaxf(mx0, __shfl_xor_sync(0xffffffffu, mx0, 2));
        mx1 = fmaxf(mx1, __shfl_xor_sync(0xffffffffu, mx1, 1));
        mx1 = fmaxf(mx1, __shfl_xor_sync(0xffffffffu, mx1, 2));
        float mn0 = fmaxf(m0, mx0), mn1 = fmaxf(m1, mx1);
        float a0 = exp2f(m0 - mn0), a1 = exp2f(m1 - mn1);
        m0 = mn0; m1 = mn1;

        float s0 = 0.0f, s1 = 0.0f;
        uint32_t ph[4][4], pl[4][4];
        #pragma unroll
        for (int j = 0; j < 8; j++) {
            float p00 = exp2f(s[j][0] - mn0);
            float p01 = exp2f(s[j][1] - mn0);
            float p10 = exp2f(s[j][2] - mn1);
            float p11 = exp2f(s[j][3] - mn1);
            s0 += p00 + p01;
            s1 += p10 + p11;
            __half q00 = __float2half_rn(p00);
            __half q01 = __float2half_rn(p01);
            __half q10 = __float2half_rn(p10);
            __half q11 = __float2half_rn(p11);
            uint32_t hA, hB, lA, lB;
            { __half2 v = {q00, q01}; hA = *(uint32_t*)&v; }
            { __half2 v = {q10, q11}; hB = *(uint32_t*)&v; }
            lA = pack_h2(p00 - __half2float(q00), p01 - __half2float(q01));
            lB = pack_h2(p10 - __half2float(q10), p11 - __half2float(q11));
            int kc = j >> 1;
            if ((j & 1) == 0) {
                ph[kc][0] = hA; ph[kc][1] = hB;
                pl[kc][0] = lA; pl[kc][1] = lB;
            } else {
                ph[kc][2] = hA; ph[kc][3] = hB;
                pl[kc][2] = lA; pl[kc][3] = lB;
            }
        }
        s0 += __shfl_xor_sync(0xffffffffu, s0, 1);
        s0 += __shfl_xor_sync(0xffffffffu, s0, 2);
        s1 += __shfl_xor_sync(0xffffffffu, s1, 1);
        s1 += __shfl_xor_sync(0xffffffffu, s1, 2);
        l0 = l0 * a0 + s0;
        l1 = l1 * a1 + s1;
        #pragma unroll
        for (int j = 0; j < 8; j++) {
            y[j][0] *= a0; y[j][1] *= a0;
            y[j][2] *= a1; y[j][3] *= a1;
        }

        // ---- Y += P V (2-product: ph*vh + pl*vh) ----
        #pragma unroll
        for (int kc = 0; kc < 4; kc++) {
            uint32_t vh[4][4];
            #pragma unroll
            for (int dg = 0; dg < 4; dg++) {
                int row = kc * 16 + (lg & 1) * 8 + lr;
                int seg = 2 * dg + (lg >> 1);
                uint32_t so = (uint32_t)(row * 128 + ((seg ^ (row & 7)) << 4));
                ldsm_x4t(vh[dg][0], vh[dg][1], vh[dg][2], vh[dg][3], B + 8192 + so);
            }
            #pragma unroll
            for (int dg = 0; dg < 4; dg++) {
                mma2(y[2*dg],   ph[kc], vh[dg][0], vh[dg][1]);
                mma2(y[2*dg+1], ph[kc], vh[dg][2], vh[dg][3]);
            }
            #pragma unroll
            for (int dg = 0; dg < 4; dg++) {
                mma2(y[2*dg],   pl[kc], vh[dg][0], vh[dg][1]);
                mma2(y[2*dg+1], pl[kc], vh[dg][2], vh[dg][3]);
            }
        }
    }

    // ---- epilogue: normalize + fp16 hi/lo split -> g_yh / g_yl [B,S,E] ----
    const float i0 = 1.0f / l0, i1 = 1.0f / l1;
    const int r0 = wr0 + g;
    const int r1 = r0 + 8;
    const size_t rb0 = ((size_t)(bb * SEQ + r0)) * E_DIM + hh * HD;
    const size_t rb1 = ((size_t)(bb * SEQ + r1)) * E_DIM + hh * HD;
    #pragma unroll
    for (int j = 0; j < 8; j++) {
        int col = j * 8 + t2;
        float f0 = y[j][0] * i0, f1 = y[j][1] * i0;
        float f2 = y[j][2] * i1, f3 = y[j][3] * i1;
        __half2 h0 = __floats2half2_rn(f0, f1);
        __half2 h1 = __floats2half2_rn(f2, f3);
        __half2 l0p = __floats2half2_rn(
            f0 - __half2float(h0.x), f1 - __half2float(h0.y));
        __half2 l1p = __floats2half2_rn(
            f2 - __half2float(h1.x), f3 - __half2float(h1.y));
        *(__half2*)(g_yh + rb0 + col) = h0;
        *(__half2*)(g_yl + rb0 + col) = l0p;
        *(__half2*)(g_yh + rb1 + col) = h1;
        *(__half2*)(g_yl + rb1 + col) = l1p;
    }
}

// ---------------------------------------------------------------------------
extern "C" void kernel_launch(void* const* d_in, const int* in_sizes, int n_in,
                              void* d_out, int out_size)
{
    const float* x      = (const float*)d_in[0];
    const float* W_attn = (const float*)d_in[1];
    const float* b_attn = (const float*)d_in[2];
    const float* W_proj = (const float*)d_in[3];
    const float* b_proj = (const float*)d_in[4];
    float* out = (float*)d_out;

    cudaFuncSetAttribute(flash_attn_mma,
                         cudaFuncAttributeMaxDynamicSharedMemorySize, ATT_SMEM);
    cudaFuncSetAttribute(gemm_mma<0, 2>,
                         cudaFuncAttributeMaxDynamicSharedMemorySize, GEMM_SMEM_MAX);
    cudaFuncSetAttribute(gemm_mma<0, 1>,
                         cudaFuncAttributeMaxDynamicSharedMemorySize, GEMM_SMEM_MAX);
    cudaFuncSetAttribute(gemm_mma<1, 2>,
                         cudaFuncAttributeMaxDynamicSharedMemorySize, GEMM_SMEM_MAX);

    __half *xh, *xl, *yh, *yl, *wah, *wph;
    cudaGetSymbolAddress((void**)&xh,  g_xh);
    cudaGetSymbolAddress((void**)&xl,  g_xl);
    cudaGetSymbolAddress((void**)&yh,  g_yh);
    cudaGetSymbolAddress((void**)&yl,  g_yl);
    cudaGetSymbolAddress((void**)&wah, g_wah);
    cudaGetSymbolAddress((void**)&wph, g_wph);

    split_scale<<<BS * E_DIM / 1024, 256>>>(x, xh, xl, 1.0f);
    {
        dim3 g(3 * E_DIM / 32, E_DIM / 32);
        wcast_t<<<g, 256>>>(W_attn, wah, 3 * E_DIM);
    }
    {
        dim3 g(E_DIM / 32, E_DIM / 32);
        wcast_t<<<g, 256>>>(W_proj, wph, E_DIM);
    }

    // 1a) q columns: 2-product (q stored hi/lo, keeps precision for QK^T)
    {
        dim3 grid(E_DIM / 128, BS / 128);                    // 8 x 64
        gemm_mma<0, 2><<<grid, 256, 2*24576>>>(xh, xl, wah, b_attn, nullptr, 0);
    }
    // 1b) k/v columns: 1-product (stored as single fp16 anyway)
    {
        dim3 grid(2 * E_DIM / 128, BS / 128);                // 16 x 64
        gemm_mma<0, 1><<<grid, 256, 2*16384>>>(xh, xl, wah, b_attn, nullptr, 1024);
    }

    // 2) causal flash attention (HMMA fp16, exp2 softmax) -> yh/yl
    {
        dim3 grid(SEQ / 128, HEADS, BATCH);
        flash_attn_mma<<<grid, 256, ATT_SMEM>>>();
    }

    // 3) proj GEMM -> out
    {
        dim3 grid(E_DIM / 128, BS / 128);
        gemm_mma<1, 2><<<grid, 256, 2*24576>>>(yh, yl, wph, b_proj, out, 0);
    }
}

// round 10
// speedup vs baseline: 6.7188x; 1.2205x over previous
#include <cuda_runtime.h>
#include <cuda_fp16.h>
#include <cstdint>

#define E_DIM 1024
#define HEADS 16
#define HD 64
#define BATCH 4
#define SEQ 2048
#define BS (BATCH*SEQ)   // 8192

// q scale with log2(e) folded in: softmax done in exp2 domain
#define QSCALE 0.18033688011112042f   // 0.125 * log2(e)

// ---------------- scratch (device globals: allocation-guard safe) ----------
__device__ __align__(16) __half g_qh[BATCH*HEADS*SEQ*HD];
__device__ __align__(16) __half g_ql[BATCH*HEADS*SEQ*HD];
__device__ __align__(16) __half g_kh[BATCH*HEADS*SEQ*HD];
__device__ __align__(16) __half g_vh[BATCH*HEADS*SEQ*HD];

__device__ __align__(16) __half g_xh[BS*E_DIM];
__device__ __align__(16) __half g_xl[BS*E_DIM];
__device__ __align__(16) __half g_yh[BS*E_DIM];
__device__ __align__(16) __half g_wah[3*E_DIM*E_DIM];   // W_attn^T fp16 [3072,1024]
__device__ __align__(16) __half g_wph[E_DIM*E_DIM];     // W_proj^T fp16 [1024,1024]

// ---------------- PTX helpers (all valid at compute_103) --------------------
__device__ __forceinline__ uint32_t smem_u32(const void* p) {
    uint32_t a;
    asm("{ .reg .u64 t; cvta.to.shared.u64 t, %1; cvt.u32.u64 %0, t; }"
        : "=r"(a) : "l"(p));
    return a;
}
#define CP_ASYNC16(sa, ga) \
    asm volatile("cp.async.cg.shared.global [%0], [%1], 16;" :: "r"(sa), "l"(ga))
#define CP_COMMIT() asm volatile("cp.async.commit_group;" ::: "memory")
#define CP_WAIT0()  asm volatile("cp.async.wait_group 0;" ::: "memory")

__device__ __forceinline__ void ldsm_x4(uint32_t& r0, uint32_t& r1,
                                        uint32_t& r2, uint32_t& r3, uint32_t addr) {
    asm volatile("ldmatrix.sync.aligned.m8n8.x4.shared.b16 {%0,%1,%2,%3}, [%4];"
                 : "=r"(r0), "=r"(r1), "=r"(r2), "=r"(r3) : "r"(addr));
}
__device__ __forceinline__ void ldsm_x4t(uint32_t& r0, uint32_t& r1,
                                         uint32_t& r2, uint32_t& r3, uint32_t addr) {
    asm volatile("ldmatrix.sync.aligned.m8n8.x4.trans.shared.b16 {%0,%1,%2,%3}, [%4];"
                 : "=r"(r0), "=r"(r1), "=r"(r2), "=r"(r3) : "r"(addr));
}
__device__ __forceinline__ void mma16816(float* d, const uint32_t* a, const uint32_t* b) {
    asm volatile(
        "mma.sync.aligned.m16n8k16.row.col.f32.f16.f16.f32 "
        "{%0,%1,%2,%3}, {%4,%5,%6,%7}, {%8,%9}, {%0,%1,%2,%3};"
        : "+f"(d[0]), "+f"(d[1]), "+f"(d[2]), "+f"(d[3])
        : "r"(a[0]), "r"(a[1]), "r"(a[2]), "r"(a[3]), "r"(b[0]), "r"(b[1]));
}
__device__ __forceinline__ void mma2(float* d, const uint32_t* a, uint32_t b0, uint32_t b1) {
    asm volatile(
        "mma.sync.aligned.m16n8k16.row.col.f32.f16.f16.f32 "
        "{%0,%1,%2,%3}, {%4,%5,%6,%7}, {%8,%9}, {%0,%1,%2,%3};"
        : "+f"(d[0]), "+f"(d[1]), "+f"(d[2]), "+f"(d[3])
        : "r"(a[0]), "r"(a[1]), "r"(a[2]), "r"(a[3]), "r"(b0), "r"(b1));
}

// ---------------- prep kernels ---------------------------------------------
__global__ __launch_bounds__(256)
void split_scale(const float* __restrict__ src,
                 __half* __restrict__ hi, __half* __restrict__ lo, float sc)
{
    int i = (blockIdx.x * 256 + threadIdx.x) * 4;
    float4 v = *(const float4*)(src + i);
    v.x *= sc; v.y *= sc; v.z *= sc; v.w *= sc;
    __half h0 = __float2half_rn(v.x), h1 = __float2half_rn(v.y);
    __half h2 = __float2half_rn(v.z), h3 = __float2half_rn(v.w);
    __half2 H0 = {h0, h1}, H1 = {h2, h3};
    __half2 L0 = __floats2half2_rn(v.x - __half2float(h0), v.y - __half2float(h1));
    __half2 L1 = __floats2half2_rn(v.z - __half2float(h2), v.w - __half2float(h3));
    *(__half2*)(hi + i)     = H0;
    *(__half2*)(hi + i + 2) = H1;
    *(__half2*)(lo + i)     = L0;
    *(__half2*)(lo + i + 2) = L1;
}

// W [1024, N] row-major -> Wt fp16 [N, 1024]
__global__ __launch_bounds__(256)
void wcast_t(const float* __restrict__ W, __half* __restrict__ Wh, int N)
{
    __shared__ float tile[32][33];
    int c0 = blockIdx.x * 32;
    int r0 = blockIdx.y * 32;
    int tx = threadIdx.x & 31, ty = threadIdx.x >> 5;
    #pragma unroll
    for (int i = ty; i < 32; i += 8)
        tile[i][tx] = W[(size_t)(r0 + i) * N + c0 + tx];
    __syncthreads();
    #pragma unroll
    for (int i = ty; i < 32; i += 8)
        Wh[(size_t)(c0 + i) * 1024 + r0 + tx] = __float2half_rn(tile[tx][i]);
}

// ---------------- HMMA GEMM -------------------------------------------------
// NPROD=2: Ah*Bh + Al*Bh. NPROD=1: Ah*Bh only.
// MODE 0: epilogue -> q fp16 hi/lo (QSCALE) / k / v in [B,H,S,D]
// MODE 1: epilogue -> out fp32 [8192,1024]
#define GEMM_SMEM_MAX (2*24576)

template<int MODE, int NPROD>
__global__ __launch_bounds__(256, 2)
void gemm_mma(const __half* __restrict__ Ah, const __half* __restrict__ Al,
              const __half* __restrict__ Bh,
              const float* __restrict__ bias, float* __restrict__ out,
              int nbase)
{
    constexpr uint32_t B_OFF = (NPROD == 2) ? 16384u : 8192u;
    constexpr uint32_t BUFB  = (NPROD == 2) ? 24576u : 16384u;

    extern __shared__ char smem[];
    const uint32_t sb = smem_u32(smem);
    const int tid  = threadIdx.x;
    const int wid  = tid >> 5;
    const int lane = tid & 31;
    const int m0 = blockIdx.y * 128;
    const int n0 = nbase + blockIdx.x * 128;

    const int wm = wid & 1;
    const int wn = wid >> 1;
    const int lr = lane & 7;
    const int lg = lane >> 3;

    float acc[4][4][4];
    #pragma unroll
    for (int i = 0; i < 4; i++)
        #pragma unroll
        for (int j = 0; j < 4; j++)
            #pragma unroll
            for (int r = 0; r < 4; r++) acc[i][j][r] = 0.0f;

    auto load_chunk = [&](int c) {
        const int k0 = c * 32;
        const uint32_t sbase = sb + (uint32_t)(c & 1) * BUFB;
        #pragma unroll
        for (int t = 0; t < 2; t++) {
            int u = tid + t * 256;
            int r = u >> 2, seg = u & 3;
            uint32_t soff = (uint32_t)(r * 64 + ((seg ^ ((r >> 1) & 3)) << 4));
            size_t ga = (size_t)(m0 + r) * 1024 + k0 + seg * 8;
            size_t gb = (size_t)(n0 + r) * 1024 + k0 + seg * 8;
            CP_ASYNC16(sbase + soff, Ah + ga);
            if (NPROD == 2) CP_ASYNC16(sbase + 8192 + soff, Al + ga);
            CP_ASYNC16(sbase + B_OFF + soff, Bh + gb);
        }
        CP_COMMIT();
    };

    load_chunk(0);

    for (int c = 0; c < 32; c++) {
        CP_WAIT0();
        __syncthreads();
        if (c + 1 < 32) load_chunk(c + 1);

        const uint32_t sbase = sb + (uint32_t)(c & 1) * BUFB;
        #pragma unroll
        for (int s = 0; s < 2; s++) {
            uint32_t ah[4][4], al[4][4], bh[4][2];
            #pragma unroll
            for (int i = 0; i < 4; i++) {
                int row = wm * 64 + i * 16 + lr + (lg & 1) * 8;
                int seg = 2 * s + (lg >> 1);
                uint32_t ad = sbase + (uint32_t)(row * 64 +
                              ((seg ^ ((row >> 1) & 3)) << 4));
                ldsm_x4(ah[i][0], ah[i][1], ah[i][2], ah[i][3], ad);
                if (NPROD == 2)
                    ldsm_x4(al[i][0], al[i][1], al[i][2], al[i][3], ad + 8192);
            }
            #pragma unroll
            for (int p = 0; p < 2; p++) {
                int row = wn * 32 + p * 16 + lr + (lg >> 1) * 8;
                int seg = 2 * s + (lg & 1);
                uint32_t bd = sbase + B_OFF + (uint32_t)(row * 64 +
                              ((seg ^ ((row >> 1) & 3)) << 4));
                uint32_t r0, r1, r2, r3;
                ldsm_x4(r0, r1, r2, r3, bd);
                bh[2*p][0] = r0; bh[2*p][1] = r1;
                bh[2*p+1][0] = r2; bh[2*p+1][1] = r3;
            }
            #pragma unroll
            for (int i = 0; i < 4; i++)
                #pragma unroll
                for (int j = 0; j < 4; j++)
                    mma16816(acc[i][j], ah[i], bh[j]);
            if (NPROD == 2) {
                #pragma unroll
                for (int i = 0; i < 4; i++)
                    #pragma unroll
                    for (int j = 0; j < 4; j++)
                        mma16816(acc[i][j], al[i], bh[j]);
            }
        }
    }

    const int mrow = m0 + wm * 64 + (lane >> 2);
    const int ncol = n0 + wn * 32 + (lane & 3) * 2;
    #pragma unroll
    for (int i = 0; i < 4; i++) {
        #pragma unroll
        for (int j = 0; j < 4; j++) {
            int m = mrow + i * 16;
            int n = ncol + j * 8;
            float b0 = __ldg(&bias[n]), b1 = __ldg(&bias[n + 1]);
            float f0 = acc[i][j][0] + b0, f1 = acc[i][j][1] + b1;
            float f2 = acc[i][j][2] + b0, f3 = acc[i][j][3] + b1;
            if (MODE == 0) {
                int sec = n >> 10;
                int e   = n & 1023;
                int hh  = e >> 6;
                int d   = e & 63;
                int b_ = m >> 11, s_ = m & 2047;
                size_t o0 = ((size_t)((b_ * HEADS + hh) * SEQ) + s_) * HD + d;
                size_t o1 = o0 + 8 * HD;
                if (sec == 0) {
                    f0 *= QSCALE; f1 *= QSCALE; f2 *= QSCALE; f3 *= QSCALE;
                    __half2 h0 = __floats2half2_rn(f0, f1);
                    __half2 h1 = __floats2half2_rn(f2, f3);
                    __half2 l0 = __floats2half2_rn(
                        f0 - __half2float(h0.x), f1 - __half2float(h0.y));
                    __half2 l1 = __floats2half2_rn(
                        f2 - __half2float(h1.x), f3 - __half2float(h1.y));
                    *(__half2*)(g_qh + o0) = h0;
                    *(__half2*)(g_ql + o0) = l0;
                    *(__half2*)(g_qh + o1) = h1;
                    *(__half2*)(g_ql + o1) = l1;
                } else {
                    __half* dst = (sec == 1) ? g_kh : g_vh;
                    *(__half2*)(dst + o0) = __floats2half2_rn(f0, f1);
                    *(__half2*)(dst + o1) = __floats2half2_rn(f2, f3);
                }
            } else {
                *(float2*)(out + (size_t)m * 1024 + n) = {f0, f1};
                *(float2*)(out + (size_t)(m + 8) * 1024 + n) = {f2, f3};
            }
        }
    }
}

// ---------------- HMMA flash attention --------------------------------------
// QK: 2-product (qh,ql x kh). PV: 1-product (P fp16 x vh).
// y stored as single fp16 -> proj is a 1-product GEMM.
// smem: Qh(16K) Ql(16K) + 2 x [Kh(8K) Vh(8K)] = 64K
#define ATT_SMEM (32768 + 2*16384)   // 65536

__global__ __launch_bounds__(256, 2)
void flash_attn_mma()
{
    extern __shared__ char smc[];
    const uint32_t sb = smem_u32(smc);
    const int tid  = threadIdx.x;
    const int wid  = tid >> 5;       // 0..7
    const int lane = tid & 31;
    const int lr = lane & 7;
    const int lg = lane >> 3;
    const int g  = lane >> 2;
    const int t2 = (lane & 3) * 2;

    const int qi = (int)gridDim.x - 1 - (int)blockIdx.x;
    const int qb = qi * 128;
    const int hh = blockIdx.y;
    const int bb = blockIdx.z;
    const size_t bhof = ((size_t)(bb * HEADS + hh)) * SEQ * HD;

    const __half* qh_g = g_qh + bhof;
    const __half* ql_g = g_ql + bhof;
    const __half* kh_g = g_kh + bhof;
    const __half* vh_g = g_vh + bhof;

    const uint32_t QH = sb, QL = sb + 16384;
    const uint32_t BUF0 = sb + 32768;

    #pragma unroll
    for (int u = tid; u < 1024; u += 256) {
        int row = u >> 3, seg = u & 7;
        uint32_t so = (uint32_t)(row * 128 + ((seg ^ (row & 7)) << 4));
        size_t go = (size_t)(qb + row) * 64 + seg * 8;
        CP_ASYNC16(QH + so, qh_g + go);
        CP_ASYNC16(QL + so, ql_g + go);
    }

    auto load_kv = [&](int kj) {
        uint32_t base = BUF0 + (uint32_t)(kj & 1) * 16384u;
        #pragma unroll
        for (int u = tid; u < 512; u += 256) {
            int row = u >> 3, seg = u & 7;
            uint32_t so = (uint32_t)(row * 128 + ((seg ^ (row & 7)) << 4));
            size_t go = (size_t)(kj * 64 + row) * 64 + seg * 8;
            CP_ASYNC16(base + so,         kh_g + go);
            CP_ASYNC16(base + 8192 + so,  vh_g + go);
        }
    };
    load_kv(0);
    CP_COMMIT();

    uint32_t qfh[4][4], qfl[4][4];
    float y[8][4];
    #pragma unroll
    for (int j = 0; j < 8; j++)
        #pragma unroll
        for (int r = 0; r < 4; r++) y[j][r] = 0.0f;
    float m0 = -1e30f, m1 = -1e30f, l0 = 0.0f, l1 = 0.0f;
    bool qloaded = false;

    const int nkj = 2 * qi + 2;
    const int wr0 = qb + wid * 16;

    for (int kj = 0; kj < nkj; kj++) {
        CP_WAIT0();
        __syncthreads();
        if (kj + 1 < nkj) { load_kv(kj + 1); CP_COMMIT(); }

        if (!qloaded) {
            qloaded = true;
            #pragma unroll
            for (int kc = 0; kc < 4; kc++) {
                int row = wid * 16 + lr + (lg & 1) * 8;
                int seg = 2 * kc + (lg >> 1);
                uint32_t so = (uint32_t)(row * 128 + ((seg ^ (row & 7)) << 4));
                ldsm_x4(qfh[kc][0], qfh[kc][1], qfh[kc][2], qfh[kc][3], QH + so);
                ldsm_x4(qfl[kc][0], qfl[kc][1], qfl[kc][2], qfl[kc][3], QL + so);
            }
        }

        const int c0t = kj * 64;
        if (c0t > wr0 + 15) continue;

        const uint32_t B = BUF0 + (uint32_t)(kj & 1) * 16384u;

        // ---- S = Q K^T (2-product: qh*kh + ql*kh) ----
        float s[8][4];
        #pragma unroll
        for (int j = 0; j < 8; j++)
            #pragma unroll
            for (int r = 0; r < 4; r++) s[j][r] = 0.0f;

        #pragma unroll
        for (int kc = 0; kc < 4; kc++) {
            uint32_t kh[4][4];
            #pragma unroll
            for (int p = 0; p < 4; p++) {
                int row = p * 16 + lr + (lg >> 1) * 8;
                int seg = 2 * kc + (lg & 1);
                uint32_t so = (uint32_t)(row * 128 + ((seg ^ (row & 7)) << 4));
                ldsm_x4(kh[p][0], kh[p][1], kh[p][2], kh[p][3], B + so);
            }
            #pragma unroll
            for (int p = 0; p < 4; p++) {
                mma2(s[2*p],   qfh[kc], kh[p][0], kh[p][1]);
                mma2(s[2*p+1], qfh[kc], kh[p][2], kh[p][3]);
            }
            #pragma unroll
            for (int p = 0; p < 4; p++) {
                mma2(s[2*p],   qfl[kc], kh[p][0], kh[p][1]);
                mma2(s[2*p+1], qfl[kc], kh[p][2], kh[p][3]);
            }
        }

        // ---- causal mask ----
        if (c0t + 63 > wr0) {
            int R0 = wr0 + g, R1 = wr0 + g + 8;
            #pragma unroll
            for (int j = 0; j < 8; j++) {
                int cg = c0t + j * 8 + t2;
                if (cg     > R0) s[j][0] = -1e30f;
                if (cg + 1 > R0) s[j][1] = -1e30f;
                if (cg     > R1) s[j][2] = -1e30f;
                if (cg + 1 > R1) s[j][3] = -1e30f;
            }
        }

        // ---- online softmax (exp2 domain) ----
        float mx0 = -1e30f, mx1 = -1e30f;
        #pragma unroll
        for (int j = 0; j < 8; j++) {
            mx0 = fmaxf(mx0, fmaxf(s[j][0], s[j][1]));
            mx1 = fmaxf(mx1, fmaxf(s[j][2], s[j][3]));
        }
        mx0 = fmaxf(mx0, __shfl_xor_sync(0xffffffffu, mx0, 1));
        mx0 = fmaxf(mx0, __shfl_xor_sync(0xffffffffu, mx0, 2));
        mx1 = fmaxf(mx1, __shfl_xor_sync(0xffffffffu, mx1, 1));
        mx1 = fmaxf(mx1, __shfl_xor_sync(0xffffffffu, mx1, 2));
        float mn0 = fmaxf(m0, mx0), mn1 = fmaxf(m1, mx1);
        float a0 = exp2f(m0 - mn0), a1 = exp2f(m1 - mn1);
        m0 = mn0; m1 = mn1;

        float s0 = 0.0f, s1 = 0.0f;
        uint32_t ph[4][4];
        #pragma unroll
        for (int j = 0; j < 8; j++) {
            float p00 = exp2f(s[j][0] - mn0);
            float p01 = exp2f(s[j][1] - mn0);
            float p10 = exp2f(s[j][2] - mn1);
            float p11 = exp2f(s[j][3] - mn1);
            s0 += p00 + p01;
            s1 += p10 + p11;
            uint32_t hA, hB;
            { __half2 v = __floats2half2_rn(p00, p01); hA = *(uint32_t*)&v; }
            { __half2 v = __floats2half2_rn(p10, p11); hB = *(uint32_t*)&v; }
            int kc = j >> 1;
            if ((j & 1) == 0) { ph[kc][0] = hA; ph[kc][1] = hB; }
            else              { ph[kc][2] = hA; ph[kc][3] = hB; }
        }
        s0 += __shfl_xor_sync(0xffffffffu, s0, 1);
        s0 += __shfl_xor_sync(0xffffffffu, s0, 2);
        s1 += __shfl_xor_sync(0xffffffffu, s1, 1);
        s1 += __shfl_xor_sync(0xffffffffu, s1, 2);
        l0 = l0 * a0 + s0;
        l1 = l1 * a1 + s1;
        #pragma unroll
        for (int j = 0; j < 8; j++) {
            y[j][0] *= a0; y[j][1] *= a0;
            y[j][2] *= a1; y[j][3] *= a1;
        }

        // ---- Y += P V (1-product) ----
        #pragma unroll
        for (int kc = 0; kc < 4; kc++) {
            uint32_t vh[4][4];
            #pragma unroll
            for (int dg = 0; dg < 4; dg++) {
                int row = kc * 16 + (lg & 1) * 8 + lr;
                int seg = 2 * dg + (lg >> 1);
                uint32_t so = (uint32_t)(row * 128 + ((seg ^ (row & 7)) << 4));
                ldsm_x4t(vh[dg][0], vh[dg][1], vh[dg][2], vh[dg][3], B + 8192 + so);
            }
            #pragma unroll
            for (int dg = 0; dg < 4; dg++) {
                mma2(y[2*dg],   ph[kc], vh[dg][0], vh[dg][1]);
                mma2(y[2*dg+1], ph[kc], vh[dg][2], vh[dg][3]);
            }
        }
    }

    // ---- epilogue: normalize -> g_yh single fp16 [B,S,E] ----
    const float i0 = 1.0f / l0, i1 = 1.0f / l1;
    const int r0 = wr0 + g;
    const int r1 = r0 + 8;
    const size_t rb0 = ((size_t)(bb * SEQ + r0)) * E_DIM + hh * HD;
    const size_t rb1 = ((size_t)(bb * SEQ + r1)) * E_DIM + hh * HD;
    #pragma unroll
    for (int j = 0; j < 8; j++) {
        int col = j * 8 + t2;
        *(__half2*)(g_yh + rb0 + col) =
            __floats2half2_rn(y[j][0] * i0, y[j][1] * i0);
        *(__half2*)(g_yh + rb1 + col) =
            __floats2half2_rn(y[j][2] * i1, y[j][3] * i1);
    }
}

// ---------------------------------------------------------------------------
extern "C" void kernel_launch(void* const* d_in, const int* in_sizes, int n_in,
                              void* d_out, int out_size)
{
    const float* x      = (const float*)d_in[0];
    const float* W_attn = (const float*)d_in[1];
    const float* b_attn = (const float*)d_in[2];
    const float* W_proj = (const float*)d_in[3];
    const float* b_proj = (const float*)d_in[4];
    float* out = (float*)d_out;

    cudaFuncSetAttribute(flash_attn_mma,
                         cudaFuncAttributeMaxDynamicSharedMemorySize, ATT_SMEM);
    cudaFuncSetAttribute(gemm_mma<0, 2>,
                         cudaFuncAttributeMaxDynamicSharedMemorySize, GEMM_SMEM_MAX);
    cudaFuncSetAttribute(gemm_mma<0, 1>,
                         cudaFuncAttributeMaxDynamicSharedMemorySize, GEMM_SMEM_MAX);
    cudaFuncSetAttribute(gemm_mma<1, 1>,
                         cudaFuncAttributeMaxDynamicSharedMemorySize, GEMM_SMEM_MAX);

    __half *xh, *xl, *yh, *wah, *wph;
    cudaGetSymbolAddress((void**)&xh,  g_xh);
    cudaGetSymbolAddress((void**)&xl,  g_xl);
    cudaGetSymbolAddress((void**)&yh,  g_yh);
    cudaGetSymbolAddress((void**)&wah, g_wah);
    cudaGetSymbolAddress((void**)&wph, g_wph);

    split_scale<<<BS * E_DIM / 1024, 256>>>(x, xh, xl, 1.0f);
    {
        dim3 g(3 * E_DIM / 32, E_DIM / 32);
        wcast_t<<<g, 256>>>(W_attn, wah, 3 * E_DIM);
    }
    {
        dim3 g(E_DIM / 32, E_DIM / 32);
        wcast_t<<<g, 256>>>(W_proj, wph, E_DIM);
    }

    // 1a) q columns: 2-product
    {
        dim3 grid(E_DIM / 128, BS / 128);
        gemm_mma<0, 2><<<grid, 256, 2*24576>>>(xh, xl, wah, b_attn, nullptr, 0);
    }
    // 1b) k/v columns: 1-product
    {
        dim3 grid(2 * E_DIM / 128, BS / 128);
        gemm_mma<0, 1><<<grid, 256, 2*16384>>>(xh, xl, wah, b_attn, nullptr, 1024);
    }

    // 2) causal flash attention -> yh (single fp16)
    {
        dim3 grid(SEQ / 128, HEADS, BATCH);
        flash_attn_mma<<<grid, 256, ATT_SMEM>>>();
    }

    // 3) proj GEMM: 1-product (y already rounded to fp16)
    {
        dim3 grid(E_DIM / 128, BS / 128);
        gemm_mma<1, 1><<<grid, 256, 2*16384>>>(yh, nullptr, wph, b_proj, out, 0);
    }
}

// round 11
// speedup vs baseline: 8.6100x; 1.2815x over previous
#include <cuda_runtime.h>
#include <cuda_fp16.h>
#include <cstdint>

#define E_DIM 1024
#define HEADS 16
#define HD 64
#define BATCH 4
#define SEQ 2048
#define BS (BATCH*SEQ)   // 8192

// q scale with log2(e) folded in: softmax done in exp2 domain
#define QSCALE 0.18033688011112042f   // 0.125 * log2(e)

// ---------------- scratch (device globals: allocation-guard safe) ----------
__device__ __align__(16) __half g_qh[BATCH*HEADS*SEQ*HD];
__device__ __align__(16) __half g_kh[BATCH*HEADS*SEQ*HD];
__device__ __align__(16) __half g_vh[BATCH*HEADS*SEQ*HD];

__device__ __align__(16) __half g_xh[BS*E_DIM];
__device__ __align__(16) __half g_yh[BS*E_DIM];
__device__ __align__(16) __half g_wah[3*E_DIM*E_DIM];   // W_attn^T fp16 [3072,1024]
__device__ __align__(16) __half g_wph[E_DIM*E_DIM];     // W_proj^T fp16 [1024,1024]

// ---------------- PTX helpers (all valid at compute_103) --------------------
__device__ __forceinline__ uint32_t smem_u32(const void* p) {
    uint32_t a;
    asm("{ .reg .u64 t; cvta.to.shared.u64 t, %1; cvt.u32.u64 %0, t; }"
        : "=r"(a) : "l"(p));
    return a;
}
#define CP_ASYNC16(sa, ga) \
    asm volatile("cp.async.cg.shared.global [%0], [%1], 16;" :: "r"(sa), "l"(ga))
#define CP_COMMIT() asm volatile("cp.async.commit_group;" ::: "memory")
#define CP_WAIT0()  asm volatile("cp.async.wait_group 0;" ::: "memory")

__device__ __forceinline__ void ldsm_x4(uint32_t& r0, uint32_t& r1,
                                        uint32_t& r2, uint32_t& r3, uint32_t addr) {
    asm volatile("ldmatrix.sync.aligned.m8n8.x4.shared.b16 {%0,%1,%2,%3}, [%4];"
                 : "=r"(r0), "=r"(r1), "=r"(r2), "=r"(r3) : "r"(addr));
}
__device__ __forceinline__ void ldsm_x4t(uint32_t& r0, uint32_t& r1,
                                         uint32_t& r2, uint32_t& r3, uint32_t addr) {
    asm volatile("ldmatrix.sync.aligned.m8n8.x4.trans.shared.b16 {%0,%1,%2,%3}, [%4];"
                 : "=r"(r0), "=r"(r1), "=r"(r2), "=r"(r3) : "r"(addr));
}
__device__ __forceinline__ void mma16816(float* d, const uint32_t* a, const uint32_t* b) {
    asm volatile(
        "mma.sync.aligned.m16n8k16.row.col.f32.f16.f16.f32 "
        "{%0,%1,%2,%3}, {%4,%5,%6,%7}, {%8,%9}, {%0,%1,%2,%3};"
        : "+f"(d[0]), "+f"(d[1]), "+f"(d[2]), "+f"(d[3])
        : "r"(a[0]), "r"(a[1]), "r"(a[2]), "r"(a[3]), "r"(b[0]), "r"(b[1]));
}
__device__ __forceinline__ void mma2(float* d, const uint32_t* a, uint32_t b0, uint32_t b1) {
    asm volatile(
        "mma.sync.aligned.m16n8k16.row.col.f32.f16.f16.f32 "
        "{%0,%1,%2,%3}, {%4,%5,%6,%7}, {%8,%9}, {%0,%1,%2,%3};"
        : "+f"(d[0]), "+f"(d[1]), "+f"(d[2]), "+f"(d[3])
        : "r"(a[0]), "r"(a[1]), "r"(a[2]), "r"(a[3]), "r"(b0), "r"(b1));
}

// ---------------- prep kernels ---------------------------------------------
__global__ __launch_bounds__(256)
void cast_f16(const float* __restrict__ src, __half* __restrict__ dst)
{
    int i = (blockIdx.x * 256 + threadIdx.x) * 4;
    float4 v = *(const float4*)(src + i);
    *(__half2*)(dst + i)     = __floats2half2_rn(v.x, v.y);
    *(__half2*)(dst + i + 2) = __floats2half2_rn(v.z, v.w);
}

// W [1024, N] row-major -> Wt fp16 [N, 1024]
__global__ __launch_bounds__(256)
void wcast_t(const float* __restrict__ W, __half* __restrict__ Wh, int N)
{
    __shared__ float tile[32][33];
    int c0 = blockIdx.x * 32;
    int r0 = blockIdx.y * 32;
    int tx = threadIdx.x & 31, ty = threadIdx.x >> 5;
    #pragma unroll
    for (int i = ty; i < 32; i += 8)
        tile[i][tx] = W[(size_t)(r0 + i) * N + c0 + tx];
    __syncthreads();
    #pragma unroll
    for (int i = ty; i < 32; i += 8)
        Wh[(size_t)(c0 + i) * 1024 + r0 + tx] = __float2half_rn(tile[tx][i]);
}

// ---------------- HMMA GEMM (fp16 1-product) --------------------------------
// MODE 0: epilogue -> q (QSCALE) / k / v fp16 in [B,H,S,D]
// MODE 1: epilogue -> out fp32 [8192,1024]
#define GEMM_BUFB 16384u
#define GEMM_SMEM (2*16384)

template<int MODE>
__global__ __launch_bounds__(256, 2)
void gemm_mma(const __half* __restrict__ Ah, const __half* __restrict__ Bh,
              const float* __restrict__ bias, float* __restrict__ out)
{
    extern __shared__ char smem[];
    const uint32_t sb = smem_u32(smem);
    const int tid  = threadIdx.x;
    const int wid  = tid >> 5;
    const int lane = tid & 31;
    const int m0 = blockIdx.y * 128;
    const int n0 = blockIdx.x * 128;

    const int wm = wid & 1;
    const int wn = wid >> 1;
    const int lr = lane & 7;
    const int lg = lane >> 3;

    float acc[4][4][4];
    #pragma unroll
    for (int i = 0; i < 4; i++)
        #pragma unroll
        for (int j = 0; j < 4; j++)
            #pragma unroll
            for (int r = 0; r < 4; r++) acc[i][j][r] = 0.0f;

    auto load_chunk = [&](int c) {
        const int k0 = c * 32;
        const uint32_t sbase = sb + (uint32_t)(c & 1) * GEMM_BUFB;
        #pragma unroll
        for (int t = 0; t < 2; t++) {
            int u = tid + t * 256;
            int r = u >> 2, seg = u & 3;
            uint32_t soff = (uint32_t)(r * 64 + ((seg ^ ((r >> 1) & 3)) << 4));
            size_t ga = (size_t)(m0 + r) * 1024 + k0 + seg * 8;
            size_t gb = (size_t)(n0 + r) * 1024 + k0 + seg * 8;
            CP_ASYNC16(sbase + soff,        Ah + ga);
            CP_ASYNC16(sbase + 8192 + soff, Bh + gb);
        }
        CP_COMMIT();
    };

    load_chunk(0);

    for (int c = 0; c < 32; c++) {
        CP_WAIT0();
        __syncthreads();
        if (c + 1 < 32) load_chunk(c + 1);

        const uint32_t sbase = sb + (uint32_t)(c & 1) * GEMM_BUFB;
        #pragma unroll
        for (int s = 0; s < 2; s++) {
            uint32_t ah[4][4], bh[4][2];
            #pragma unroll
            for (int i = 0; i < 4; i++) {
                int row = wm * 64 + i * 16 + lr + (lg & 1) * 8;
                int seg = 2 * s + (lg >> 1);
                uint32_t ad = sbase + (uint32_t)(row * 64 +
                              ((seg ^ ((row >> 1) & 3)) << 4));
                ldsm_x4(ah[i][0], ah[i][1], ah[i][2], ah[i][3], ad);
            }
            #pragma unroll
            for (int p = 0; p < 2; p++) {
                int row = wn * 32 + p * 16 + lr + (lg >> 1) * 8;
                int seg = 2 * s + (lg & 1);
                uint32_t bd = sbase + 8192u + (uint32_t)(row * 64 +
                              ((seg ^ ((row >> 1) & 3)) << 4));
                uint32_t r0, r1, r2, r3;
                ldsm_x4(r0, r1, r2, r3, bd);
                bh[2*p][0] = r0; bh[2*p][1] = r1;
                bh[2*p+1][0] = r2; bh[2*p+1][1] = r3;
            }
            #pragma unroll
            for (int i = 0; i < 4; i++)
                #pragma unroll
                for (int j = 0; j < 4; j++)
                    mma16816(acc[i][j], ah[i], bh[j]);
        }
    }

    const int mrow = m0 + wm * 64 + (lane >> 2);
    const int ncol = n0 + wn * 32 + (lane & 3) * 2;
    #pragma unroll
    for (int i = 0; i < 4; i++) {
        #pragma unroll
        for (int j = 0; j < 4; j++) {
            int m = mrow + i * 16;
            int n = ncol + j * 8;
            float b0 = __ldg(&bias[n]), b1 = __ldg(&bias[n + 1]);
            float f0 = acc[i][j][0] + b0, f1 = acc[i][j][1] + b1;
            float f2 = acc[i][j][2] + b0, f3 = acc[i][j][3] + b1;
            if (MODE == 0) {
                int sec = n >> 10;
                int e   = n & 1023;
                int hh  = e >> 6;
                int d   = e & 63;
                int b_ = m >> 11, s_ = m & 2047;
                size_t o0 = ((size_t)((b_ * HEADS + hh) * SEQ) + s_) * HD + d;
                size_t o1 = o0 + 8 * HD;
                __half* dst;
                if (sec == 0) {
                    dst = g_qh;
                    f0 *= QSCALE; f1 *= QSCALE; f2 *= QSCALE; f3 *= QSCALE;
                } else {
                    dst = (sec == 1) ? g_kh : g_vh;
                }
                *(__half2*)(dst + o0) = __floats2half2_rn(f0, f1);
                *(__half2*)(dst + o1) = __floats2half2_rn(f2, f3);
            } else {
                *(float2*)(out + (size_t)m * 1024 + n) = {f0, f1};
                *(float2*)(out + (size_t)(m + 8) * 1024 + n) = {f2, f3};
            }
        }
    }
}

// ---------------- HMMA flash attention (all 1-product fp16) -----------------
// smem: Qh(16K) + 2 x [Kh(8K) Vh(8K)] = 48K
#define ATT_SMEM (16384 + 2*16384)   // 49152

__global__ __launch_bounds__(256, 2)
void flash_attn_mma()
{
    extern __shared__ char smc[];
    const uint32_t sb = smem_u32(smc);
    const int tid  = threadIdx.x;
    const int wid  = tid >> 5;       // 0..7
    const int lane = tid & 31;
    const int lr = lane & 7;
    const int lg = lane >> 3;
    const int g  = lane >> 2;
    const int t2 = (lane & 3) * 2;

    const int qi = (int)gridDim.x - 1 - (int)blockIdx.x;
    const int qb = qi * 128;
    const int hh = blockIdx.y;
    const int bb = blockIdx.z;
    const size_t bhof = ((size_t)(bb * HEADS + hh)) * SEQ * HD;

    const __half* qh_g = g_qh + bhof;
    const __half* kh_g = g_kh + bhof;
    const __half* vh_g = g_vh + bhof;

    const uint32_t QH = sb;
    const uint32_t BUF0 = sb + 16384;

    #pragma unroll
    for (int u = tid; u < 1024; u += 256) {
        int row = u >> 3, seg = u & 7;
        uint32_t so = (uint32_t)(row * 128 + ((seg ^ (row & 7)) << 4));
        size_t go = (size_t)(qb + row) * 64 + seg * 8;
        CP_ASYNC16(QH + so, qh_g + go);
    }

    auto load_kv = [&](int kj) {
        uint32_t base = BUF0 + (uint32_t)(kj & 1) * 16384u;
        #pragma unroll
        for (int u = tid; u < 512; u += 256) {
            int row = u >> 3, seg = u & 7;
            uint32_t so = (uint32_t)(row * 128 + ((seg ^ (row & 7)) << 4));
            size_t go = (size_t)(kj * 64 + row) * 64 + seg * 8;
            CP_ASYNC16(base + so,         kh_g + go);
            CP_ASYNC16(base + 8192 + so,  vh_g + go);
        }
    };
    load_kv(0);
    CP_COMMIT();

    uint32_t qfh[4][4];
    float y[8][4];
    #pragma unroll
    for (int j = 0; j < 8; j++)
        #pragma unroll
        for (int r = 0; r < 4; r++) y[j][r] = 0.0f;
    float m0 = -1e30f, m1 = -1e30f, l0 = 0.0f, l1 = 0.0f;
    bool qloaded = false;

    const int nkj = 2 * qi + 2;
    const int wr0 = qb + wid * 16;

    for (int kj = 0; kj < nkj; kj++) {
        CP_WAIT0();
        __syncthreads();
        if (kj + 1 < nkj) { load_kv(kj + 1); CP_COMMIT(); }

        if (!qloaded) {
            qloaded = true;
            #pragma unroll
            for (int kc = 0; kc < 4; kc++) {
                int row = wid * 16 + lr + (lg & 1) * 8;
                int seg = 2 * kc + (lg >> 1);
                uint32_t so = (uint32_t)(row * 128 + ((seg ^ (row & 7)) << 4));
                ldsm_x4(qfh[kc][0], qfh[kc][1], qfh[kc][2], qfh[kc][3], QH + so);
            }
        }

        const int c0t = kj * 64;
        if (c0t > wr0 + 15) continue;

        const uint32_t B = BUF0 + (uint32_t)(kj & 1) * 16384u;

        // ---- S = Q K^T (1-product) ----
        float s[8][4];
        #pragma unroll
        for (int j = 0; j < 8; j++)
            #pragma unroll
            for (int r = 0; r < 4; r++) s[j][r] = 0.0f;

        #pragma unroll
        for (int kc = 0; kc < 4; kc++) {
            uint32_t kh[4][4];
            #pragma unroll
            for (int p = 0; p < 4; p++) {
                int row = p * 16 + lr + (lg >> 1) * 8;
                int seg = 2 * kc + (lg & 1);
                uint32_t so = (uint32_t)(row * 128 + ((seg ^ (row & 7)) << 4));
                ldsm_x4(kh[p][0], kh[p][1], kh[p][2], kh[p][3], B + so);
            }
            #pragma unroll
            for (int p = 0; p < 4; p++) {
                mma2(s[2*p],   qfh[kc], kh[p][0], kh[p][1]);
                mma2(s[2*p+1], qfh[kc], kh[p][2], kh[p][3]);
            }
        }

        // ---- causal mask ----
        if (c0t + 63 > wr0) {
            int R0 = wr0 + g, R1 = wr0 + g + 8;
            #pragma unroll
            for (int j = 0; j < 8; j++) {
                int cg = c0t + j * 8 + t2;
                if (cg     > R0) s[j][0] = -1e30f;
                if (cg + 1 > R0) s[j][1] = -1e30f;
                if (cg     > R1) s[j][2] = -1e30f;
                if (cg + 1 > R1) s[j][3] = -1e30f;
            }
        }

        // ---- online softmax (exp2 domain) ----
        float mx0 = -1e30f, mx1 = -1e30f;
        #pragma unroll
        for (int j = 0; j < 8; j++) {
            mx0 = fmaxf(mx0, fmaxf(s[j][0], s[j][1]));
            mx1 = fmaxf(mx1, fmaxf(s[j][2], s[j][3]));
        }
        mx0 = fmaxf(mx0, __shfl_xor_sync(0xffffffffu, mx0, 1));
        mx0 = fmaxf(mx0, __shfl_xor_sync(0xffffffffu, mx0, 2));
        mx1 = fmaxf(mx1, __shfl_xor_sync(0xffffffffu, mx1, 1));
        mx1 = fmaxf(mx1, __shfl_xor_sync(0xffffffffu, mx1, 2));
        float mn0 = fmaxf(m0, mx0), mn1 = fmaxf(m1, mx1);
        float a0 = exp2f(m0 - mn0), a1 = exp2f(m1 - mn1);
        m0 = mn0; m1 = mn1;

        float s0 = 0.0f, s1 = 0.0f;
        uint32_t ph[4][4];
        #pragma unroll
        for (int j = 0; j < 8; j++) {
            float p00 = exp2f(s[j][0] - mn0);
            float p01 = exp2f(s[j][1] - mn0);
            float p10 = exp2f(s[j][2] - mn1);
            float p11 = exp2f(s[j][3] - mn1);
            s0 += p00 + p01;
            s1 += p10 + p11;
            uint32_t hA, hB;
            { __half2 v = __floats2half2_rn(p00, p01); hA = *(uint32_t*)&v; }
            { __half2 v = __floats2half2_rn(p10, p11); hB = *(uint32_t*)&v; }
            int kc = j >> 1;
            if ((j & 1) == 0) { ph[kc][0] = hA; ph[kc][1] = hB; }
            else              { ph[kc][2] = hA; ph[kc][3] = hB; }
        }
        s0 += __shfl_xor_sync(0xffffffffu, s0, 1);
        s0 += __shfl_xor_sync(0xffffffffu, s0, 2);
        s1 += __shfl_xor_sync(0xffffffffu, s1, 1);
        s1 += __shfl_xor_sync(0xffffffffu, s1, 2);
        l0 = l0 * a0 + s0;
        l1 = l1 * a1 + s1;
        #pragma unroll
        for (int j = 0; j < 8; j++) {
            y[j][0] *= a0; y[j][1] *= a0;
            y[j][2] *= a1; y[j][3] *= a1;
        }

        // ---- Y += P V (1-product) ----
        #pragma unroll
        for (int kc = 0; kc < 4; kc++) {
            uint32_t vh[4][4];
            #pragma unroll
            for (int dg = 0; dg < 4; dg++) {
                int row = kc * 16 + (lg & 1) * 8 + lr;
                int seg = 2 * dg + (lg >> 1);
                uint32_t so = (uint32_t)(row * 128 + ((seg ^ (row & 7)) << 4));
                ldsm_x4t(vh[dg][0], vh[dg][1], vh[dg][2], vh[dg][3], B + 8192 + so);
            }
            #pragma unroll
            for (int dg = 0; dg < 4; dg++) {
                mma2(y[2*dg],   ph[kc], vh[dg][0], vh[dg][1]);
                mma2(y[2*dg+1], ph[kc], vh[dg][2], vh[dg][3]);
            }
        }
    }

    // ---- epilogue: normalize -> g_yh single fp16 [B,S,E] ----
    const float i0 = 1.0f / l0, i1 = 1.0f / l1;
    const int r0 = wr0 + g;
    const int r1 = r0 + 8;
    const size_t rb0 = ((size_t)(bb * SEQ + r0)) * E_DIM + hh * HD;
    const size_t rb1 = ((size_t)(bb * SEQ + r1)) * E_DIM + hh * HD;
    #pragma unroll
    for (int j = 0; j < 8; j++) {
        int col = j * 8 + t2;
        *(__half2*)(g_yh + rb0 + col) =
            __floats2half2_rn(y[j][0] * i0, y[j][1] * i0);
        *(__half2*)(g_yh + rb1 + col) =
            __floats2half2_rn(y[j][2] * i1, y[j][3] * i1);
    }
}

// ---------------------------------------------------------------------------
extern "C" void kernel_launch(void* const* d_in, const int* in_sizes, int n_in,
                              void* d_out, int out_size)
{
    const float* x      = (const float*)d_in[0];
    const float* W_attn = (const float*)d_in[1];
    const float* b_attn = (const float*)d_in[2];
    const float* W_proj = (const float*)d_in[3];
    const float* b_proj = (const float*)d_in[4];
    float* out = (float*)d_out;

    cudaFuncSetAttribute(flash_attn_mma,
                         cudaFuncAttributeMaxDynamicSharedMemorySize, ATT_SMEM);
    cudaFuncSetAttribute(gemm_mma<0>,
                         cudaFuncAttributeMaxDynamicSharedMemorySize, GEMM_SMEM);
    cudaFuncSetAttribute(gemm_mma<1>,
                         cudaFuncAttributeMaxDynamicSharedMemorySize, GEMM_SMEM);

    __half *xh, *yh, *wah, *wph;
    cudaGetSymbolAddress((void**)&xh,  g_xh);
    cudaGetSymbolAddress((void**)&yh,  g_yh);
    cudaGetSymbolAddress((void**)&wah, g_wah);
    cudaGetSymbolAddress((void**)&wph, g_wph);

    cast_f16<<<BS * E_DIM / 1024, 256>>>(x, xh);
    {
        dim3 g(3 * E_DIM / 32, E_DIM / 32);
        wcast_t<<<g, 256>>>(W_attn, wah, 3 * E_DIM);
    }
    {
        dim3 g(E_DIM / 32, E_DIM / 32);
        wcast_t<<<g, 256>>>(W_proj, wph, E_DIM);
    }

    // 1) QKV GEMM (single 1-product launch) -> q(QSCALE)/k/v fp16 [B,H,S,D]
    {
        dim3 grid(3 * E_DIM / 128, BS / 128);   // 24 x 64
        gemm_mma<0><<<grid, 256, GEMM_SMEM>>>(xh, wah, b_attn, nullptr);
    }

    // 2) causal flash attention -> yh fp16
    {
        dim3 grid(SEQ / 128, HEADS, BATCH);
        flash_attn_mma<<<grid, 256, ATT_SMEM>>>();
    }

    // 3) proj GEMM (1-product) -> out
    {
        dim3 grid(E_DIM / 128, BS / 128);
        gemm_mma<1><<<grid, 256, GEMM_SMEM>>>(yh, wph, b_proj, out);
    }
}

// round 12
// speedup vs baseline: 8.9391x; 1.0382x over previous
#include <cuda_runtime.h>
#include <cuda_fp16.h>
#include <cstdint>

#define E_DIM 1024
#define HEADS 16
#define HD 64
#define BATCH 4
#define SEQ 2048
#define BS (BATCH*SEQ)   // 8192

// q scale with log2(e) folded in: softmax done in exp2 domain
#define QSCALE 0.18033688011112042f   // 0.125 * log2(e)

// ---------------- scratch (device globals: allocation-guard safe) ----------
__device__ __align__(16) __half g_qh[BATCH*HEADS*SEQ*HD];
__device__ __align__(16) __half g_kh[BATCH*HEADS*SEQ*HD];
__device__ __align__(16) __half g_vh[BATCH*HEADS*SEQ*HD];

__device__ __align__(16) __half g_xh[BS*E_DIM];
__device__ __align__(16) __half g_yh[BS*E_DIM];
__device__ __align__(16) __half g_wah[3*E_DIM*E_DIM];   // W_attn^T fp16 [3072,1024]
__device__ __align__(16) __half g_wph[E_DIM*E_DIM];     // W_proj^T fp16 [1024,1024]

// ---------------- PTX helpers (all valid at compute_103) --------------------
__device__ __forceinline__ uint32_t smem_u32(const void* p) {
    uint32_t a;
    asm("{ .reg .u64 t; cvta.to.shared.u64 t, %1; cvt.u32.u64 %0, t; }"
        : "=r"(a) : "l"(p));
    return a;
}
#define CP_ASYNC16(sa, ga) \
    asm volatile("cp.async.cg.shared.global [%0], [%1], 16;" :: "r"(sa), "l"(ga))
#define CP_COMMIT() asm volatile("cp.async.commit_group;" ::: "memory")
#define CP_WAIT0()  asm volatile("cp.async.wait_group 0;" ::: "memory")

__device__ __forceinline__ void ldsm_x4(uint32_t& r0, uint32_t& r1,
                                        uint32_t& r2, uint32_t& r3, uint32_t addr) {
    asm volatile("ldmatrix.sync.aligned.m8n8.x4.shared.b16 {%0,%1,%2,%3}, [%4];"
                 : "=r"(r0), "=r"(r1), "=r"(r2), "=r"(r3) : "r"(addr));
}
__device__ __forceinline__ void ldsm_x4t(uint32_t& r0, uint32_t& r1,
                                         uint32_t& r2, uint32_t& r3, uint32_t addr) {
    asm volatile("ldmatrix.sync.aligned.m8n8.x4.trans.shared.b16 {%0,%1,%2,%3}, [%4];"
                 : "=r"(r0), "=r"(r1), "=r"(r2), "=r"(r3) : "r"(addr));
}
__device__ __forceinline__ void mma16816(float* d, const uint32_t* a, const uint32_t* b) {
    asm volatile(
        "mma.sync.aligned.m16n8k16.row.col.f32.f16.f16.f32 "
        "{%0,%1,%2,%3}, {%4,%5,%6,%7}, {%8,%9}, {%0,%1,%2,%3};"
        : "+f"(d[0]), "+f"(d[1]), "+f"(d[2]), "+f"(d[3])
        : "r"(a[0]), "r"(a[1]), "r"(a[2]), "r"(a[3]), "r"(b[0]), "r"(b[1]));
}
__device__ __forceinline__ void mma2(float* d, const uint32_t* a, uint32_t b0, uint32_t b1) {
    asm volatile(
        "mma.sync.aligned.m16n8k16.row.col.f32.f16.f16.f32 "
        "{%0,%1,%2,%3}, {%4,%5,%6,%7}, {%8,%9}, {%0,%1,%2,%3};"
        : "+f"(d[0]), "+f"(d[1]), "+f"(d[2]), "+f"(d[3])
        : "r"(a[0]), "r"(a[1]), "r"(a[2]), "r"(a[3]), "r"(b0), "r"(b1));
}

// ---------------- prep kernels ---------------------------------------------
__global__ __launch_bounds__(256)
void cast_f16(const float* __restrict__ src, __half* __restrict__ dst)
{
    int i = (blockIdx.x * 256 + threadIdx.x) * 4;
    float4 v = *(const float4*)(src + i);
    *(__half2*)(dst + i)     = __floats2half2_rn(v.x, v.y);
    *(__half2*)(dst + i + 2) = __floats2half2_rn(v.z, v.w);
}

// W [1024, N] row-major -> Wt fp16 [N, 1024]
__global__ __launch_bounds__(256)
void wcast_t(const float* __restrict__ W, __half* __restrict__ Wh, int N)
{
    __shared__ float tile[32][33];
    int c0 = blockIdx.x * 32;
    int r0 = blockIdx.y * 32;
    int tx = threadIdx.x & 31, ty = threadIdx.x >> 5;
    #pragma unroll
    for (int i = ty; i < 32; i += 8)
        tile[i][tx] = W[(size_t)(r0 + i) * N + c0 + tx];
    __syncthreads();
    #pragma unroll
    for (int i = ty; i < 32; i += 8)
        Wh[(size_t)(c0 + i) * 1024 + r0 + tx] = __float2half_rn(tile[tx][i]);
}

// ---------------- HMMA GEMM (fp16 1-product, K-chunk 64) --------------------
// MODE 0: epilogue -> q (QSCALE) / k / v fp16 in [B,H,S,D]
// MODE 1: epilogue -> out fp32 [8192,1024]
// Buffer: A(16K) + B(16K), rows 128B wide, swizzle seg ^= row&7. Double-buffered.
#define GEMM_BUFB 32768u
#define GEMM_SMEM (2*32768)

template<int MODE>
__global__ __launch_bounds__(256, 2)
void gemm_mma(const __half* __restrict__ Ah, const __half* __restrict__ Bh,
              const float* __restrict__ bias, float* __restrict__ out)
{
    extern __shared__ char smem[];
    const uint32_t sb = smem_u32(smem);
    const int tid  = threadIdx.x;
    const int wid  = tid >> 5;
    const int lane = tid & 31;
    const int m0 = blockIdx.y * 128;
    const int n0 = blockIdx.x * 128;

    const int wm = wid & 1;
    const int wn = wid >> 1;
    const int lr = lane & 7;
    const int lg = lane >> 3;

    float acc[4][4][4];
    #pragma unroll
    for (int i = 0; i < 4; i++)
        #pragma unroll
        for (int j = 0; j < 4; j++)
            #pragma unroll
            for (int r = 0; r < 4; r++) acc[i][j][r] = 0.0f;

    auto load_chunk = [&](int c) {
        const int k0 = c * 64;
        const uint32_t sbase = sb + (uint32_t)(c & 1) * GEMM_BUFB;
        #pragma unroll
        for (int t = 0; t < 4; t++) {
            int u = tid + t * 256;
            int r = u >> 3, seg = u & 7;
            uint32_t soff = (uint32_t)(r * 128 + ((seg ^ (r & 7)) << 4));
            size_t ga = (size_t)(m0 + r) * 1024 + k0 + seg * 8;
            size_t gb = (size_t)(n0 + r) * 1024 + k0 + seg * 8;
            CP_ASYNC16(sbase + soff,         Ah + ga);
            CP_ASYNC16(sbase + 16384 + soff, Bh + gb);
        }
        CP_COMMIT();
    };

    load_chunk(0);

    for (int c = 0; c < 16; c++) {
        CP_WAIT0();
        __syncthreads();
        if (c + 1 < 16) load_chunk(c + 1);

        const uint32_t sbase = sb + (uint32_t)(c & 1) * GEMM_BUFB;
        #pragma unroll
        for (int s = 0; s < 4; s++) {
            uint32_t ah[4][4], bh[4][2];
            #pragma unroll
            for (int i = 0; i < 4; i++) {
                int row = wm * 64 + i * 16 + lr + (lg & 1) * 8;
                int seg = 2 * s + (lg >> 1);
                uint32_t ad = sbase + (uint32_t)(row * 128 +
                              ((seg ^ (row & 7)) << 4));
                ldsm_x4(ah[i][0], ah[i][1], ah[i][2], ah[i][3], ad);
            }
            #pragma unroll
            for (int p = 0; p < 2; p++) {
                int row = wn * 32 + p * 16 + lr + (lg >> 1) * 8;
                int seg = 2 * s + (lg & 1);
                uint32_t bd = sbase + 16384u + (uint32_t)(row * 128 +
                              ((seg ^ (row & 7)) << 4));
                uint32_t r0, r1, r2, r3;
                ldsm_x4(r0, r1, r2, r3, bd);
                bh[2*p][0] = r0; bh[2*p][1] = r1;
                bh[2*p+1][0] = r2; bh[2*p+1][1] = r3;
            }
            #pragma unroll
            for (int i = 0; i < 4; i++)
                #pragma unroll
                for (int j = 0; j < 4; j++)
                    mma16816(acc[i][j], ah[i], bh[j]);
        }
    }

    const int mrow = m0 + wm * 64 + (lane >> 2);
    const int ncol = n0 + wn * 32 + (lane & 3) * 2;
    #pragma unroll
    for (int i = 0; i < 4; i++) {
        #pragma unroll
        for (int j = 0; j < 4; j++) {
            int m = mrow + i * 16;
            int n = ncol + j * 8;
            float b0 = __ldg(&bias[n]), b1 = __ldg(&bias[n + 1]);
            float f0 = acc[i][j][0] + b0, f1 = acc[i][j][1] + b1;
            float f2 = acc[i][j][2] + b0, f3 = acc[i][j][3] + b1;
            if (MODE == 0) {
                int sec = n >> 10;
                int e   = n & 1023;
                int hh  = e >> 6;
                int d   = e & 63;
                int b_ = m >> 11, s_ = m & 2047;
                size_t o0 = ((size_t)((b_ * HEADS + hh) * SEQ) + s_) * HD + d;
                size_t o1 = o0 + 8 * HD;
                __half* dst;
                if (sec == 0) {
                    dst = g_qh;
                    f0 *= QSCALE; f1 *= QSCALE; f2 *= QSCALE; f3 *= QSCALE;
                } else {
                    dst = (sec == 1) ? g_kh : g_vh;
                }
                *(__half2*)(dst + o0) = __floats2half2_rn(f0, f1);
                *(__half2*)(dst + o1) = __floats2half2_rn(f2, f3);
            } else {
                *(float2*)(out + (size_t)m * 1024 + n) = {f0, f1};
                *(float2*)(out + (size_t)(m + 8) * 1024 + n) = {f2, f3};
            }
        }
    }
}

// ---------------- HMMA flash attention (all 1-product fp16) -----------------
// smem: Qh(16K) + 2 x [Kh(8K) Vh(8K)] = 48K
#define ATT_SMEM (16384 + 2*16384)   // 49152

__global__ __launch_bounds__(256, 2)
void flash_attn_mma()
{
    extern __shared__ char smc[];
    const uint32_t sb = smem_u32(smc);
    const int tid  = threadIdx.x;
    const int wid  = tid >> 5;       // 0..7
    const int lane = tid & 31;
    const int lr = lane & 7;
    const int lg = lane >> 3;
    const int g  = lane >> 2;
    const int t2 = (lane & 3) * 2;

    const int qi = (int)gridDim.x - 1 - (int)blockIdx.x;
    const int qb = qi * 128;
    const int hh = blockIdx.y;
    const int bb = blockIdx.z;
    const size_t bhof = ((size_t)(bb * HEADS + hh)) * SEQ * HD;

    const __half* qh_g = g_qh + bhof;
    const __half* kh_g = g_kh + bhof;
    const __half* vh_g = g_vh + bhof;

    const uint32_t QH = sb;
    const uint32_t BUF0 = sb + 16384;

    #pragma unroll
    for (int u = tid; u < 1024; u += 256) {
        int row = u >> 3, seg = u & 7;
        uint32_t so = (uint32_t)(row * 128 + ((seg ^ (row & 7)) << 4));
        size_t go = (size_t)(qb + row) * 64 + seg * 8;
        CP_ASYNC16(QH + so, qh_g + go);
    }

    auto load_kv = [&](int kj) {
        uint32_t base = BUF0 + (uint32_t)(kj & 1) * 16384u;
        #pragma unroll
        for (int u = tid; u < 512; u += 256) {
            int row = u >> 3, seg = u & 7;
            uint32_t so = (uint32_t)(row * 128 + ((seg ^ (row & 7)) << 4));
            size_t go = (size_t)(kj * 64 + row) * 64 + seg * 8;
            CP_ASYNC16(base + so,         kh_g + go);
            CP_ASYNC16(base + 8192 + so,  vh_g + go);
        }
    };
    load_kv(0);
    CP_COMMIT();

    uint32_t qfh[4][4];
    float y[8][4];
    #pragma unroll
    for (int j = 0; j < 8; j++)
        #pragma unroll
        for (int r = 0; r < 4; r++) y[j][r] = 0.0f;
    float m0 = -1e30f, m1 = -1e30f, l0 = 0.0f, l1 = 0.0f;
    bool qloaded = false;

    const int nkj = 2 * qi + 2;
    const int wr0 = qb + wid * 16;

    for (int kj = 0; kj < nkj; kj++) {
        CP_WAIT0();
        __syncthreads();
        if (kj + 1 < nkj) { load_kv(kj + 1); CP_COMMIT(); }

        if (!qloaded) {
            qloaded = true;
            #pragma unroll
            for (int kc = 0; kc < 4; kc++) {
                int row = wid * 16 + lr + (lg & 1) * 8;
                int seg = 2 * kc + (lg >> 1);
                uint32_t so = (uint32_t)(row * 128 + ((seg ^ (row & 7)) << 4));
                ldsm_x4(qfh[kc][0], qfh[kc][1], qfh[kc][2], qfh[kc][3], QH + so);
            }
        }

        const int c0t = kj * 64;
        if (c0t > wr0 + 15) continue;

        const uint32_t B = BUF0 + (uint32_t)(kj & 1) * 16384u;

        // ---- S = Q K^T (1-product) ----
        float s[8][4];
        #pragma unroll
        for (int j = 0; j < 8; j++)
            #pragma unroll
            for (int r = 0; r < 4; r++) s[j][r] = 0.0f;

        #pragma unroll
        for (int kc = 0; kc < 4; kc++) {
            uint32_t kh[4][4];
            #pragma unroll
            for (int p = 0; p < 4; p++) {
                int row = p * 16 + lr + (lg >> 1) * 8;
                int seg = 2 * kc + (lg & 1);
                uint32_t so = (uint32_t)(row * 128 + ((seg ^ (row & 7)) << 4));
                ldsm_x4(kh[p][0], kh[p][1], kh[p][2], kh[p][3], B + so);
            }
            #pragma unroll
            for (int p = 0; p < 4; p++) {
                mma2(s[2*p],   qfh[kc], kh[p][0], kh[p][1]);
                mma2(s[2*p+1], qfh[kc], kh[p][2], kh[p][3]);
            }
        }

        // ---- causal mask ----
        if (c0t + 63 > wr0) {
            int R0 = wr0 + g, R1 = wr0 + g + 8;
            #pragma unroll
            for (int j = 0; j < 8; j++) {
                int cg = c0t + j * 8 + t2;
                if (cg     > R0) s[j][0] = -1e30f;
                if (cg + 1 > R0) s[j][1] = -1e30f;
                if (cg     > R1) s[j][2] = -1e30f;
                if (cg + 1 > R1) s[j][3] = -1e30f;
            }
        }

        // ---- online softmax (exp2 domain) ----
        float mx0 = -1e30f, mx1 = -1e30f;
        #pragma unroll
        for (int j = 0; j < 8; j++) {
            mx0 = fmaxf(mx0, fmaxf(s[j][0], s[j][1]));
            mx1 = fmaxf(mx1, fmaxf(s[j][2], s[j][3]));
        }
        mx0 = fmaxf(mx0, __shfl_xor_sync(0xffffffffu, mx0, 1));
        mx0 = fmaxf(mx0, __shfl_xor_sync(0xffffffffu, mx0, 2));
        mx1 = fmaxf(mx1, __shfl_xor_sync(0xffffffffu, mx1, 1));
        mx1 = fmaxf(mx1, __shfl_xor_sync(0xffffffffu, mx1, 2));
        float mn0 = fmaxf(m0, mx0), mn1 = fmaxf(m1, mx1);
        float a0 = exp2f(m0 - mn0), a1 = exp2f(m1 - mn1);
        m0 = mn0; m1 = mn1;

        float s0 = 0.0f, s1 = 0.0f;
        uint32_t ph[4][4];
        #pragma unroll
        for (int j = 0; j < 8; j++) {
            float p00 = exp2f(s[j][0] - mn0);
            float p01 = exp2f(s[j][1] - mn0);
            float p10 = exp2f(s[j][2] - mn1);
            float p11 = exp2f(s[j][3] - mn1);
            s0 += p00 + p01;
            s1 += p10 + p11;
            uint32_t hA, hB;
            { __half2 v = __floats2half2_rn(p00, p01); hA = *(uint32_t*)&v; }
            { __half2 v = __floats2half2_rn(p10, p11); hB = *(uint32_t*)&v; }
            int kc = j >> 1;
            if ((j & 1) == 0) { ph[kc][0] = hA; ph[kc][1] = hB; }
            else              { ph[kc][2] = hA; ph[kc][3] = hB; }
        }
        s0 += __shfl_xor_sync(0xffffffffu, s0, 1);
        s0 += __shfl_xor_sync(0xffffffffu, s0, 2);
        s1 += __shfl_xor_sync(0xffffffffu, s1, 1);
        s1 += __shfl_xor_sync(0xffffffffu, s1, 2);
        l0 = l0 * a0 + s0;
        l1 = l1 * a1 + s1;
        #pragma unroll
        for (int j = 0; j < 8; j++) {
            y[j][0] *= a0; y[j][1] *= a0;
            y[j][2] *= a1; y[j][3] *= a1;
        }

        // ---- Y += P V (1-product) ----
        #pragma unroll
        for (int kc = 0; kc < 4; kc++) {
            uint32_t vh[4][4];
            #pragma unroll
            for (int dg = 0; dg < 4; dg++) {
                int row = kc * 16 + (lg & 1) * 8 + lr;
                int seg = 2 * dg + (lg >> 1);
                uint32_t so = (uint32_t)(row * 128 + ((seg ^ (row & 7)) << 4));
                ldsm_x4t(vh[dg][0], vh[dg][1], vh[dg][2], vh[dg][3], B + 8192 + so);
            }
            #pragma unroll
            for (int dg = 0; dg < 4; dg++) {
                mma2(y[2*dg],   ph[kc], vh[dg][0], vh[dg][1]);
                mma2(y[2*dg+1], ph[kc], vh[dg][2], vh[dg][3]);
            }
        }
    }

    // ---- epilogue: normalize -> g_yh single fp16 [B,S,E] ----
    const float i0 = 1.0f / l0, i1 = 1.0f / l1;
    const int r0 = wr0 + g;
    const int r1 = r0 + 8;
    const size_t rb0 = ((size_t)(bb * SEQ + r0)) * E_DIM + hh * HD;
    const size_t rb1 = ((size_t)(bb * SEQ + r1)) * E_DIM + hh * HD;
    #pragma unroll
    for (int j = 0; j < 8; j++) {
        int col = j * 8 + t2;
        *(__half2*)(g_yh + rb0 + col) =
            __floats2half2_rn(y[j][0] * i0, y[j][1] * i0);
        *(__half2*)(g_yh + rb1 + col) =
            __floats2half2_rn(y[j][2] * i1, y[j][3] * i1);
    }
}

// ---------------------------------------------------------------------------
extern "C" void kernel_launch(void* const* d_in, const int* in_sizes, int n_in,
                              void* d_out, int out_size)
{
    const float* x      = (const float*)d_in[0];
    const float* W_attn = (const float*)d_in[1];
    const float* b_attn = (const float*)d_in[2];
    const float* W_proj = (const float*)d_in[3];
    const float* b_proj = (const float*)d_in[4];
    float* out = (float*)d_out;

    cudaFuncSetAttribute(flash_attn_mma,
                         cudaFuncAttributeMaxDynamicSharedMemorySize, ATT_SMEM);
    cudaFuncSetAttribute(gemm_mma<0>,
                         cudaFuncAttributeMaxDynamicSharedMemorySize, GEMM_SMEM);
    cudaFuncSetAttribute(gemm_mma<1>,
                         cudaFuncAttributeMaxDynamicSharedMemorySize, GEMM_SMEM);

    __half *xh, *yh, *wah, *wph;
    cudaGetSymbolAddress((void**)&xh,  g_xh);
    cudaGetSymbolAddress((void**)&yh,  g_yh);
    cudaGetSymbolAddress((void**)&wah, g_wah);
    cudaGetSymbolAddress((void**)&wph, g_wph);

    cast_f16<<<BS * E_DIM / 1024, 256>>>(x, xh);
    {
        dim3 g(3 * E_DIM / 32, E_DIM / 32);
        wcast_t<<<g, 256>>>(W_attn, wah, 3 * E_DIM);
    }
    {
        dim3 g(E_DIM / 32, E_DIM / 32);
        wcast_t<<<g, 256>>>(W_proj, wph, E_DIM);
    }

    // 1) QKV GEMM (1-product, K-chunk 64) -> q(QSCALE)/k/v fp16 [B,H,S,D]
    {
        dim3 grid(3 * E_DIM / 128, BS / 128);   // 24 x 64
        gemm_mma<0><<<grid, 256, GEMM_SMEM>>>(xh, wah, b_attn, nullptr);
    }

    // 2) causal flash attention -> yh fp16
    {
        dim3 grid(SEQ / 128, HEADS, BATCH);
        flash_attn_mma<<<grid, 256, ATT_SMEM>>>();
    }

    // 3) proj GEMM (1-product, K-chunk 64) -> out
    {
        dim3 grid(E_DIM / 128, BS / 128);
        gemm_mma<1><<<grid, 256, GEMM_SMEM>>>(yh, wph, b_proj, out);
    }
}

// round 13
// speedup vs baseline: 9.0495x; 1.0124x over previous
#include <cuda_runtime.h>
#include <cuda_fp16.h>
#include <cstdint>

#define E_DIM 1024
#define HEADS 16
#define HD 64
#define BATCH 4
#define SEQ 2048
#define BS (BATCH*SEQ)   // 8192

// q scale with log2(e) folded in: softmax done in exp2 domain
#define QSCALE 0.18033688011112042f   // 0.125 * log2(e)

// ---------------- scratch (device globals: allocation-guard safe) ----------
__device__ __align__(16) __half g_qh[BATCH*HEADS*SEQ*HD];
__device__ __align__(16) __half g_kh[BATCH*HEADS*SEQ*HD];
__device__ __align__(16) __half g_vh[BATCH*HEADS*SEQ*HD];

__device__ __align__(16) __half g_xh[BS*E_DIM];
__device__ __align__(16) __half g_yh[BS*E_DIM];
__device__ __align__(16) __half g_wah[3*E_DIM*E_DIM];   // W_attn^T fp16 [3072,1024]
__device__ __align__(16) __half g_wph[E_DIM*E_DIM];     // W_proj^T fp16 [1024,1024]

// ---------------- PTX helpers (all valid at compute_103) --------------------
__device__ __forceinline__ uint32_t smem_u32(const void* p) {
    uint32_t a;
    asm("{ .reg .u64 t; cvta.to.shared.u64 t, %1; cvt.u32.u64 %0, t; }"
        : "=r"(a) : "l"(p));
    return a;
}
#define CP_ASYNC16(sa, ga) \
    asm volatile("cp.async.cg.shared.global [%0], [%1], 16;" :: "r"(sa), "l"(ga))
#define CP_COMMIT() asm volatile("cp.async.commit_group;" ::: "memory")
#define CP_WAIT0()  asm volatile("cp.async.wait_group 0;" ::: "memory")
#define CP_WAIT1()  asm volatile("cp.async.wait_group 1;" ::: "memory")

__device__ __forceinline__ void ldsm_x4(uint32_t& r0, uint32_t& r1,
                                        uint32_t& r2, uint32_t& r3, uint32_t addr) {
    asm volatile("ldmatrix.sync.aligned.m8n8.x4.shared.b16 {%0,%1,%2,%3}, [%4];"
                 : "=r"(r0), "=r"(r1), "=r"(r2), "=r"(r3) : "r"(addr));
}
__device__ __forceinline__ void ldsm_x4t(uint32_t& r0, uint32_t& r1,
                                         uint32_t& r2, uint32_t& r3, uint32_t addr) {
    asm volatile("ldmatrix.sync.aligned.m8n8.x4.trans.shared.b16 {%0,%1,%2,%3}, [%4];"
                 : "=r"(r0), "=r"(r1), "=r"(r2), "=r"(r3) : "r"(addr));
}
__device__ __forceinline__ void mma16816(float* d, const uint32_t* a, const uint32_t* b) {
    asm volatile(
        "mma.sync.aligned.m16n8k16.row.col.f32.f16.f16.f32 "
        "{%0,%1,%2,%3}, {%4,%5,%6,%7}, {%8,%9}, {%0,%1,%2,%3};"
        : "+f"(d[0]), "+f"(d[1]), "+f"(d[2]), "+f"(d[3])
        : "r"(a[0]), "r"(a[1]), "r"(a[2]), "r"(a[3]), "r"(b[0]), "r"(b[1]));
}
__device__ __forceinline__ void mma2(float* d, const uint32_t* a, uint32_t b0, uint32_t b1) {
    asm volatile(
        "mma.sync.aligned.m16n8k16.row.col.f32.f16.f16.f32 "
        "{%0,%1,%2,%3}, {%4,%5,%6,%7}, {%8,%9}, {%0,%1,%2,%3};"
        : "+f"(d[0]), "+f"(d[1]), "+f"(d[2]), "+f"(d[3])
        : "r"(a[0]), "r"(a[1]), "r"(a[2]), "r"(a[3]), "r"(b0), "r"(b1));
}

// ---------------- prep kernels ---------------------------------------------
__global__ __launch_bounds__(256)
void cast_f16(const float* __restrict__ src, __half* __restrict__ dst)
{
    int i = (blockIdx.x * 256 + threadIdx.x) * 4;
    float4 v = *(const float4*)(src + i);
    *(__half2*)(dst + i)     = __floats2half2_rn(v.x, v.y);
    *(__half2*)(dst + i + 2) = __floats2half2_rn(v.z, v.w);
}

// W [1024, N] row-major -> Wt fp16 [N, 1024]
__global__ __launch_bounds__(256)
void wcast_t(const float* __restrict__ W, __half* __restrict__ Wh, int N)
{
    __shared__ float tile[32][33];
    int c0 = blockIdx.x * 32;
    int r0 = blockIdx.y * 32;
    int tx = threadIdx.x & 31, ty = threadIdx.x >> 5;
    #pragma unroll
    for (int i = ty; i < 32; i += 8)
        tile[i][tx] = W[(size_t)(r0 + i) * N + c0 + tx];
    __syncthreads();
    #pragma unroll
    for (int i = ty; i < 32; i += 8)
        Wh[(size_t)(c0 + i) * 1024 + r0 + tx] = __float2half_rn(tile[tx][i]);
}

// ---------------- HMMA GEMM (fp16 1-product, K-chunk 64, 3-stage) -----------
// MODE 0: epilogue -> q (QSCALE) / k / v fp16 in [B,H,S,D]
// MODE 1: epilogue -> out fp32 [8192,1024]
#define GEMM_BUFB 32768u
#define GEMM_SMEM (3*32768)

template<int MODE>
__global__ __launch_bounds__(256, 2)
void gemm_mma(const __half* __restrict__ Ah, const __half* __restrict__ Bh,
              const float* __restrict__ bias, float* __restrict__ out)
{
    extern __shared__ char smem[];
    const uint32_t sb = smem_u32(smem);
    const int tid  = threadIdx.x;
    const int wid  = tid >> 5;
    const int lane = tid & 31;
    const int m0 = blockIdx.y * 128;
    const int n0 = blockIdx.x * 128;

    const int wm = wid & 1;
    const int wn = wid >> 1;
    const int lr = lane & 7;
    const int lg = lane >> 3;

    float acc[4][4][4];
    #pragma unroll
    for (int i = 0; i < 4; i++)
        #pragma unroll
        for (int j = 0; j < 4; j++)
            #pragma unroll
            for (int r = 0; r < 4; r++) acc[i][j][r] = 0.0f;

    auto load_chunk = [&](int c, int buf) {
        const int k0 = c * 64;
        const uint32_t sbase = sb + (uint32_t)buf * GEMM_BUFB;
        #pragma unroll
        for (int t = 0; t < 4; t++) {
            int u = tid + t * 256;
            int r = u >> 3, seg = u & 7;
            uint32_t soff = (uint32_t)(r * 128 + ((seg ^ (r & 7)) << 4));
            size_t ga = (size_t)(m0 + r) * 1024 + k0 + seg * 8;
            size_t gb = (size_t)(n0 + r) * 1024 + k0 + seg * 8;
            CP_ASYNC16(sbase + soff,         Ah + ga);
            CP_ASYNC16(sbase + 16384 + soff, Bh + gb);
        }
        CP_COMMIT();
    };

    load_chunk(0, 0);
    load_chunk(1, 1);

    int buf = 0;
    for (int c = 0; c < 16; c++) {
        CP_WAIT1();          // chunk c resident (c+1 may still be in flight)
        __syncthreads();
        if (c + 2 < 16) {
            int nb = buf - 1; if (nb < 0) nb += 3;   // (c+2)%3
            load_chunk(c + 2, nb);
        }

        const uint32_t sbase = sb + (uint32_t)buf * GEMM_BUFB;
        #pragma unroll
        for (int s = 0; s < 4; s++) {
            uint32_t ah[4][4], bh[4][2];
            #pragma unroll
            for (int i = 0; i < 4; i++) {
                int row = wm * 64 + i * 16 + lr + (lg & 1) * 8;
                int seg = 2 * s + (lg >> 1);
                uint32_t ad = sbase + (uint32_t)(row * 128 +
                              ((seg ^ (row & 7)) << 4));
                ldsm_x4(ah[i][0], ah[i][1], ah[i][2], ah[i][3], ad);
            }
            #pragma unroll
            for (int p = 0; p < 2; p++) {
                int row = wn * 32 + p * 16 + lr + (lg >> 1) * 8;
                int seg = 2 * s + (lg & 1);
                uint32_t bd = sbase + 16384u + (uint32_t)(row * 128 +
                              ((seg ^ (row & 7)) << 4));
                uint32_t r0, r1, r2, r3;
                ldsm_x4(r0, r1, r2, r3, bd);
                bh[2*p][0] = r0; bh[2*p][1] = r1;
                bh[2*p+1][0] = r2; bh[2*p+1][1] = r3;
            }
            #pragma unroll
            for (int i = 0; i < 4; i++)
                #pragma unroll
                for (int j = 0; j < 4; j++)
                    mma16816(acc[i][j], ah[i], bh[j]);
        }
        if (++buf == 3) buf = 0;
    }

    const int mrow = m0 + wm * 64 + (lane >> 2);
    const int ncol = n0 + wn * 32 + (lane & 3) * 2;
    #pragma unroll
    for (int i = 0; i < 4; i++) {
        #pragma unroll
        for (int j = 0; j < 4; j++) {
            int m = mrow + i * 16;
            int n = ncol + j * 8;
            float b0 = __ldg(&bias[n]), b1 = __ldg(&bias[n + 1]);
            float f0 = acc[i][j][0] + b0, f1 = acc[i][j][1] + b1;
            float f2 = acc[i][j][2] + b0, f3 = acc[i][j][3] + b1;
            if (MODE == 0) {
                int sec = n >> 10;
                int e   = n & 1023;
                int hh  = e >> 6;
                int d   = e & 63;
                int b_ = m >> 11, s_ = m & 2047;
                size_t o0 = ((size_t)((b_ * HEADS + hh) * SEQ) + s_) * HD + d;
                size_t o1 = o0 + 8 * HD;
                __half* dst;
                if (sec == 0) {
                    dst = g_qh;
                    f0 *= QSCALE; f1 *= QSCALE; f2 *= QSCALE; f3 *= QSCALE;
                } else {
                    dst = (sec == 1) ? g_kh : g_vh;
                }
                *(__half2*)(dst + o0) = __floats2half2_rn(f0, f1);
                *(__half2*)(dst + o1) = __floats2half2_rn(f2, f3);
            } else {
                *(float2*)(out + (size_t)m * 1024 + n) = {f0, f1};
                *(float2*)(out + (size_t)(m + 8) * 1024 + n) = {f2, f3};
            }
        }
    }
}

// ---------------- HMMA flash attention (1-product fp16, 3-stage KV) ---------
// smem: Qh(16K) + 3 x [Kh(8K) Vh(8K)] = 64K
#define ATT_SMEM (16384 + 3*16384)   // 65536

__global__ __launch_bounds__(256, 2)
void flash_attn_mma()
{
    extern __shared__ char smc[];
    const uint32_t sb = smem_u32(smc);
    const int tid  = threadIdx.x;
    const int wid  = tid >> 5;       // 0..7
    const int lane = tid & 31;
    const int lr = lane & 7;
    const int lg = lane >> 3;
    const int g  = lane >> 2;
    const int t2 = (lane & 3) * 2;

    const int qi = (int)gridDim.x - 1 - (int)blockIdx.x;
    const int qb = qi * 128;
    const int hh = blockIdx.y;
    const int bb = blockIdx.z;
    const size_t bhof = ((size_t)(bb * HEADS + hh)) * SEQ * HD;

    const __half* qh_g = g_qh + bhof;
    const __half* kh_g = g_kh + bhof;
    const __half* vh_g = g_vh + bhof;

    const uint32_t QH = sb;
    const uint32_t BUF0 = sb + 16384;

    #pragma unroll
    for (int u = tid; u < 1024; u += 256) {
        int row = u >> 3, seg = u & 7;
        uint32_t so = (uint32_t)(row * 128 + ((seg ^ (row & 7)) << 4));
        size_t go = (size_t)(qb + row) * 64 + seg * 8;
        CP_ASYNC16(QH + so, qh_g + go);
    }

    auto load_kv = [&](int kj, int buf) {
        uint32_t base = BUF0 + (uint32_t)buf * 16384u;
        #pragma unroll
        for (int u = tid; u < 512; u += 256) {
            int row = u >> 3, seg = u & 7;
            uint32_t so = (uint32_t)(row * 128 + ((seg ^ (row & 7)) << 4));
            size_t go = (size_t)(kj * 64 + row) * 64 + seg * 8;
            CP_ASYNC16(base + so,         kh_g + go);
            CP_ASYNC16(base + 8192 + so,  vh_g + go);
        }
        CP_COMMIT();
    };

    const int nkj = 2 * qi + 2;
    load_kv(0, 0);   // same group as Q (committed here)
    if (nkj > 1) load_kv(1, 1);

    uint32_t qfh[4][4];
    float y[8][4];
    #pragma unroll
    for (int j = 0; j < 8; j++)
        #pragma unroll
        for (int r = 0; r < 4; r++) y[j][r] = 0.0f;
    float m0 = -1e30f, m1 = -1e30f, l0 = 0.0f, l1 = 0.0f;
    bool qloaded = false;

    const int wr0 = qb + wid * 16;

    int buf = 0;
    for (int kj = 0; kj < nkj; kj++) {
        if (kj + 1 < nkj) CP_WAIT1(); else CP_WAIT0();
        __syncthreads();
        if (kj + 2 < nkj) {
            int nb = buf - 1; if (nb < 0) nb += 3;   // (kj+2)%3
            load_kv(kj + 2, nb);
        }

        if (!qloaded) {
            qloaded = true;
            #pragma unroll
            for (int kc = 0; kc < 4; kc++) {
                int row = wid * 16 + lr + (lg & 1) * 8;
                int seg = 2 * kc + (lg >> 1);
                uint32_t so = (uint32_t)(row * 128 + ((seg ^ (row & 7)) << 4));
                ldsm_x4(qfh[kc][0], qfh[kc][1], qfh[kc][2], qfh[kc][3], QH + so);
            }
        }

        const int c0t = kj * 64;
        const uint32_t B = BUF0 + (uint32_t)buf * 16384u;
        if (++buf == 3) buf = 0;
        if (c0t > wr0 + 15) continue;

        // ---- S = Q K^T (1-product) ----
        float s[8][4];
        #pragma unroll
        for (int j = 0; j < 8; j++)
            #pragma unroll
            for (int r = 0; r < 4; r++) s[j][r] = 0.0f;

        #pragma unroll
        for (int kc = 0; kc < 4; kc++) {
            uint32_t kh[4][4];
            #pragma unroll
            for (int p = 0; p < 4; p++) {
                int row = p * 16 + lr + (lg >> 1) * 8;
                int seg = 2 * kc + (lg & 1);
                uint32_t so = (uint32_t)(row * 128 + ((seg ^ (row & 7)) << 4));
                ldsm_x4(kh[p][0], kh[p][1], kh[p][2], kh[p][3], B + so);
            }
            #pragma unroll
            for (int p = 0; p < 4; p++) {
                mma2(s[2*p],   qfh[kc], kh[p][0], kh[p][1]);
                mma2(s[2*p+1], qfh[kc], kh[p][2], kh[p][3]);
            }
        }

        // ---- causal mask ----
        if (c0t + 63 > wr0) {
            int R0 = wr0 + g, R1 = wr0 + g + 8;
            #pragma unroll
            for (int j = 0; j < 8; j++) {
                int cg = c0t + j * 8 + t2;
                if (cg     > R0) s[j][0] = -1e30f;
                if (cg + 1 > R0) s[j][1] = -1e30f;
                if (cg     > R1) s[j][2] = -1e30f;
                if (cg + 1 > R1) s[j][3] = -1e30f;
            }
        }

        // ---- online softmax (exp2 domain) ----
        float mx0 = -1e30f, mx1 = -1e30f;
        #pragma unroll
        for (int j = 0; j < 8; j++) {
            mx0 = fmaxf(mx0, fmaxf(s[j][0], s[j][1]));
            mx1 = fmaxf(mx1, fmaxf(s[j][2], s[j][3]));
        }
        mx0 = fmaxf(mx0, __shfl_xor_sync(0xffffffffu, mx0, 1));
        mx0 = fmaxf(mx0, __shfl_xor_sync(0xffffffffu, mx0, 2));
        mx1 = fmaxf(mx1, __shfl_xor_sync(0xffffffffu, mx1, 1));
        mx1 = fmaxf(mx1, __shfl_xor_sync(0xffffffffu, mx1, 2));
        float mn0 = fmaxf(m0, mx0), mn1 = fmaxf(m1, mx1);
        float a0 = exp2f(m0 - mn0), a1 = exp2f(m1 - mn1);
        m0 = mn0; m1 = mn1;

        float s0 = 0.0f, s1 = 0.0f;
        uint32_t ph[4][4];
        #pragma unroll
        for (int j = 0; j < 8; j++) {
            float p00 = exp2f(s[j][0] - mn0);
            float p01 = exp2f(s[j][1] - mn0);
            float p10 = exp2f(s[j][2] - mn1);
            float p11 = exp2f(s[j][3] - mn1);
            s0 += p00 + p01;
            s1 += p10 + p11;
            uint32_t hA, hB;
            { __half2 v = __floats2half2_rn(p00, p01); hA = *(uint32_t*)&v; }
            { __half2 v = __floats2half2_rn(p10, p11); hB = *(uint32_t*)&v; }
            int kc = j >> 1;
            if ((j & 1) == 0) { ph[kc][0] = hA; ph[kc][1] = hB; }
            else              { ph[kc][2] = hA; ph[kc][3] = hB; }
        }
        s0 += __shfl_xor_sync(0xffffffffu, s0, 1);
        s0 += __shfl_xor_sync(0xffffffffu, s0, 2);
        s1 += __shfl_xor_sync(0xffffffffu, s1, 1);
        s1 += __shfl_xor_sync(0xffffffffu, s1, 2);
        l0 = l0 * a0 + s0;
        l1 = l1 * a1 + s1;
        #pragma unroll
        for (int j = 0; j < 8; j++) {
            y[j][0] *= a0; y[j][1] *= a0;
            y[j][2] *= a1; y[j][3] *= a1;
        }

        // ---- Y += P V (1-product) ----
        #pragma unroll
        for (int kc = 0; kc < 4; kc++) {
            uint32_t vh[4][4];
            #pragma unroll
            for (int dg = 0; dg < 4; dg++) {
                int row = kc * 16 + (lg & 1) * 8 + lr;
                int seg = 2 * dg + (lg >> 1);
                uint32_t so = (uint32_t)(row * 128 + ((seg ^ (row & 7)) << 4));
                ldsm_x4t(vh[dg][0], vh[dg][1], vh[dg][2], vh[dg][3], B + 8192 + so);
            }
            #pragma unroll
            for (int dg = 0; dg < 4; dg++) {
                mma2(y[2*dg],   ph[kc], vh[dg][0], vh[dg][1]);
                mma2(y[2*dg+1], ph[kc], vh[dg][2], vh[dg][3]);
            }
        }
    }

    // ---- epilogue: normalize -> g_yh single fp16 [B,S,E] ----
    const float i0 = 1.0f / l0, i1 = 1.0f / l1;
    const int r0 = wr0 + g;
    const int r1 = r0 + 8;
    const size_t rb0 = ((size_t)(bb * SEQ + r0)) * E_DIM + hh * HD;
    const size_t rb1 = ((size_t)(bb * SEQ + r1)) * E_DIM + hh * HD;
    #pragma unroll
    for (int j = 0; j < 8; j++) {
        int col = j * 8 + t2;
        *(__half2*)(g_yh + rb0 + col) =
            __floats2half2_rn(y[j][0] * i0, y[j][1] * i0);
        *(__half2*)(g_yh + rb1 + col) =
            __floats2half2_rn(y[j][2] * i1, y[j][3] * i1);
    }
}

// ---------------------------------------------------------------------------
extern "C" void kernel_launch(void* const* d_in, const int* in_sizes, int n_in,
                              void* d_out, int out_size)
{
    const float* x      = (const float*)d_in[0];
    const float* W_attn = (const float*)d_in[1];
    const float* b_attn = (const float*)d_in[2];
    const float* W_proj = (const float*)d_in[3];
    const float* b_proj = (const float*)d_in[4];
    float* out = (float*)d_out;

    cudaFuncSetAttribute(flash_attn_mma,
                         cudaFuncAttributeMaxDynamicSharedMemorySize, ATT_SMEM);
    cudaFuncSetAttribute(gemm_mma<0>,
                         cudaFuncAttributeMaxDynamicSharedMemorySize, GEMM_SMEM);
    cudaFuncSetAttribute(gemm_mma<1>,
                         cudaFuncAttributeMaxDynamicSharedMemorySize, GEMM_SMEM);

    __half *xh, *yh, *wah, *wph;
    cudaGetSymbolAddress((void**)&xh,  g_xh);
    cudaGetSymbolAddress((void**)&yh,  g_yh);
    cudaGetSymbolAddress((void**)&wah, g_wah);
    cudaGetSymbolAddress((void**)&wph, g_wph);

    cast_f16<<<BS * E_DIM / 1024, 256>>>(x, xh);
    {
        dim3 g(3 * E_DIM / 32, E_DIM / 32);
        wcast_t<<<g, 256>>>(W_attn, wah, 3 * E_DIM);
    }
    {
        dim3 g(E_DIM / 32, E_DIM / 32);
        wcast_t<<<g, 256>>>(W_proj, wph, E_DIM);
    }

    // 1) QKV GEMM (1-product, 3-stage pipeline) -> q(QSCALE)/k/v fp16 [B,H,S,D]
    {
        dim3 grid(3 * E_DIM / 128, BS / 128);   // 24 x 64
        gemm_mma<0><<<grid, 256, GEMM_SMEM>>>(xh, wah, b_attn, nullptr);
    }

    // 2) causal flash attention (3-stage KV pipeline) -> yh fp16
    {
        dim3 grid(SEQ / 128, HEADS, BATCH);
        flash_attn_mma<<<grid, 256, ATT_SMEM>>>();
    }

    // 3) proj GEMM (1-product, 3-stage pipeline) -> out
    {
        dim3 grid(E_DIM / 128, BS / 128);
        gemm_mma<1><<<grid, 256, GEMM_SMEM>>>(yh, wph, b_proj, out);
    }
}